// round 2
// baseline (speedup 1.0000x reference)
#include <cuda_runtime.h>
#include <cstdint>

#define BB 16
#define NC 1023
#define NN 1024
#define BN (BB*NN)

// degree-5 economized sigmoid poly on [-1,1]: sigma(x) ~= 0.5 + PC1 x + PC3 x^3 + PC5 x^5
#define PC1 0.24997694f
#define PC3 (-0.02064887f)
#define PC5 0.00171441f

// ---------------- static device scratch (no allocation allowed) ----------------
__device__ float g_P [BB*NC*NN];   // presence softmax [b][c][n]
__device__ float g_Dm[BB*NC*NN];   // edge[...,0]      [b][c][n]
__device__ float g_Pt[BB*NN*NN];   // transposed, c padded to 1024 (pad col = 0)
__device__ float g_Dt[BB*NN*NN];
__device__ float g_xa[BN];
__device__ float g_la[BN*64];
__device__ float g_uaA[BN*64];
__device__ float g_uaB[BN*64];
__device__ float g_ub [BN*64];
__device__ float g_x2 [BN*128];
__device__ float g_l2 [BN*128];
__device__ float g_gA [BN*128];
__device__ float g_gB [BN*128];

// ---------------- packed f32x2 helpers (sm_100+) ----------------
__device__ __forceinline__ float2 f2(float x) { return make_float2(x, x); }
__device__ __forceinline__ float2 fma2(float2 a, float2 b, float2 c) {
    float2 r;
    asm("fma.rn.f32x2 %0, %1, %2, %3;"
        : "=l"(*(unsigned long long*)&r)
        : "l"(*(unsigned long long*)&a), "l"(*(unsigned long long*)&b),
          "l"(*(unsigned long long*)&c));
    return r;
}
__device__ __forceinline__ float2 mul2(float2 a, float2 b) {
    float2 r;
    asm("mul.rn.f32x2 %0, %1, %2;"
        : "=l"(*(unsigned long long*)&r)
        : "l"(*(unsigned long long*)&a), "l"(*(unsigned long long*)&b));
    return r;
}

// ---------------- x_a[b,n] = max_r xs * (prev + action) ----------------
__global__ void __launch_bounds__(256) k_xa(const float* __restrict__ xs,
                                            const float* __restrict__ ap,
                                            const float* __restrict__ ac,
                                            float* __restrict__ xa) {
    int idx = blockIdx.x * 256 + threadIdx.x;   // b*1024+n
    int b = idx >> 10, n = idx & (NN - 1);
    float best = -3.4e38f;
#pragma unroll
    for (int r = 0; r < 8; r++) {
        int o = (((b << 3) + r) << 10) + n;
        best = fmaxf(best, xs[o] * (ap[o] + ac[o]));
    }
    xa[idx] = best;
}

// ---------------- presence MLP + masked softmax; one block per (b,c) ----------------
__global__ void __launch_bounds__(256) k_presence(const float* __restrict__ edge,
                                                  const float* __restrict__ avail,
                                                  const float* __restrict__ W1,
                                                  const float* __restrict__ W2,
                                                  float* __restrict__ P,
                                                  float* __restrict__ Dm) {
    __shared__ float sW1[192];
    __shared__ float sW2[64];
    __shared__ float redA[8], redB[8];
    int bc = blockIdx.x;
    int b = bc / NC, c = bc - b * NC;
    int tid = threadIdx.x, lane = tid & 31, warp = tid >> 5;
    if (tid < 192) sW1[tid] = W1[tid];
    if (tid < 64)  sW2[tid] = W2[tid];
    __syncthreads();

    size_t ebase = (size_t)bc * NN * 3;
    size_t pbase = (size_t)bc * NN;
    float lg[4];
#pragma unroll
    for (int j = 0; j < 2; j++) {
        int n0 = tid + j * 512;
        int n1 = n0 + 256;
        float e00 = edge[ebase + (size_t)n0 * 3];
        float e01 = edge[ebase + (size_t)n0 * 3 + 1];
        float e02 = edge[ebase + (size_t)n0 * 3 + 2];
        float e10 = edge[ebase + (size_t)n1 * 3];
        float e11 = edge[ebase + (size_t)n1 * 3 + 1];
        float e12 = edge[ebase + (size_t)n1 * 3 + 2];
        float2 E0 = make_float2(e00, e10);
        float2 E1 = make_float2(e01, e11);
        float2 E2 = make_float2(e02, e12);
        float2 acc = f2(0.f);
#pragma unroll
        for (int h = 0; h < 64; h++) {
            float2 t = mul2(E0, f2(sW1[h]));
            t = fma2(E1, f2(sW1[64 + h]), t);
            t = fma2(E2, f2(sW1[128 + h]), t);
            t.x = fmaxf(t.x, 0.f); t.y = fmaxf(t.y, 0.f);
            acc = fma2(t, f2(sW2[h]), acc);
        }
        float h2a = fmaxf(acc.x, 0.f);
        float h2b = fmaxf(acc.y, 0.f);
        float m0 = (n0 == c ? 0.f : 1.f) * avail[(b << 10) + n0];
        float m1 = (n1 == c ? 0.f : 1.f) * avail[(b << 10) + n1];
        lg[2 * j]     = h2a * m0 - (1.f - m0) * 1e10f;
        lg[2 * j + 1] = h2b * m1 - (1.f - m1) * 1e10f;
        Dm[pbase + n0] = e00;
        Dm[pbase + n1] = e10;
    }
    // block softmax over 1024 logits (4 per thread)
    float m = fmaxf(fmaxf(lg[0], lg[1]), fmaxf(lg[2], lg[3]));
#pragma unroll
    for (int o = 16; o; o >>= 1) m = fmaxf(m, __shfl_xor_sync(0xffffffffu, m, o));
    if (lane == 0) redA[warp] = m;
    __syncthreads();
    m = redA[0];
#pragma unroll
    for (int w = 1; w < 8; w++) m = fmaxf(m, redA[w]);
    float e0 = __expf(lg[0] - m), e1 = __expf(lg[1] - m);
    float e2 = __expf(lg[2] - m), e3 = __expf(lg[3] - m);
    float s = (e0 + e1) + (e2 + e3);
#pragma unroll
    for (int o = 16; o; o >>= 1) s += __shfl_xor_sync(0xffffffffu, s, o);
    if (lane == 0) redB[warp] = s;
    __syncthreads();
    s = redB[0];
#pragma unroll
    for (int w = 1; w < 8; w++) s += redB[w];
    float inv = 1.0f / s;
    P[pbase + tid]       = e0 * inv;
    P[pbase + tid + 256] = e1 * inv;
    P[pbase + tid + 512] = e2 * inv;
    P[pbase + tid + 768] = e3 * inv;
}

// ---------------- transpose [b][c][n] -> [b][n][c_pad1024] ----------------
__global__ void __launch_bounds__(256) k_trans(const float* __restrict__ P,
                                               const float* __restrict__ D,
                                               float* __restrict__ Pt,
                                               float* __restrict__ Dt) {
    __shared__ float sP[32][33], sD[32][33];
    int b = blockIdx.z, nt = blockIdx.x, ct = blockIdx.y, tid = threadIdx.x;
#pragma unroll
    for (int k = 0; k < 4; k++) {
        int idx = tid + (k << 8);
        int r = idx >> 5, j = idx & 31;
        int c = (ct << 5) + r, n = (nt << 5) + j;
        float pv = 0.f, dv = 0.f;
        if (c < NC) {
            size_t g = ((size_t)(b * NC + c) << 10) + n;
            pv = P[g]; dv = D[g];
        }
        sP[r][j] = pv; sD[r][j] = dv;
    }
    __syncthreads();
#pragma unroll
    for (int k = 0; k < 4; k++) {
        int idx = tid + (k << 8);
        int rn = idx >> 5, jc = idx & 31;
        size_t g = (((size_t)(b << 10) + (nt << 5) + rn) << 10) + (ct << 5) + jc;
        Pt[g] = sP[jc][rn];
        Dt[g] = sD[jc][rn];
    }
}

// ---------------- main contraction: L[b,i,h] = sum_c P u sigma(d w_h) via poly ----------------
template<int H>
__global__ void __launch_bounds__(256) k_contract(const float* __restrict__ u,
                                                  const float* __restrict__ Pt,
                                                  const float* __restrict__ Dt,
                                                  const float* __restrict__ Wemb,
                                                  float* __restrict__ L) {
    constexpr int HT = H / 16;   // h per thread: 4 or 8
    constexpr int HV = H / 4;    // float4 per row
    __shared__ float sP[16][65], sD[16][65];
    __shared__ float4 sU[64 * HV];
    const int tid = threadIdx.x;
    const int ii = tid & 15, hq = tid >> 4;
    const int b = blockIdx.y, i0 = blockIdx.x << 4;
    float2 S0[HT / 2], S1[HT / 2], S3[HT / 2], S5[HT / 2];
#pragma unroll
    for (int q = 0; q < HT / 2; q++) { S0[q] = f2(0.f); S1[q] = f2(0.f); S3[q] = f2(0.f); S5[q] = f2(0.f); }

    for (int c0 = 0; c0 < NN; c0 += 64) {
#pragma unroll
        for (int k = 0; k < 4; k++) {
            int idx = tid + (k << 8);
            int r = idx >> 6, c = idx & 63;
            size_t g = (((size_t)((b << 10) + i0 + r)) << 10) + c0 + c;
            sP[r][c] = Pt[g];
            sD[r][c] = Dt[g];
        }
        const float4* u4 = (const float4*)(u + ((size_t)(b << 10) + c0) * H);
#pragma unroll
        for (int idx = tid; idx < 64 * HV; idx += 256) sU[idx] = u4[idx];
        __syncthreads();
#pragma unroll 4
        for (int cc = 0; cc < 64; cc++) {
            float p = sP[ii][cc], d = sD[ii][cc];
            float d2 = d * d;
            float t1 = p * d, t3 = t1 * d2, t5 = t3 * d2;
            const float4* ur = &sU[cc * HV + hq * (HT / 4)];
#pragma unroll
            for (int q = 0; q < HT / 4; q++) {
                float4 uv = ur[q];
                float2 ua = make_float2(uv.x, uv.y);
                float2 ub = make_float2(uv.z, uv.w);
                S0[2 * q]     = fma2(f2(p),  ua, S0[2 * q]);
                S0[2 * q + 1] = fma2(f2(p),  ub, S0[2 * q + 1]);
                S1[2 * q]     = fma2(f2(t1), ua, S1[2 * q]);
                S1[2 * q + 1] = fma2(f2(t1), ub, S1[2 * q + 1]);
                S3[2 * q]     = fma2(f2(t3), ua, S3[2 * q]);
                S3[2 * q + 1] = fma2(f2(t3), ub, S3[2 * q + 1]);
                S5[2 * q]     = fma2(f2(t5), ua, S5[2 * q]);
                S5[2 * q + 1] = fma2(f2(t5), ub, S5[2 * q + 1]);
            }
        }
        __syncthreads();
    }
    const int h0 = hq * HT;
    float* lrow = L + ((size_t)((b << 10) + i0 + ii)) * H + h0;
#pragma unroll
    for (int q = 0; q < HT / 2; q++) {
        float wa = Wemb[h0 + 2 * q], wb = Wemb[h0 + 2 * q + 1];
        float wa2 = wa * wa, wb2 = wb * wb;
        float la = 0.5f * S0[q].x + (PC1 * wa) * S1[q].x + (PC3 * wa * wa2) * S3[q].x
                 + (PC5 * wa * wa2 * wa2) * S5[q].x;
        float lb = 0.5f * S0[q].y + (PC1 * wb) * S1[q].y + (PC3 * wb * wb2) * S3[q].y
                 + (PC5 * wb * wb2 * wb2) * S5[q].y;
        lrow[2 * q]     = la;
        lrow[2 * q + 1] = lb;
    }
}

// ---------------- small GEMM epilogue: out = [relu]( A@W [+ A2@W2] [+ bias] [+ xa*wx] ) ----------------
template<int K, int NO, bool RELU, bool HAS2, bool HASB, bool HASX>
__global__ void __launch_bounds__(NO * 4) k_gemm(const float* __restrict__ A,
                                                 const float* __restrict__ A2,
                                                 const float* __restrict__ W,
                                                 const float* __restrict__ W2,
                                                 const float* __restrict__ bias,
                                                 const float* __restrict__ xa,
                                                 const float* __restrict__ wx,
                                                 float* __restrict__ out) {
    constexpr int NT = NO * 4;
    __shared__ float sA[16][33];
    __shared__ __align__(16) float sW[32 * NO];
    const int tid = threadIdx.x, rr = tid & 15, cq = tid >> 4;
    const int r0 = blockIdx.x << 4;
    float2 acc0 = f2(0.f), acc1 = f2(0.f);
    const int NP = HAS2 ? 2 : 1;
    for (int pass = 0; pass < NP; pass++) {
        const float* Ap = (HAS2 && pass) ? A2 : A;
        const float* Wp = (HAS2 && pass) ? W2 : W;
        for (int k0 = 0; k0 < K; k0 += 32) {
#pragma unroll
            for (int idx = tid; idx < 512; idx += NT) {
                int r = idx >> 5, c = idx & 31;
                sA[r][c] = Ap[(size_t)(r0 + r) * K + k0 + c];
            }
#pragma unroll
            for (int idx = tid; idx < 32 * NO; idx += NT)
                sW[idx] = Wp[(size_t)(k0 + idx / NO) * NO + (idx & (NO - 1))];
            __syncthreads();
#pragma unroll
            for (int kk = 0; kk < 32; kk++) {
                float a = sA[rr][kk];
                float4 wv = ((const float4*)sW)[kk * (NO / 4) + cq];
                acc0 = fma2(f2(a), make_float2(wv.x, wv.y), acc0);
                acc1 = fma2(f2(a), make_float2(wv.z, wv.w), acc1);
            }
            __syncthreads();
        }
    }
    float4 r;
    r.x = acc0.x; r.y = acc0.y; r.z = acc1.x; r.w = acc1.y;
    size_t orow = (size_t)(r0 + rr) * NO + (cq << 2);
    if (HASX) {
        float xv = xa[r0 + rr];
        float4 wv = ((const float4*)wx)[cq];
        r.x += xv * wv.x; r.y += xv * wv.y; r.z += xv * wv.z; r.w += xv * wv.w;
    }
    if (HASB) {
        float4 bv = ((const float4*)bias)[orow >> 2];
        r.x += bv.x; r.y += bv.y; r.z += bv.z; r.w += bv.w;
    }
    if (RELU) {
        r.x = fmaxf(r.x, 0.f); r.y = fmaxf(r.y, 0.f);
        r.z = fmaxf(r.z, 0.f); r.w = fmaxf(r.w, 0.f);
    }
    ((float4*)out)[orow >> 2] = r;
}

// ---------------- final reduction Q[b] = sum_{n,h} gamma * W_Q ----------------
__global__ void __launch_bounds__(256) k_q(const float* __restrict__ g,
                                           const float* __restrict__ wq,
                                           float* __restrict__ out) {
    __shared__ float red[8];
    int b = blockIdx.x, tid = threadIdx.x, lane = tid & 31, warp = tid >> 5;
    const float* gb = g + (size_t)b * NN * 128;
    float acc = 0.f;
    for (int idx = tid; idx < NN * 128; idx += 256)
        acc += gb[idx] * wq[idx & 127];
#pragma unroll
    for (int o = 16; o; o >>= 1) acc += __shfl_xor_sync(0xffffffffu, acc, o);
    if (lane == 0) red[warp] = acc;
    __syncthreads();
    if (tid == 0) {
        float s = 0.f;
#pragma unroll
        for (int w = 0; w < 8; w++) s += red[w];
        out[b] = s;
    }
}

#define GETSYM(p, s) do { void* _q = nullptr; cudaGetSymbolAddress(&_q, s); (p) = (float*)_q; } while (0)

extern "C" void kernel_launch(void* const* d_in, const int* in_sizes, int n_in,
                              void* d_out, int out_size) {
    (void)in_sizes; (void)n_in; (void)out_size;
    const float* xs     = (const float*)d_in[0];
    const float* ap     = (const float*)d_in[1];
    const float* ac     = (const float*)d_in[2];
    const float* edge   = (const float*)d_in[3];
    const float* avail  = (const float*)d_in[4];
    const float* ua0    = (const float*)d_in[5];
    // d_in[6] = u_b0: unused by the reference
    const float* g0     = (const float*)d_in[7];
    const float* W1p    = (const float*)d_in[8];
    const float* W2p    = (const float*)d_in[9];
    const float* Wx1a   = (const float*)d_in[10];
    const float* Wemb1a = (const float*)d_in[11];
    const float* Wl1a   = (const float*)d_in[12];
    const float* Wx1b   = (const float*)d_in[13];
    // d_in[14] = W_emb_1b: computed but unused by the reference
    const float* Wl1b   = (const float*)d_in[15];
    const float* Wx2    = (const float*)d_in[16];
    const float* Wemb2  = (const float*)d_in[17];
    const float* Wl2    = (const float*)d_in[18];
    const float* WQ     = (const float*)d_in[19];

    float *pP, *pDm, *pPt, *pDt, *pxa, *pla, *puaA, *puaB, *pub, *px2, *pl2, *pgA, *pgB;
    GETSYM(pP, g_P);   GETSYM(pDm, g_Dm); GETSYM(pPt, g_Pt); GETSYM(pDt, g_Dt);
    GETSYM(pxa, g_xa); GETSYM(pla, g_la); GETSYM(puaA, g_uaA); GETSYM(puaB, g_uaB);
    GETSYM(pub, g_ub); GETSYM(px2, g_x2); GETSYM(pl2, g_l2);
    GETSYM(pgA, g_gA); GETSYM(pgB, g_gB);

    k_xa<<<64, 256>>>(xs, ap, ac, pxa);
    k_presence<<<BB * NC, 256>>>(edge, avail, W1p, W2p, pP, pDm);
    k_trans<<<dim3(32, 32, BB), 256>>>(pP, pDm, pPt, pDt);

    // T1: 5 iterations (H = 64)
    const float* uin = ua0;
    for (int it = 0; it < 5; it++) {
        k_contract<64><<<dim3(64, BB), 256>>>(uin, pPt, pDt, Wemb1a, pla);
        float* uout = (it & 1) ? puaB : puaA;
        k_gemm<64, 64, true, false, false, true><<<1024, 256>>>(
            pla, nullptr, Wl1a, nullptr, nullptr, pxa, Wx1a, uout);
        if (it == 4)
            k_gemm<64, 64, true, false, false, true><<<1024, 256>>>(
                pla, nullptr, Wl1b, nullptr, nullptr, pxa, Wx1b, pub);
        uin = uout;
    }

    // x2 = [u_a | u_b] @ W_x_2
    k_gemm<64, 128, false, true, false, false><<<1024, 512>>>(
        uin, pub, Wx2, Wx2 + 64 * 128, nullptr, nullptr, nullptr, px2);

    // T2: 5 iterations (H = 128)
    const float* gin = g0;
    for (int it = 0; it < 5; it++) {
        k_contract<128><<<dim3(64, BB), 256>>>(gin, pPt, pDt, Wemb2, pl2);
        float* gout = (it & 1) ? pgB : pgA;
        k_gemm<128, 128, true, false, true, false><<<1024, 512>>>(
            pl2, nullptr, Wl2, nullptr, px2, nullptr, nullptr, gout);
        gin = gout;
    }

    k_q<<<BB, 256>>>(gin, WQ, (float*)d_out);
}

// round 5
// speedup vs baseline: 3.2628x; 3.2628x over previous
#include <cuda_runtime.h>
#include <cuda_fp16.h>
#include <cstdint>

#define BB 16
#define NC 1023
#define NN 1024
#define BN (BB*NN)
#define KK 4096

// degree-5 economized sigmoid poly on [-1,1]
#define PC1 0.24997694f
#define PC3 (-0.02064887f)
#define PC5 0.00171441f

// ---------------- static device scratch ----------------
__device__ float g_P [BB*NC*NN];
__device__ float g_Dm[BB*NC*NN];
__device__ __half g_A[(size_t)BB*NN*KK];     // [b][i][kp*1024+c]
__device__ __half g_Bop[(size_t)BB*128*KK];  // [b][h][kp*1024+c]
__device__ float g_xa[BN];
__device__ float g_la[BN*64];
__device__ float g_uaA[BN*64];
__device__ float g_uaB[BN*64];
__device__ float g_ub [BN*64];
__device__ float g_x2 [BN*128];
__device__ float g_l2 [BN*128];
__device__ float g_gA [BN*128];
__device__ float g_gB [BN*128];

// ---------------- packed f32x2 helpers ----------------
__device__ __forceinline__ float2 f2(float x) { return make_float2(x, x); }
__device__ __forceinline__ float2 fma2(float2 a, float2 b, float2 c) {
    float2 r;
    asm("fma.rn.f32x2 %0, %1, %2, %3;"
        : "=l"(*(unsigned long long*)&r)
        : "l"(*(unsigned long long*)&a), "l"(*(unsigned long long*)&b),
          "l"(*(unsigned long long*)&c));
    return r;
}
__device__ __forceinline__ float2 mul2(float2 a, float2 b) {
    float2 r;
    asm("mul.rn.f32x2 %0, %1, %2;"
        : "=l"(*(unsigned long long*)&r)
        : "l"(*(unsigned long long*)&a), "l"(*(unsigned long long*)&b));
    return r;
}

__device__ __forceinline__ uint32_t smem_u32(const void* p) {
    uint32_t a;
    asm("{ .reg .u64 t; cvta.to.shared.u64 t, %1; cvt.u32.u64 %0, t; }" : "=r"(a) : "l"(p));
    return a;
}
__device__ __forceinline__ void ldgsts16(uint32_t s, const void* g) {
    asm volatile("cp.async.cg.shared.global [%0], [%1], 16;" :: "r"(s), "l"(g));
}
__device__ __forceinline__ void ldsm_x4(uint32_t& r0, uint32_t& r1, uint32_t& r2,
                                        uint32_t& r3, uint32_t addr) {
    asm volatile("ldmatrix.sync.aligned.m8n8.x4.shared.b16 {%0,%1,%2,%3}, [%4];"
        : "=r"(r0), "=r"(r1), "=r"(r2), "=r"(r3) : "r"(addr));
}
__device__ __forceinline__ void mma16816(float* c, uint32_t a0, uint32_t a1,
                                         uint32_t a2, uint32_t a3,
                                         uint32_t b0, uint32_t b1) {
    asm volatile("mma.sync.aligned.m16n8k16.row.col.f32.f16.f16.f32 "
        "{%0,%1,%2,%3}, {%4,%5,%6,%7}, {%8,%9}, {%0,%1,%2,%3};"
        : "+f"(c[0]), "+f"(c[1]), "+f"(c[2]), "+f"(c[3])
        : "r"(a0), "r"(a1), "r"(a2), "r"(a3), "r"(b0), "r"(b1));
}

// ---------------- x_a ----------------
__global__ void __launch_bounds__(256) k_xa(const float* __restrict__ xs,
                                            const float* __restrict__ ap,
                                            const float* __restrict__ ac,
                                            float* __restrict__ xa) {
    int idx = blockIdx.x * 256 + threadIdx.x;
    int b = idx >> 10, n = idx & (NN - 1);
    float best = -3.4e38f;
#pragma unroll
    for (int r = 0; r < 8; r++) {
        int o = (((b << 3) + r) << 10) + n;
        best = fmaxf(best, xs[o] * (ap[o] + ac[o]));
    }
    xa[idx] = best;
}

// ---------------- presence MLP + masked softmax ----------------
__global__ void __launch_bounds__(256) k_presence(const float* __restrict__ edge,
                                                  const float* __restrict__ avail,
                                                  const float* __restrict__ W1,
                                                  const float* __restrict__ W2,
                                                  float* __restrict__ P,
                                                  float* __restrict__ Dm) {
    __shared__ float sW1[192];
    __shared__ float sW2[64];
    __shared__ float redA[8], redB[8];
    int bc = blockIdx.x;
    int b = bc / NC, c = bc - b * NC;
    int tid = threadIdx.x, lane = tid & 31, warp = tid >> 5;
    if (tid < 192) sW1[tid] = W1[tid];
    if (tid < 64)  sW2[tid] = W2[tid];
    __syncthreads();

    size_t ebase = (size_t)bc * NN * 3;
    size_t pbase = (size_t)bc * NN;
    float lg[4];
#pragma unroll
    for (int j = 0; j < 2; j++) {
        int n0 = tid + j * 512;
        int n1 = n0 + 256;
        float e00 = edge[ebase + (size_t)n0 * 3];
        float e01 = edge[ebase + (size_t)n0 * 3 + 1];
        float e02 = edge[ebase + (size_t)n0 * 3 + 2];
        float e10 = edge[ebase + (size_t)n1 * 3];
        float e11 = edge[ebase + (size_t)n1 * 3 + 1];
        float e12 = edge[ebase + (size_t)n1 * 3 + 2];
        float2 E0 = make_float2(e00, e10);
        float2 E1 = make_float2(e01, e11);
        float2 E2 = make_float2(e02, e12);
        float2 acc = f2(0.f);
#pragma unroll
        for (int h = 0; h < 64; h++) {
            float2 t = mul2(E0, f2(sW1[h]));
            t = fma2(E1, f2(sW1[64 + h]), t);
            t = fma2(E2, f2(sW1[128 + h]), t);
            t.x = fmaxf(t.x, 0.f); t.y = fmaxf(t.y, 0.f);
            acc = fma2(t, f2(sW2[h]), acc);
        }
        float h2a = fmaxf(acc.x, 0.f);
        float h2b = fmaxf(acc.y, 0.f);
        float m0 = (n0 == c ? 0.f : 1.f) * avail[(b << 10) + n0];
        float m1 = (n1 == c ? 0.f : 1.f) * avail[(b << 10) + n1];
        lg[2 * j]     = h2a * m0 - (1.f - m0) * 1e10f;
        lg[2 * j + 1] = h2b * m1 - (1.f - m1) * 1e10f;
        Dm[pbase + n0] = e00;
        Dm[pbase + n1] = e10;
    }
    float m = fmaxf(fmaxf(lg[0], lg[1]), fmaxf(lg[2], lg[3]));
#pragma unroll
    for (int o = 16; o; o >>= 1) m = fmaxf(m, __shfl_xor_sync(0xffffffffu, m, o));
    if (lane == 0) redA[warp] = m;
    __syncthreads();
    m = redA[0];
#pragma unroll
    for (int w = 1; w < 8; w++) m = fmaxf(m, redA[w]);
    float e0 = __expf(lg[0] - m), e1 = __expf(lg[1] - m);
    float e2 = __expf(lg[2] - m), e3 = __expf(lg[3] - m);
    float s = (e0 + e1) + (e2 + e3);
#pragma unroll
    for (int o = 16; o; o >>= 1) s += __shfl_xor_sync(0xffffffffu, s, o);
    if (lane == 0) redB[warp] = s;
    __syncthreads();
    s = redB[0];
#pragma unroll
    for (int w = 1; w < 8; w++) s += redB[w];
    float inv = 1.0f / s;
    P[pbase + tid]       = e0 * inv;
    P[pbase + tid + 256] = e1 * inv;
    P[pbase + tid + 512] = e2 * inv;
    P[pbase + tid + 768] = e3 * inv;
}

// ---------------- build A: transpose + powers, fp32 -> fp16 ----------------
__global__ void __launch_bounds__(256) k_buildA(const float* __restrict__ P,
                                                const float* __restrict__ D,
                                                __half* __restrict__ A) {
    __shared__ float sP[32][33], sD[32][33];
    int b = blockIdx.z, ct = blockIdx.y, nt = blockIdx.x, tid = threadIdx.x;
#pragma unroll
    for (int k = 0; k < 4; k++) {
        int idx = tid + (k << 8);
        int r = idx >> 5, j = idx & 31;
        int c = (ct << 5) + r, n = (nt << 5) + j;
        float pv = 0.f, dv = 0.f;
        if (c < NC) {
            size_t g = ((size_t)(b * NC + c) << 10) + n;
            pv = P[g]; dv = D[g];
        }
        sP[r][j] = pv; sD[r][j] = dv;
    }
    __syncthreads();
#pragma unroll
    for (int k = 0; k < 4; k++) {
        int idx = tid + (k << 8);
        int rn = idx >> 5, jc = idx & 31;
        int n = (nt << 5) + rn, c = (ct << 5) + jc;
        float p = sP[jc][rn], d = sD[jc][rn];
        float d2 = d * d;
        __half* row = A + ((size_t)((b << 10) + n)) * KK + c;
        row[0]    = __float2half(p);
        row[1024] = __float2half(p * d);
        row[2048] = __float2half(p * d * d2);
        row[3072] = __float2half(p * d * d2 * d2);
    }
}

// ---------------- build B: coef(kp,h) * u[b,c,h] -> [h][kp*1024+c] ----------------
template<int H>
__global__ void __launch_bounds__(256) k_buildB(const float* __restrict__ u,
                                                const float* __restrict__ W,
                                                __half* __restrict__ Bm) {
    __shared__ float sU[32][33];
    int b = blockIdx.z, ht = blockIdx.y, ct = blockIdx.x, tid = threadIdx.x;
#pragma unroll
    for (int k = 0; k < 4; k++) {
        int idx = tid + (k << 8);
        int r = idx >> 5, j = idx & 31;
        sU[r][j] = u[((size_t)((b << 10) + (ct << 5) + r)) * H + (ht << 5) + j];
    }
    __syncthreads();
#pragma unroll
    for (int k = 0; k < 4; k++) {
        int idx = tid + (k << 8);
        int rh = idx >> 5, jc = idx & 31;
        int h = (ht << 5) + rh, c = (ct << 5) + jc;
        float uu = sU[jc][rh];
        float w = W[h], w2 = w * w;
        __half* row = Bm + ((size_t)(b * 128 + h)) * KK + c;
        row[0]    = __float2half(0.5f * uu);
        row[1024] = __float2half(PC1 * w * uu);
        row[2048] = __float2half(PC3 * w * w2 * uu);
        row[3072] = __float2half(PC5 * w * w2 * w2 * uu);
    }
}

// ---------------- mma.sync GEMM: L[b,i,h] = A[b,i,:] . B[b,h,:], K=4096 ----------------
template<int H>
__global__ void __launch_bounds__(256, 1) k_mma(const __half* __restrict__ A,
                                                const __half* __restrict__ Bm,
                                                float* __restrict__ L) {
    constexpr int STAGE = (128 + H) * 128;       // bytes per stage
    constexpr int NG = (128 + H) * 8 / 256;      // 16B granules per thread per stage
    constexpr int NTILE = H / 2;                 // n-cols per warp
    constexpr int NT8 = NTILE / 8;               // n8 tiles per warp (4 or 8)
    extern __shared__ char dsm[];
    const int tid = threadIdx.x;
    const int wid = tid >> 5, lane = tid & 31;
    const int wm = wid & 3, wn = wid >> 2;
    const int b = blockIdx.y, i0 = blockIdx.x << 7;

    const uint32_t sbase = smem_u32(dsm);
    const __half* Ab = A + ((size_t)(b * NN) + i0) * KK;
    const __half* Bb = Bm + (size_t)b * 128 * KK;

    const __half* lsrc[NG]; uint32_t ldst[NG];
#pragma unroll
    for (int i = 0; i < NG; i++) {
        int idx = tid + (i << 8);
        int row = idx >> 3, g = idx & 7;
        if (row < 128) {
            lsrc[i] = Ab + (size_t)row * KK + (g << 3);
            ldst[i] = sbase + (((row << 3) + (g ^ (row & 7))) << 4);
        } else {
            int h = row - 128;
            lsrc[i] = Bb + (size_t)h * KK + (g << 3);
            ldst[i] = sbase + 16384 + (((h << 3) + (g ^ (h & 7))) << 4);
        }
    }

    float acc[2][NT8][4];
#pragma unroll
    for (int ms = 0; ms < 2; ms++)
#pragma unroll
        for (int j = 0; j < NT8; j++)
#pragma unroll
            for (int q = 0; q < 4; q++) acc[ms][j][q] = 0.f;

#pragma unroll
    for (int i = 0; i < NG; i++) ldgsts16(ldst[i], lsrc[i]);
    asm volatile("cp.async.commit_group;" ::: "memory");

#pragma unroll 1
    for (int ks = 0; ks < 64; ks++) {
        if (ks < 63) {
            int s2 = (ks + 1) & 1;
            int koff = (ks + 1) << 6;
#pragma unroll
            for (int i = 0; i < NG; i++)
                ldgsts16(ldst[i] + s2 * STAGE, lsrc[i] + koff);
            asm volatile("cp.async.commit_group;" ::: "memory");
            asm volatile("cp.async.wait_group 1;" ::: "memory");
        } else {
            asm volatile("cp.async.wait_group 0;" ::: "memory");
        }
        __syncthreads();

        const uint32_t sA = sbase + (ks & 1) * STAGE;
        const uint32_t sB = sA + 16384;
#pragma unroll
        for (int kk = 0; kk < 4; kk++) {
            uint32_t a[2][4];
#pragma unroll
            for (int ms = 0; ms < 2; ms++) {
                int row = wm * 32 + ms * 16 + (lane & 15);
                int g = kk * 2 + (lane >> 4);
                uint32_t addr = sA + (((row << 3) + (g ^ (row & 7))) << 4);
                ldsm_x4(a[ms][0], a[ms][1], a[ms][2], a[ms][3], addr);
            }
#pragma unroll
            for (int nt = 0; nt < NT8 / 2; nt++) {
                uint32_t br[4];
                int h = wn * NTILE + nt * 16 + (lane & 15);
                int g = kk * 2 + (lane >> 4);
                uint32_t addr = sB + (((h << 3) + (g ^ (h & 7))) << 4);
                ldsm_x4(br[0], br[1], br[2], br[3], addr);
#pragma unroll
                for (int ms = 0; ms < 2; ms++) {
                    mma16816(acc[ms][2 * nt],     a[ms][0], a[ms][1], a[ms][2], a[ms][3], br[0], br[2]);
                    mma16816(acc[ms][2 * nt + 1], a[ms][0], a[ms][1], a[ms][2], a[ms][3], br[1], br[3]);
                }
            }
        }
        __syncthreads();
    }

#pragma unroll
    for (int ms = 0; ms < 2; ms++) {
        int r0 = i0 + wm * 32 + ms * 16 + (lane >> 2);
        int cb = wn * NTILE + (lane & 3) * 2;
#pragma unroll
        for (int j = 0; j < NT8; j++) {
            float* p0 = L + ((size_t)(b * NN) + r0) * H + cb + j * 8;
            float* p1 = p0 + 8 * H;
            *(float2*)p0 = make_float2(acc[ms][j][0], acc[ms][j][1]);
            *(float2*)p1 = make_float2(acc[ms][j][2], acc[ms][j][3]);
        }
    }
}

// ---------------- small GEMM epilogue ----------------
template<int K, int NO, bool RELU, bool HAS2, bool HASB, bool HASX>
__global__ void __launch_bounds__(NO * 4) k_gemm(const float* __restrict__ A,
                                                 const float* __restrict__ A2,
                                                 const float* __restrict__ W,
                                                 const float* __restrict__ W2,
                                                 const float* __restrict__ bias,
                                                 const float* __restrict__ xa,
                                                 const float* __restrict__ wx,
                                                 float* __restrict__ out) {
    constexpr int NT = NO * 4;
    __shared__ float sA[16][33];
    __shared__ __align__(16) float sW[32 * NO];
    const int tid = threadIdx.x, rr = tid & 15, cq = tid >> 4;
    const int r0 = blockIdx.x << 4;
    float2 acc0 = f2(0.f), acc1 = f2(0.f);
    const int NP = HAS2 ? 2 : 1;
    for (int pass = 0; pass < NP; pass++) {
        const float* Ap = (HAS2 && pass) ? A2 : A;
        const float* Wp = (HAS2 && pass) ? W2 : W;
        for (int k0 = 0; k0 < K; k0 += 32) {
#pragma unroll
            for (int idx = tid; idx < 512; idx += NT) {
                int r = idx >> 5, c = idx & 31;
                sA[r][c] = Ap[(size_t)(r0 + r) * K + k0 + c];
            }
#pragma unroll
            for (int idx = tid; idx < 32 * NO; idx += NT)
                sW[idx] = Wp[(size_t)(k0 + idx / NO) * NO + (idx & (NO - 1))];
            __syncthreads();
#pragma unroll
            for (int kk = 0; kk < 32; kk++) {
                float a = sA[rr][kk];
                float4 wv = ((const float4*)sW)[kk * (NO / 4) + cq];
                acc0 = fma2(f2(a), make_float2(wv.x, wv.y), acc0);
                acc1 = fma2(f2(a), make_float2(wv.z, wv.w), acc1);
            }
            __syncthreads();
        }
    }
    float4 r;
    r.x = acc0.x; r.y = acc0.y; r.z = acc1.x; r.w = acc1.y;
    size_t orow = (size_t)(r0 + rr) * NO + (cq << 2);
    if (HASX) {
        float xv = xa[r0 + rr];
        float4 wv = ((const float4*)wx)[cq];
        r.x += xv * wv.x; r.y += xv * wv.y; r.z += xv * wv.z; r.w += xv * wv.w;
    }
    if (HASB) {
        float4 bv = ((const float4*)bias)[orow >> 2];
        r.x += bv.x; r.y += bv.y; r.z += bv.z; r.w += bv.w;
    }
    if (RELU) {
        r.x = fmaxf(r.x, 0.f); r.y = fmaxf(r.y, 0.f);
        r.z = fmaxf(r.z, 0.f); r.w = fmaxf(r.w, 0.f);
    }
    ((float4*)out)[orow >> 2] = r;
}

// ---------------- final reduction ----------------
__global__ void __launch_bounds__(256) k_q(const float* __restrict__ g,
                                           const float* __restrict__ wq,
                                           float* __restrict__ out) {
    __shared__ float red[8];
    int b = blockIdx.x, tid = threadIdx.x, lane = tid & 31, warp = tid >> 5;
    const float* gb = g + (size_t)b * NN * 128;
    float acc = 0.f;
    for (int idx = tid; idx < NN * 128; idx += 256)
        acc += gb[idx] * wq[idx & 127];
#pragma unroll
    for (int o = 16; o; o >>= 1) acc += __shfl_xor_sync(0xffffffffu, acc, o);
    if (lane == 0) red[warp] = acc;
    __syncthreads();
    if (tid == 0) {
        float s = 0.f;
#pragma unroll
        for (int w = 0; w < 8; w++) s += red[w];
        out[b] = s;
    }
}

#define GETSYM(p, T, s) do { void* _q = nullptr; cudaGetSymbolAddress(&_q, s); (p) = (T*)_q; } while (0)

extern "C" void kernel_launch(void* const* d_in, const int* in_sizes, int n_in,
                              void* d_out, int out_size) {
    (void)in_sizes; (void)n_in; (void)out_size;
    const float* xs     = (const float*)d_in[0];
    const float* ap     = (const float*)d_in[1];
    const float* ac     = (const float*)d_in[2];
    const float* edge   = (const float*)d_in[3];
    const float* avail  = (const float*)d_in[4];
    const float* ua0    = (const float*)d_in[5];
    const float* g0     = (const float*)d_in[7];
    const float* W1p    = (const float*)d_in[8];
    const float* W2p    = (const float*)d_in[9];
    const float* Wx1a   = (const float*)d_in[10];
    const float* Wemb1a = (const float*)d_in[11];
    const float* Wl1a   = (const float*)d_in[12];
    const float* Wx1b   = (const float*)d_in[13];
    const float* Wl1b   = (const float*)d_in[15];
    const float* Wx2    = (const float*)d_in[16];
    const float* Wemb2  = (const float*)d_in[17];
    const float* Wl2    = (const float*)d_in[18];
    const float* WQ     = (const float*)d_in[19];

    float *pP, *pDm, *pxa, *pla, *puaA, *puaB, *pub, *px2, *pl2, *pgA, *pgB;
    __half *pA, *pB;
    GETSYM(pP, float, g_P);   GETSYM(pDm, float, g_Dm);
    GETSYM(pA, __half, g_A); GETSYM(pB, __half, g_Bop);
    GETSYM(pxa, float, g_xa); GETSYM(pla, float, g_la);
    GETSYM(puaA, float, g_uaA); GETSYM(puaB, float, g_uaB);
    GETSYM(pub, float, g_ub); GETSYM(px2, float, g_x2); GETSYM(pl2, float, g_l2);
    GETSYM(pgA, float, g_gA); GETSYM(pgB, float, g_gB);

    const int smem64  = 2 * (128 + 64) * 128;    // 49152
    const int smem128 = 2 * (128 + 128) * 128;   // 65536
    cudaFuncSetAttribute(k_mma<64>,  cudaFuncAttributeMaxDynamicSharedMemorySize, smem64);
    cudaFuncSetAttribute(k_mma<128>, cudaFuncAttributeMaxDynamicSharedMemorySize, smem128);

    k_xa<<<64, 256>>>(xs, ap, ac, pxa);
    k_presence<<<BB * NC, 256>>>(edge, avail, W1p, W2p, pP, pDm);
    k_buildA<<<dim3(32, 32, BB), 256>>>(pP, pDm, pA);

    // T1: 5 iterations (H = 64)
    const float* uin = ua0;
    for (int it = 0; it < 5; it++) {
        k_buildB<64><<<dim3(32, 2, BB), 256>>>(uin, Wemb1a, pB);
        k_mma<64><<<dim3(8, BB), 256, smem64>>>(pA, pB, pla);
        float* uout = (it & 1) ? puaB : puaA;
        k_gemm<64, 64, true, false, false, true><<<1024, 256>>>(
            pla, nullptr, Wl1a, nullptr, nullptr, pxa, Wx1a, uout);
        if (it == 4)
            k_gemm<64, 64, true, false, false, true><<<1024, 256>>>(
                pla, nullptr, Wl1b, nullptr, nullptr, pxa, Wx1b, pub);
        uin = uout;
    }

    // x2 = [u_a | u_b] @ W_x_2
    k_gemm<64, 128, false, true, false, false><<<1024, 512>>>(
        uin, pub, Wx2, Wx2 + 64 * 128, nullptr, nullptr, nullptr, px2);

    // T2: 5 iterations (H = 128)
    const float* gin = g0;
    for (int it = 0; it < 5; it++) {
        k_buildB<128><<<dim3(32, 4, BB), 256>>>(gin, Wemb2, pB);
        k_mma<128><<<dim3(8, BB), 256, smem128>>>(pA, pB, pl2);
        float* gout = (it & 1) ? pgB : pgA;
        k_gemm<128, 128, true, false, true, false><<<1024, 512>>>(
            pl2, nullptr, Wl2, nullptr, px2, nullptr, nullptr, gout);
        gin = gout;
    }

    k_q<<<BB, 256>>>(gin, WQ, (float*)d_out);
}

// round 6
// speedup vs baseline: 4.2052x; 1.2888x over previous
#include <cuda_runtime.h>
#include <cuda_fp16.h>
#include <cstdint>

#define BB 16
#define NC 1023
#define NN 1024
#define BN (BB*NN)
#define KK 3072
#define KSTEPS (KK/64)

// degree-3 economized sigmoid poly on [-1,1]: sigma(x) ~= 0.5 + B1 x + B3 x^3 (max err ~1.2e-4)
#define PB1 0.24944117f
#define PB3 (-0.01850583f)

// ---------------- static device scratch ----------------
__device__ float g_P [BB*NC*NN];
__device__ float g_Dm[BB*NC*NN];
__device__ __half g_A[(size_t)BB*NN*KK];     // [b][i][kp*1024+c], planes p, p*d, p*d^3
__device__ __half g_Bop[(size_t)BB*128*KK];  // [b][h][kp*1024+c]
__device__ float g_xa[BN];
__device__ float g_uaA[BN*64];
__device__ float g_uaB[BN*64];
__device__ float g_ub [BN*64];
__device__ float g_x2 [BN*128];
__device__ float g_gA [BN*128];
__device__ float g_gB [BN*128];

// ---------------- packed f32x2 helpers ----------------
__device__ __forceinline__ float2 f2(float x) { return make_float2(x, x); }
__device__ __forceinline__ float2 fma2(float2 a, float2 b, float2 c) {
    float2 r;
    asm("fma.rn.f32x2 %0, %1, %2, %3;"
        : "=l"(*(unsigned long long*)&r)
        : "l"(*(unsigned long long*)&a), "l"(*(unsigned long long*)&b),
          "l"(*(unsigned long long*)&c));
    return r;
}
__device__ __forceinline__ float2 mul2(float2 a, float2 b) {
    float2 r;
    asm("mul.rn.f32x2 %0, %1, %2;"
        : "=l"(*(unsigned long long*)&r)
        : "l"(*(unsigned long long*)&a), "l"(*(unsigned long long*)&b));
    return r;
}

__device__ __forceinline__ uint32_t smem_u32(const void* p) {
    uint32_t a;
    asm("{ .reg .u64 t; cvta.to.shared.u64 t, %1; cvt.u32.u64 %0, t; }" : "=r"(a) : "l"(p));
    return a;
}
__device__ __forceinline__ void ldgsts16(uint32_t s, const void* g) {
    asm volatile("cp.async.cg.shared.global [%0], [%1], 16;" :: "r"(s), "l"(g));
}
__device__ __forceinline__ void ldsm_x4(uint32_t& r0, uint32_t& r1, uint32_t& r2,
                                        uint32_t& r3, uint32_t addr) {
    asm volatile("ldmatrix.sync.aligned.m8n8.x4.shared.b16 {%0,%1,%2,%3}, [%4];"
        : "=r"(r0), "=r"(r1), "=r"(r2), "=r"(r3) : "r"(addr));
}
__device__ __forceinline__ void mma16816(float* c, uint32_t a0, uint32_t a1,
                                         uint32_t a2, uint32_t a3,
                                         uint32_t b0, uint32_t b1) {
    asm volatile("mma.sync.aligned.m16n8k16.row.col.f32.f16.f16.f32 "
        "{%0,%1,%2,%3}, {%4,%5,%6,%7}, {%8,%9}, {%0,%1,%2,%3};"
        : "+f"(c[0]), "+f"(c[1]), "+f"(c[2]), "+f"(c[3])
        : "r"(a0), "r"(a1), "r"(a2), "r"(a3), "r"(b0), "r"(b1));
}

// ---------------- x_a ----------------
__global__ void __launch_bounds__(256) k_xa(const float* __restrict__ xs,
                                            const float* __restrict__ ap,
                                            const float* __restrict__ ac,
                                            float* __restrict__ xa) {
    int idx = blockIdx.x * 256 + threadIdx.x;
    int b = idx >> 10, n = idx & (NN - 1);
    float best = -3.4e38f;
#pragma unroll
    for (int r = 0; r < 8; r++) {
        int o = (((b << 3) + r) << 10) + n;
        best = fmaxf(best, xs[o] * (ap[o] + ac[o]));
    }
    xa[idx] = best;
}

// ---------------- presence MLP + masked softmax ----------------
__global__ void __launch_bounds__(256) k_presence(const float* __restrict__ edge,
                                                  const float* __restrict__ avail,
                                                  const float* __restrict__ W1,
                                                  const float* __restrict__ W2,
                                                  float* __restrict__ P,
                                                  float* __restrict__ Dm) {
    __shared__ float sW1[192];
    __shared__ float sW2[64];
    __shared__ float redA[8], redB[8];
    int bc = blockIdx.x;
    int b = bc / NC, c = bc - b * NC;
    int tid = threadIdx.x, lane = tid & 31, warp = tid >> 5;
    if (tid < 192) sW1[tid] = W1[tid];
    if (tid < 64)  sW2[tid] = W2[tid];
    __syncthreads();

    size_t ebase = (size_t)bc * NN * 3;
    size_t pbase = (size_t)bc * NN;
    float lg[4];
#pragma unroll
    for (int j = 0; j < 2; j++) {
        int n0 = tid + j * 512;
        int n1 = n0 + 256;
        float e00 = edge[ebase + (size_t)n0 * 3];
        float e01 = edge[ebase + (size_t)n0 * 3 + 1];
        float e02 = edge[ebase + (size_t)n0 * 3 + 2];
        float e10 = edge[ebase + (size_t)n1 * 3];
        float e11 = edge[ebase + (size_t)n1 * 3 + 1];
        float e12 = edge[ebase + (size_t)n1 * 3 + 2];
        float2 E0 = make_float2(e00, e10);
        float2 E1 = make_float2(e01, e11);
        float2 E2 = make_float2(e02, e12);
        float2 acc = f2(0.f);
#pragma unroll
        for (int h = 0; h < 64; h++) {
            float2 t = mul2(E0, f2(sW1[h]));
            t = fma2(E1, f2(sW1[64 + h]), t);
            t = fma2(E2, f2(sW1[128 + h]), t);
            t.x = fmaxf(t.x, 0.f); t.y = fmaxf(t.y, 0.f);
            acc = fma2(t, f2(sW2[h]), acc);
        }
        float h2a = fmaxf(acc.x, 0.f);
        float h2b = fmaxf(acc.y, 0.f);
        float m0 = (n0 == c ? 0.f : 1.f) * avail[(b << 10) + n0];
        float m1 = (n1 == c ? 0.f : 1.f) * avail[(b << 10) + n1];
        lg[2 * j]     = h2a * m0 - (1.f - m0) * 1e10f;
        lg[2 * j + 1] = h2b * m1 - (1.f - m1) * 1e10f;
        Dm[pbase + n0] = e00;
        Dm[pbase + n1] = e10;
    }
    float m = fmaxf(fmaxf(lg[0], lg[1]), fmaxf(lg[2], lg[3]));
#pragma unroll
    for (int o = 16; o; o >>= 1) m = fmaxf(m, __shfl_xor_sync(0xffffffffu, m, o));
    if (lane == 0) redA[warp] = m;
    __syncthreads();
    m = redA[0];
#pragma unroll
    for (int w = 1; w < 8; w++) m = fmaxf(m, redA[w]);
    float e0 = __expf(lg[0] - m), e1 = __expf(lg[1] - m);
    float e2 = __expf(lg[2] - m), e3 = __expf(lg[3] - m);
    float s = (e0 + e1) + (e2 + e3);
#pragma unroll
    for (int o = 16; o; o >>= 1) s += __shfl_xor_sync(0xffffffffu, s, o);
    if (lane == 0) redB[warp] = s;
    __syncthreads();
    s = redB[0];
#pragma unroll
    for (int w = 1; w < 8; w++) s += redB[w];
    float inv = 1.0f / s;
    P[pbase + tid]       = e0 * inv;
    P[pbase + tid + 256] = e1 * inv;
    P[pbase + tid + 512] = e2 * inv;
    P[pbase + tid + 768] = e3 * inv;
}

// ---------------- build A: transpose + powers {1, d, d^3}, fp32 -> fp16 ----------------
__global__ void __launch_bounds__(256) k_buildA(const float* __restrict__ P,
                                                const float* __restrict__ D,
                                                __half* __restrict__ A) {
    __shared__ float sP[32][33], sD[32][33];
    int b = blockIdx.z, ct = blockIdx.y, nt = blockIdx.x, tid = threadIdx.x;
#pragma unroll
    for (int k = 0; k < 4; k++) {
        int idx = tid + (k << 8);
        int r = idx >> 5, j = idx & 31;
        int c = (ct << 5) + r, n = (nt << 5) + j;
        float pv = 0.f, dv = 0.f;
        if (c < NC) {
            size_t g = ((size_t)(b * NC + c) << 10) + n;
            pv = P[g]; dv = D[g];
        }
        sP[r][j] = pv; sD[r][j] = dv;
    }
    __syncthreads();
#pragma unroll
    for (int k = 0; k < 4; k++) {
        int idx = tid + (k << 8);
        int rn = idx >> 5, jc = idx & 31;
        int n = (nt << 5) + rn, c = (ct << 5) + jc;
        float p = sP[jc][rn], d = sD[jc][rn];
        __half* row = A + ((size_t)((b << 10) + n)) * KK + c;
        row[0]    = __float2half(p);
        row[1024] = __float2half(p * d);
        row[2048] = __float2half(p * d * d * d);
    }
}

// ---------------- build B: planes {0.5u, B1*w*u, B3*w^3*u} -> [h][kp*1024+c] ----------------
template<int H>
__global__ void __launch_bounds__(256) k_buildB(const float* __restrict__ u,
                                                const float* __restrict__ W,
                                                __half* __restrict__ Bm) {
    __shared__ float sU[32][33];
    int b = blockIdx.z, ht = blockIdx.y, ct = blockIdx.x, tid = threadIdx.x;
#pragma unroll
    for (int k = 0; k < 4; k++) {
        int idx = tid + (k << 8);
        int r = idx >> 5, j = idx & 31;
        sU[r][j] = u[((size_t)((b << 10) + (ct << 5) + r)) * H + (ht << 5) + j];
    }
    __syncthreads();
#pragma unroll
    for (int k = 0; k < 4; k++) {
        int idx = tid + (k << 8);
        int rh = idx >> 5, jc = idx & 31;
        int h = (ht << 5) + rh, c = (ct << 5) + jc;
        float uu = sU[jc][rh];
        float w = W[h];
        __half* row = Bm + ((size_t)(b * 128 + h)) * KK + c;
        row[0]    = __float2half(0.5f * uu);
        row[1024] = __float2half(PB1 * w * uu);
        row[2048] = __float2half(PB3 * w * w * w * uu);
    }
}

// ---------------- fused mma GEMM + fp32 epilogue ----------------
// mainloop: l[128,H] = A[128,KK] . B[H,KK]^T  (fp16 mma, fp32 accum)
// epilogue MODE 0: out1 = relu(l@W + xa*wx)
//          MODE 1: MODE0 plus out2 = relu(l@W2 + xa*wxb)
//          MODE 2: out1 = relu(l@W + x2)
template<int H, int MODE>
__global__ void __launch_bounds__(256, 1) k_mma(const __half* __restrict__ A,
                                                const __half* __restrict__ Bm,
                                                const float* __restrict__ Wg,
                                                const float* __restrict__ Wg2,
                                                const float* __restrict__ xa,
                                                const float* __restrict__ wx,
                                                const float* __restrict__ wxb,
                                                const float* __restrict__ x2,
                                                float* __restrict__ out1,
                                                float* __restrict__ out2) {
    constexpr int STAGE = (128 + H) * 128;       // bytes per cp.async stage
    constexpr int NG = (128 + H) / 32;           // 16B granules per thread per stage
    constexpr int NTILE = H / 2;
    constexpr int NT8 = NTILE / 8;
    constexpr int LOFF = 2 * STAGE;              // l tile fp32 [128][H]
    constexpr int WOFF = LOFF + 128 * H * 4;     // W fp32 [H][H]
    constexpr int W2OFF = WOFF + H * H * 4;
    extern __shared__ char dsm[];
    const int tid = threadIdx.x;
    const int wid = tid >> 5, lane = tid & 31;
    const int wm = wid & 3, wn = wid >> 2;
    const int b = blockIdx.y, i0 = blockIdx.x << 7;

    const uint32_t sbase = smem_u32(dsm);
    const __half* Ab = A + ((size_t)(b * NN) + i0) * KK;
    const __half* Bb = Bm + (size_t)b * 128 * KK;

    // stage W (and W2) into smem (runs once; separate region from cp.async stages)
    {
        float4* dst = (float4*)(dsm + WOFF);
        const float4* src = (const float4*)Wg;
        for (int i = tid; i < H * H / 4; i += 256) dst[i] = src[i];
        if (MODE == 1) {
            float4* dst2 = (float4*)(dsm + W2OFF);
            const float4* src2 = (const float4*)Wg2;
            for (int i = tid; i < H * H / 4; i += 256) dst2[i] = src2[i];
        }
    }

    const __half* lsrc[NG]; uint32_t ldst[NG];
#pragma unroll
    for (int i = 0; i < NG; i++) {
        int idx = tid + (i << 8);
        int row = idx >> 3, g = idx & 7;
        if (row < 128) {
            lsrc[i] = Ab + (size_t)row * KK + (g << 3);
            ldst[i] = sbase + (((row << 3) + (g ^ (row & 7))) << 4);
        } else {
            int h = row - 128;
            lsrc[i] = Bb + (size_t)h * KK + (g << 3);
            ldst[i] = sbase + 16384 + (((h << 3) + (g ^ (h & 7))) << 4);
        }
    }

    float acc[2][NT8][4];
#pragma unroll
    for (int ms = 0; ms < 2; ms++)
#pragma unroll
        for (int j = 0; j < NT8; j++)
#pragma unroll
            for (int q = 0; q < 4; q++) acc[ms][j][q] = 0.f;

#pragma unroll
    for (int i = 0; i < NG; i++) ldgsts16(ldst[i], lsrc[i]);
    asm volatile("cp.async.commit_group;" ::: "memory");

#pragma unroll 1
    for (int ks = 0; ks < KSTEPS; ks++) {
        if (ks < KSTEPS - 1) {
            int s2 = (ks + 1) & 1;
            int koff = (ks + 1) << 6;
#pragma unroll
            for (int i = 0; i < NG; i++)
                ldgsts16(ldst[i] + s2 * STAGE, lsrc[i] + koff);
            asm volatile("cp.async.commit_group;" ::: "memory");
            asm volatile("cp.async.wait_group 1;" ::: "memory");
        } else {
            asm volatile("cp.async.wait_group 0;" ::: "memory");
        }
        __syncthreads();

        const uint32_t sA = sbase + (ks & 1) * STAGE;
        const uint32_t sB = sA + 16384;
#pragma unroll
        for (int kk = 0; kk < 4; kk++) {
            uint32_t a[2][4];
#pragma unroll
            for (int ms = 0; ms < 2; ms++) {
                int row = wm * 32 + ms * 16 + (lane & 15);
                int g = kk * 2 + (lane >> 4);
                uint32_t addr = sA + (((row << 3) + (g ^ (row & 7))) << 4);
                ldsm_x4(a[ms][0], a[ms][1], a[ms][2], a[ms][3], addr);
            }
#pragma unroll
            for (int nt = 0; nt < NT8 / 2; nt++) {
                uint32_t br[4];
                int h = wn * NTILE + nt * 16 + (lane & 15);
                int g = kk * 2 + (lane >> 4);
                uint32_t addr = sB + (((h << 3) + (g ^ (h & 7))) << 4);
                ldsm_x4(br[0], br[1], br[2], br[3], addr);
#pragma unroll
                for (int ms = 0; ms < 2; ms++) {
                    mma16816(acc[ms][2 * nt],     a[ms][0], a[ms][1], a[ms][2], a[ms][3], br[0], br[2]);
                    mma16816(acc[ms][2 * nt + 1], a[ms][0], a[ms][1], a[ms][2], a[ms][3], br[1], br[3]);
                }
            }
        }
        __syncthreads();
    }

    // ---- stage l to smem (fp32) ----
    float* lsm = (float*)(dsm + LOFF);
#pragma unroll
    for (int ms = 0; ms < 2; ms++) {
        int r0 = wm * 32 + ms * 16 + (lane >> 2);
        int cb = wn * NTILE + (lane & 3) * 2;
#pragma unroll
        for (int j = 0; j < NT8; j++) {
            *(float2*)(lsm + (size_t)r0 * H + cb + j * 8)       = make_float2(acc[ms][j][0], acc[ms][j][1]);
            *(float2*)(lsm + (size_t)(r0 + 8) * H + cb + j * 8) = make_float2(acc[ms][j][2], acc[ms][j][3]);
        }
    }
    __syncthreads();

    // ---- fp32 epilogue GEMM: out = relu(l @ W + extra) ----
    if (MODE == 2) {
        // H == 128
        const float4* sW4 = (const float4*)(dsm + WOFF);
        const int ct = tid & 31, rt = tid >> 5;
        float2 a0[16], a1[16];
#pragma unroll
        for (int r = 0; r < 16; r++) { a0[r] = f2(0.f); a1[r] = f2(0.f); }
#pragma unroll 4
        for (int k = 0; k < H; k++) {
            float4 wv = sW4[k * (H / 4) + ct];
            float2 w01 = make_float2(wv.x, wv.y), w23 = make_float2(wv.z, wv.w);
            const float* lr = lsm + (size_t)rt * 16 * H + k;
#pragma unroll
            for (int r = 0; r < 16; r++) {
                float lv = lr[r * H];
                a0[r] = fma2(f2(lv), w01, a0[r]);
                a1[r] = fma2(f2(lv), w23, a1[r]);
            }
        }
#pragma unroll
        for (int r = 0; r < 16; r++) {
            int rg = (b << 10) + i0 + rt * 16 + r;
            float4 xv = *(const float4*)(x2 + (size_t)rg * H + ct * 4);
            float4 o;
            o.x = fmaxf(a0[r].x + xv.x, 0.f);
            o.y = fmaxf(a0[r].y + xv.y, 0.f);
            o.z = fmaxf(a1[r].x + xv.z, 0.f);
            o.w = fmaxf(a1[r].y + xv.w, 0.f);
            *(float4*)(out1 + (size_t)rg * H + ct * 4) = o;
        }
    } else {
        // H == 64
        const int ct = tid & 15, rt = tid >> 4;
        const int NPASS = (MODE == 1) ? 2 : 1;
#pragma unroll
        for (int pass = 0; pass < NPASS; pass++) {
            const float4* sW4 = (const float4*)(dsm + (pass ? W2OFF : WOFF));
            const float* wxp = pass ? wxb : wx;
            float* outp = pass ? out2 : out1;
            float2 a0[8], a1[8];
#pragma unroll
            for (int r = 0; r < 8; r++) { a0[r] = f2(0.f); a1[r] = f2(0.f); }
#pragma unroll 4
            for (int k = 0; k < H; k++) {
                float4 wv = sW4[k * (H / 4) + ct];
                float2 w01 = make_float2(wv.x, wv.y), w23 = make_float2(wv.z, wv.w);
                const float* lr = lsm + (size_t)rt * 8 * H + k;
#pragma unroll
                for (int r = 0; r < 8; r++) {
                    float lv = lr[r * H];
                    a0[r] = fma2(f2(lv), w01, a0[r]);
                    a1[r] = fma2(f2(lv), w23, a1[r]);
                }
            }
            float4 wxv = *(const float4*)(wxp + ct * 4);
#pragma unroll
            for (int r = 0; r < 8; r++) {
                int rg = (b << 10) + i0 + rt * 8 + r;
                float xv = xa[rg];
                float4 o;
                o.x = fmaxf(a0[r].x + xv * wxv.x, 0.f);
                o.y = fmaxf(a0[r].y + xv * wxv.y, 0.f);
                o.z = fmaxf(a1[r].x + xv * wxv.z, 0.f);
                o.w = fmaxf(a1[r].y + xv * wxv.w, 0.f);
                *(float4*)(outp + (size_t)rg * H + ct * 4) = o;
            }
        }
    }
}

// ---------------- small GEMM (only for x2 = [u_a|u_b] @ W_x_2) ----------------
template<int K, int NO>
__global__ void __launch_bounds__(NO * 4) k_gemm2(const float* __restrict__ A,
                                                  const float* __restrict__ A2,
                                                  const float* __restrict__ W,
                                                  const float* __restrict__ W2,
                                                  float* __restrict__ out) {
    constexpr int NT = NO * 4;
    __shared__ float sA[16][33];
    __shared__ __align__(16) float sW[32 * NO];
    const int tid = threadIdx.x, rr = tid & 15, cq = tid >> 4;
    const int r0 = blockIdx.x << 4;
    float2 acc0 = f2(0.f), acc1 = f2(0.f);
    for (int pass = 0; pass < 2; pass++) {
        const float* Ap = pass ? A2 : A;
        const float* Wp = pass ? W2 : W;
        for (int k0 = 0; k0 < K; k0 += 32) {
#pragma unroll
            for (int idx = tid; idx < 512; idx += NT) {
                int r = idx >> 5, c = idx & 31;
                sA[r][c] = Ap[(size_t)(r0 + r) * K + k0 + c];
            }
#pragma unroll
            for (int idx = tid; idx < 32 * NO; idx += NT)
                sW[idx] = Wp[(size_t)(k0 + idx / NO) * NO + (idx & (NO - 1))];
            __syncthreads();
#pragma unroll
            for (int kk = 0; kk < 32; kk++) {
                float a = sA[rr][kk];
                float4 wv = ((const float4*)sW)[kk * (NO / 4) + cq];
                acc0 = fma2(f2(a), make_float2(wv.x, wv.y), acc0);
                acc1 = fma2(f2(a), make_float2(wv.z, wv.w), acc1);
            }
            __syncthreads();
        }
    }
    float4 r;
    r.x = acc0.x; r.y = acc0.y; r.z = acc1.x; r.w = acc1.y;
    size_t orow = (size_t)(r0 + rr) * NO + (cq << 2);
    ((float4*)out)[orow >> 2] = r;
}

// ---------------- final reduction ----------------
__global__ void __launch_bounds__(256) k_q(const float* __restrict__ g,
                                           const float* __restrict__ wq,
                                           float* __restrict__ out) {
    __shared__ float red[8];
    int b = blockIdx.x, tid = threadIdx.x, lane = tid & 31, warp = tid >> 5;
    const float* gb = g + (size_t)b * NN * 128;
    float acc = 0.f;
    for (int idx = tid; idx < NN * 128; idx += 256)
        acc += gb[idx] * wq[idx & 127];
#pragma unroll
    for (int o = 16; o; o >>= 1) acc += __shfl_xor_sync(0xffffffffu, acc, o);
    if (lane == 0) red[warp] = acc;
    __syncthreads();
    if (tid == 0) {
        float s = 0.f;
#pragma unroll
        for (int w = 0; w < 8; w++) s += red[w];
        out[b] = s;
    }
}

#define GETSYM(p, T, s) do { void* _q = nullptr; cudaGetSymbolAddress(&_q, s); (p) = (T*)_q; } while (0)

extern "C" void kernel_launch(void* const* d_in, const int* in_sizes, int n_in,
                              void* d_out, int out_size) {
    (void)in_sizes; (void)n_in; (void)out_size;
    const float* xs     = (const float*)d_in[0];
    const float* ap     = (const float*)d_in[1];
    const float* ac     = (const float*)d_in[2];
    const float* edge   = (const float*)d_in[3];
    const float* avail  = (const float*)d_in[4];
    const float* ua0    = (const float*)d_in[5];
    const float* g0     = (const float*)d_in[7];
    const float* W1p    = (const float*)d_in[8];
    const float* W2p    = (const float*)d_in[9];
    const float* Wx1a   = (const float*)d_in[10];
    const float* Wemb1a = (const float*)d_in[11];
    const float* Wl1a   = (const float*)d_in[12];
    const float* Wx1b   = (const float*)d_in[13];
    const float* Wl1b   = (const float*)d_in[15];
    const float* Wx2    = (const float*)d_in[16];
    const float* Wemb2  = (const float*)d_in[17];
    const float* Wl2    = (const float*)d_in[18];
    const float* WQ     = (const float*)d_in[19];

    float *pP, *pDm, *pxa, *puaA, *puaB, *pub, *px2, *pgA, *pgB;
    __half *pA, *pB;
    GETSYM(pP, float, g_P);   GETSYM(pDm, float, g_Dm);
    GETSYM(pA, __half, g_A); GETSYM(pB, __half, g_Bop);
    GETSYM(pxa, float, g_xa);
    GETSYM(puaA, float, g_uaA); GETSYM(puaB, float, g_uaB);
    GETSYM(pub, float, g_ub); GETSYM(px2, float, g_x2);
    GETSYM(pgA, float, g_gA); GETSYM(pgB, float, g_gB);

    // dynamic smem: stages + l + W (+W2)
    const int sm64_0 = 2 * (128 + 64) * 128 + 128 * 64 * 4 + 64 * 64 * 4;            // 98304
    const int sm64_1 = sm64_0 + 64 * 64 * 4;                                          // 114688
    const int sm128  = 2 * (128 + 128) * 128 + 128 * 128 * 4 + 128 * 128 * 4;         // 196608
    cudaFuncSetAttribute(k_mma<64, 0>,  cudaFuncAttributeMaxDynamicSharedMemorySize, sm64_0);
    cudaFuncSetAttribute(k_mma<64, 1>,  cudaFuncAttributeMaxDynamicSharedMemorySize, sm64_1);
    cudaFuncSetAttribute(k_mma<128, 2>, cudaFuncAttributeMaxDynamicSharedMemorySize, sm128);

    k_xa<<<64, 256>>>(xs, ap, ac, pxa);
    k_presence<<<BB * NC, 256>>>(edge, avail, W1p, W2p, pP, pDm);
    k_buildA<<<dim3(32, 32, BB), 256>>>(pP, pDm, pA);

    // T1: 5 iterations (H = 64), epilogue fused
    const float* uin = ua0;
    for (int it = 0; it < 5; it++) {
        k_buildB<64><<<dim3(32, 2, BB), 256>>>(uin, Wemb1a, pB);
        float* uout = (it & 1) ? puaB : puaA;
        if (it < 4)
            k_mma<64, 0><<<dim3(8, BB), 256, sm64_0>>>(
                pA, pB, Wl1a, nullptr, pxa, Wx1a, nullptr, nullptr, uout, nullptr);
        else
            k_mma<64, 1><<<dim3(8, BB), 256, sm64_1>>>(
                pA, pB, Wl1a, Wl1b, pxa, Wx1a, Wx1b, nullptr, uout, pub);
        uin = uout;
    }

    // x2 = [u_a | u_b] @ W_x_2
    k_gemm2<64, 128><<<1024, 512>>>(uin, pub, Wx2, Wx2 + 64 * 128, px2);

    // T2: 5 iterations (H = 128), epilogue fused
    const float* gin = g0;
    for (int it = 0; it < 5; it++) {
        k_buildB<128><<<dim3(32, 4, BB), 256>>>(gin, Wemb2, pB);
        float* gout = (it & 1) ? pgB : pgA;
        k_mma<128, 2><<<dim3(8, BB), 256, sm128>>>(
            pA, pB, Wl2, nullptr, nullptr, nullptr, nullptr, px2, gout, nullptr);
        gin = gout;
    }

    k_q<<<BB, 256>>>(gin, WQ, (float*)d_out);
}

// round 7
// speedup vs baseline: 4.2250x; 1.0047x over previous
#include <cuda_runtime.h>
#include <cuda_fp16.h>
#include <cstdint>

#define BB 16
#define NC 1023
#define NN 1024
#define BN (BB*NN)
#define KK 3072
#define KSTEPS (KK/64)

// degree-3 economized sigmoid poly on [-1,1]: sigma(x) ~= 0.5 + B1 x + B3 x^3 (max err ~1.2e-4)
#define PB1 0.24944117f
#define PB3 (-0.01850583f)

// ---------------- static device scratch ----------------
__device__ float g_P [BB*NC*NN];
__device__ float g_Dm[BB*NC*NN];
__device__ __half g_A[(size_t)BB*NN*KK];     // [b][i][kp*1024+c], planes p, p*d, p*d^3
__device__ __half g_Bop[(size_t)BB*128*KK];  // [b][h][kp*1024+c]
__device__ float g_xa[BN];
__device__ float g_uaA[BN*64];
__device__ float g_uaB[BN*64];
__device__ float g_ub [BN*64];
__device__ float g_x2 [BN*128];
__device__ float g_gA [BN*128];
__device__ float g_gB [BN*128];

// ---------------- packed f32x2 helpers ----------------
__device__ __forceinline__ float2 f2(float x) { return make_float2(x, x); }
__device__ __forceinline__ float2 fma2(float2 a, float2 b, float2 c) {
    float2 r;
    asm("fma.rn.f32x2 %0, %1, %2, %3;"
        : "=l"(*(unsigned long long*)&r)
        : "l"(*(unsigned long long*)&a), "l"(*(unsigned long long*)&b),
          "l"(*(unsigned long long*)&c));
    return r;
}
__device__ __forceinline__ float2 mul2(float2 a, float2 b) {
    float2 r;
    asm("mul.rn.f32x2 %0, %1, %2;"
        : "=l"(*(unsigned long long*)&r)
        : "l"(*(unsigned long long*)&a), "l"(*(unsigned long long*)&b));
    return r;
}

__device__ __forceinline__ uint32_t smem_u32(const void* p) {
    uint32_t a;
    asm("{ .reg .u64 t; cvta.to.shared.u64 t, %1; cvt.u32.u64 %0, t; }" : "=r"(a) : "l"(p));
    return a;
}
__device__ __forceinline__ void ldgsts16(uint32_t s, const void* g) {
    asm volatile("cp.async.cg.shared.global [%0], [%1], 16;" :: "r"(s), "l"(g));
}
__device__ __forceinline__ void ldsm_x4(uint32_t& r0, uint32_t& r1, uint32_t& r2,
                                        uint32_t& r3, uint32_t addr) {
    asm volatile("ldmatrix.sync.aligned.m8n8.x4.shared.b16 {%0,%1,%2,%3}, [%4];"
        : "=r"(r0), "=r"(r1), "=r"(r2), "=r"(r3) : "r"(addr));
}
__device__ __forceinline__ void mma16816(float* c, uint32_t a0, uint32_t a1,
                                         uint32_t a2, uint32_t a3,
                                         uint32_t b0, uint32_t b1) {
    asm volatile("mma.sync.aligned.m16n8k16.row.col.f32.f16.f16.f32 "
        "{%0,%1,%2,%3}, {%4,%5,%6,%7}, {%8,%9}, {%0,%1,%2,%3};"
        : "+f"(c[0]), "+f"(c[1]), "+f"(c[2]), "+f"(c[3])
        : "r"(a0), "r"(a1), "r"(a2), "r"(a3), "r"(b0), "r"(b1));
}

// ---------------- x_a ----------------
__global__ void __launch_bounds__(256) k_xa(const float* __restrict__ xs,
                                            const float* __restrict__ ap,
                                            const float* __restrict__ ac,
                                            float* __restrict__ xa) {
    int idx = blockIdx.x * 256 + threadIdx.x;
    int b = idx >> 10, n = idx & (NN - 1);
    float best = -3.4e38f;
#pragma unroll
    for (int r = 0; r < 8; r++) {
        int o = (((b << 3) + r) << 10) + n;
        best = fmaxf(best, xs[o] * (ap[o] + ac[o]));
    }
    xa[idx] = best;
}

// ---------------- presence MLP + masked softmax ----------------
__global__ void __launch_bounds__(256) k_presence(const float* __restrict__ edge,
                                                  const float* __restrict__ avail,
                                                  const float* __restrict__ W1,
                                                  const float* __restrict__ W2,
                                                  float* __restrict__ P,
                                                  float* __restrict__ Dm) {
    __shared__ float sW1[192];
    __shared__ float sW2[64];
    __shared__ float redA[8], redB[8];
    int bc = blockIdx.x;
    int b = bc / NC, c = bc - b * NC;
    int tid = threadIdx.x, lane = tid & 31, warp = tid >> 5;
    if (tid < 192) sW1[tid] = W1[tid];
    if (tid < 64)  sW2[tid] = W2[tid];
    __syncthreads();

    size_t ebase = (size_t)bc * NN * 3;
    size_t pbase = (size_t)bc * NN;
    float lg[4];
#pragma unroll
    for (int j = 0; j < 2; j++) {
        int n0 = tid + j * 512;
        int n1 = n0 + 256;
        float e00 = edge[ebase + (size_t)n0 * 3];
        float e01 = edge[ebase + (size_t)n0 * 3 + 1];
        float e02 = edge[ebase + (size_t)n0 * 3 + 2];
        float e10 = edge[ebase + (size_t)n1 * 3];
        float e11 = edge[ebase + (size_t)n1 * 3 + 1];
        float e12 = edge[ebase + (size_t)n1 * 3 + 2];
        float2 E0 = make_float2(e00, e10);
        float2 E1 = make_float2(e01, e11);
        float2 E2 = make_float2(e02, e12);
        float2 acc = f2(0.f);
#pragma unroll
        for (int h = 0; h < 64; h++) {
            float2 t = mul2(E0, f2(sW1[h]));
            t = fma2(E1, f2(sW1[64 + h]), t);
            t = fma2(E2, f2(sW1[128 + h]), t);
            t.x = fmaxf(t.x, 0.f); t.y = fmaxf(t.y, 0.f);
            acc = fma2(t, f2(sW2[h]), acc);
        }
        float h2a = fmaxf(acc.x, 0.f);
        float h2b = fmaxf(acc.y, 0.f);
        float m0 = (n0 == c ? 0.f : 1.f) * avail[(b << 10) + n0];
        float m1 = (n1 == c ? 0.f : 1.f) * avail[(b << 10) + n1];
        lg[2 * j]     = h2a * m0 - (1.f - m0) * 1e10f;
        lg[2 * j + 1] = h2b * m1 - (1.f - m1) * 1e10f;
        Dm[pbase + n0] = e00;
        Dm[pbase + n1] = e10;
    }
    float m = fmaxf(fmaxf(lg[0], lg[1]), fmaxf(lg[2], lg[3]));
#pragma unroll
    for (int o = 16; o; o >>= 1) m = fmaxf(m, __shfl_xor_sync(0xffffffffu, m, o));
    if (lane == 0) redA[warp] = m;
    __syncthreads();
    m = redA[0];
#pragma unroll
    for (int w = 1; w < 8; w++) m = fmaxf(m, redA[w]);
    float e0 = __expf(lg[0] - m), e1 = __expf(lg[1] - m);
    float e2 = __expf(lg[2] - m), e3 = __expf(lg[3] - m);
    float s = (e0 + e1) + (e2 + e3);
#pragma unroll
    for (int o = 16; o; o >>= 1) s += __shfl_xor_sync(0xffffffffu, s, o);
    if (lane == 0) redB[warp] = s;
    __syncthreads();
    s = redB[0];
#pragma unroll
    for (int w = 1; w < 8; w++) s += redB[w];
    float inv = 1.0f / s;
    P[pbase + tid]       = e0 * inv;
    P[pbase + tid + 256] = e1 * inv;
    P[pbase + tid + 512] = e2 * inv;
    P[pbase + tid + 768] = e3 * inv;
}

// ---------------- build A: transpose + powers {1, d, d^3}, fp32 -> fp16 ----------------
__global__ void __launch_bounds__(256) k_buildA(const float* __restrict__ P,
                                                const float* __restrict__ D,
                                                __half* __restrict__ A) {
    __shared__ float sP[32][33], sD[32][33];
    int b = blockIdx.z, ct = blockIdx.y, nt = blockIdx.x, tid = threadIdx.x;
#pragma unroll
    for (int k = 0; k < 4; k++) {
        int idx = tid + (k << 8);
        int r = idx >> 5, j = idx & 31;
        int c = (ct << 5) + r, n = (nt << 5) + j;
        float pv = 0.f, dv = 0.f;
        if (c < NC) {
            size_t g = ((size_t)(b * NC + c) << 10) + n;
            pv = P[g]; dv = D[g];
        }
        sP[r][j] = pv; sD[r][j] = dv;
    }
    __syncthreads();
#pragma unroll
    for (int k = 0; k < 4; k++) {
        int idx = tid + (k << 8);
        int rn = idx >> 5, jc = idx & 31;
        int n = (nt << 5) + rn, c = (ct << 5) + jc;
        float p = sP[jc][rn], d = sD[jc][rn];
        __half* row = A + ((size_t)((b << 10) + n)) * KK + c;
        row[0]    = __float2half(p);
        row[1024] = __float2half(p * d);
        row[2048] = __float2half(p * d * d * d);
    }
}

// ---------------- build B: planes {0.5u, B1*w*u, B3*w^3*u} -> [h][kp*1024+c] ----------------
template<int H>
__global__ void __launch_bounds__(256) k_buildB(const float* __restrict__ u,
                                                const float* __restrict__ W,
                                                __half* __restrict__ Bm) {
    __shared__ float sU[32][33];
    int b = blockIdx.z, ht = blockIdx.y, ct = blockIdx.x, tid = threadIdx.x;
#pragma unroll
    for (int k = 0; k < 4; k++) {
        int idx = tid + (k << 8);
        int r = idx >> 5, j = idx & 31;
        sU[r][j] = u[((size_t)((b << 10) + (ct << 5) + r)) * H + (ht << 5) + j];
    }
    __syncthreads();
#pragma unroll
    for (int k = 0; k < 4; k++) {
        int idx = tid + (k << 8);
        int rh = idx >> 5, jc = idx & 31;
        int h = (ht << 5) + rh, c = (ct << 5) + jc;
        float uu = sU[jc][rh];
        float w = W[h];
        __half* row = Bm + ((size_t)(b * 128 + h)) * KK + c;
        row[0]    = __float2half(0.5f * uu);
        row[1024] = __float2half(PB1 * w * uu);
        row[2048] = __float2half(PB3 * w * w * w * uu);
    }
}

// ---------------- fused mma GEMM + fp32 epilogue ----------------
// mainloop: l[128,H] = A[128,KK] . B[H,KK]^T  (fp16 mma, fp32 accum)
// epilogue MODE 0: out1 = relu(l@W + xa*wx)
//          MODE 1: MODE0 plus out2 = relu(l@W2 + xa*wxb)
//          MODE 2: out1 = relu(l@W + x2)
template<int H, int MODE>
__global__ void __launch_bounds__(256, 1) k_mma(const __half* __restrict__ A,
                                                const __half* __restrict__ Bm,
                                                const float* __restrict__ Wg,
                                                const float* __restrict__ Wg2,
                                                const float* __restrict__ xa,
                                                const float* __restrict__ wx,
                                                const float* __restrict__ wxb,
                                                const float* __restrict__ x2,
                                                float* __restrict__ out1,
                                                float* __restrict__ out2) {
    constexpr int STAGE = (128 + H) * 128;       // bytes per cp.async stage
    constexpr int NG = (128 + H) / 32;           // 16B granules per thread per stage
    constexpr int NTILE = H / 2;
    constexpr int NT8 = NTILE / 8;
    constexpr int LOFF = 2 * STAGE;              // l tile fp32 [128][H]
    constexpr int WOFF = LOFF + 128 * H * 4;     // W fp32 [H][H]
    constexpr int W2OFF = WOFF + H * H * 4;
    extern __shared__ char dsm[];
    const int tid = threadIdx.x;
    const int wid = tid >> 5, lane = tid & 31;
    const int wm = wid & 3, wn = wid >> 2;
    const int b = blockIdx.y, i0 = blockIdx.x << 7;

    const uint32_t sbase = smem_u32(dsm);
    const __half* Ab = A + ((size_t)(b * NN) + i0) * KK;
    const __half* Bb = Bm + (size_t)b * 128 * KK;

    // stage W (and W2) into smem (runs once; separate region from cp.async stages)
    {
        float4* dst = (float4*)(dsm + WOFF);
        const float4* src = (const float4*)Wg;
        for (int i = tid; i < H * H / 4; i += 256) dst[i] = src[i];
        if (MODE == 1) {
            float4* dst2 = (float4*)(dsm + W2OFF);
            const float4* src2 = (const float4*)Wg2;
            for (int i = tid; i < H * H / 4; i += 256) dst2[i] = src2[i];
        }
    }

    const __half* lsrc[NG]; uint32_t ldst[NG];
#pragma unroll
    for (int i = 0; i < NG; i++) {
        int idx = tid + (i << 8);
        int row = idx >> 3, g = idx & 7;
        if (row < 128) {
            lsrc[i] = Ab + (size_t)row * KK + (g << 3);
            ldst[i] = sbase + (((row << 3) + (g ^ (row & 7))) << 4);
        } else {
            int h = row - 128;
            lsrc[i] = Bb + (size_t)h * KK + (g << 3);
            ldst[i] = sbase + 16384 + (((h << 3) + (g ^ (h & 7))) << 4);
        }
    }

    float acc[2][NT8][4];
#pragma unroll
    for (int ms = 0; ms < 2; ms++)
#pragma unroll
        for (int j = 0; j < NT8; j++)
#pragma unroll
            for (int q = 0; q < 4; q++) acc[ms][j][q] = 0.f;

#pragma unroll
    for (int i = 0; i < NG; i++) ldgsts16(ldst[i], lsrc[i]);
    asm volatile("cp.async.commit_group;" ::: "memory");

#pragma unroll 1
    for (int ks = 0; ks < KSTEPS; ks++) {
        if (ks < KSTEPS - 1) {
            int s2 = (ks + 1) & 1;
            int koff = (ks + 1) << 6;
#pragma unroll
            for (int i = 0; i < NG; i++)
                ldgsts16(ldst[i] + s2 * STAGE, lsrc[i] + koff);
            asm volatile("cp.async.commit_group;" ::: "memory");
            asm volatile("cp.async.wait_group 1;" ::: "memory");
        } else {
            asm volatile("cp.async.wait_group 0;" ::: "memory");
        }
        __syncthreads();

        const uint32_t sA = sbase + (ks & 1) * STAGE;
        const uint32_t sB = sA + 16384;
#pragma unroll
        for (int kk = 0; kk < 4; kk++) {
            uint32_t a[2][4];
#pragma unroll
            for (int ms = 0; ms < 2; ms++) {
                int row = wm * 32 + ms * 16 + (lane & 15);
                int g = kk * 2 + (lane >> 4);
                uint32_t addr = sA + (((row << 3) + (g ^ (row & 7))) << 4);
                ldsm_x4(a[ms][0], a[ms][1], a[ms][2], a[ms][3], addr);
            }
#pragma unroll
            for (int nt = 0; nt < NT8 / 2; nt++) {
                uint32_t br[4];
                int h = wn * NTILE + nt * 16 + (lane & 15);
                int g = kk * 2 + (lane >> 4);
                uint32_t addr = sB + (((h << 3) + (g ^ (h & 7))) << 4);
                ldsm_x4(br[0], br[1], br[2], br[3], addr);
#pragma unroll
                for (int ms = 0; ms < 2; ms++) {
                    mma16816(acc[ms][2 * nt],     a[ms][0], a[ms][1], a[ms][2], a[ms][3], br[0], br[2]);
                    mma16816(acc[ms][2 * nt + 1], a[ms][0], a[ms][1], a[ms][2], a[ms][3], br[1], br[3]);
                }
            }
        }
        __syncthreads();
    }

    // ---- stage l to smem (fp32) ----
    float* lsm = (float*)(dsm + LOFF);
#pragma unroll
    for (int ms = 0; ms < 2; ms++) {
        int r0 = wm * 32 + ms * 16 + (lane >> 2);
        int cb = wn * NTILE + (lane & 3) * 2;
#pragma unroll
        for (int j = 0; j < NT8; j++) {
            *(float2*)(lsm + (size_t)r0 * H + cb + j * 8)       = make_float2(acc[ms][j][0], acc[ms][j][1]);
            *(float2*)(lsm + (size_t)(r0 + 8) * H + cb + j * 8) = make_float2(acc[ms][j][2], acc[ms][j][3]);
        }
    }
    __syncthreads();

    // ---- fp32 epilogue GEMM: out = relu(l @ W + extra) ----
    if (MODE == 2) {
        // H == 128
        const float4* sW4 = (const float4*)(dsm + WOFF);
        const int ct = tid & 31, rt = tid >> 5;
        float2 a0[16], a1[16];
#pragma unroll
        for (int r = 0; r < 16; r++) { a0[r] = f2(0.f); a1[r] = f2(0.f); }
#pragma unroll 4
        for (int k = 0; k < H; k++) {
            float4 wv = sW4[k * (H / 4) + ct];
            float2 w01 = make_float2(wv.x, wv.y), w23 = make_float2(wv.z, wv.w);
            const float* lr = lsm + (size_t)rt * 16 * H + k;
#pragma unroll
            for (int r = 0; r < 16; r++) {
                float lv = lr[r * H];
                a0[r] = fma2(f2(lv), w01, a0[r]);
                a1[r] = fma2(f2(lv), w23, a1[r]);
            }
        }
#pragma unroll
        for (int r = 0; r < 16; r++) {
            int rg = (b << 10) + i0 + rt * 16 + r;
            float4 xv = *(const float4*)(x2 + (size_t)rg * H + ct * 4);
            float4 o;
            o.x = fmaxf(a0[r].x + xv.x, 0.f);
            o.y = fmaxf(a0[r].y + xv.y, 0.f);
            o.z = fmaxf(a1[r].x + xv.z, 0.f);
            o.w = fmaxf(a1[r].y + xv.w, 0.f);
            *(float4*)(out1 + (size_t)rg * H + ct * 4) = o;
        }
    } else {
        // H == 64
        const int ct = tid & 15, rt = tid >> 4;
        const int NPASS = (MODE == 1) ? 2 : 1;
#pragma unroll
        for (int pass = 0; pass < NPASS; pass++) {
            const float4* sW4 = (const float4*)(dsm + (pass ? W2OFF : WOFF));
            const float* wxp = pass ? wxb : wx;
            float* outp = pass ? out2 : out1;
            float2 a0[8], a1[8];
#pragma unroll
            for (int r = 0; r < 8; r++) { a0[r] = f2(0.f); a1[r] = f2(0.f); }
#pragma unroll 4
            for (int k = 0; k < H; k++) {
                float4 wv = sW4[k * (H / 4) + ct];
                float2 w01 = make_float2(wv.x, wv.y), w23 = make_float2(wv.z, wv.w);
                const float* lr = lsm + (size_t)rt * 8 * H + k;
#pragma unroll
                for (int r = 0; r < 8; r++) {
                    float lv = lr[r * H];
                    a0[r] = fma2(f2(lv), w01, a0[r]);
                    a1[r] = fma2(f2(lv), w23, a1[r]);
                }
            }
            float4 wxv = *(const float4*)(wxp + ct * 4);
#pragma unroll
            for (int r = 0; r < 8; r++) {
                int rg = (b << 10) + i0 + rt * 8 + r;
                float xv = xa[rg];
                float4 o;
                o.x = fmaxf(a0[r].x + xv * wxv.x, 0.f);
                o.y = fmaxf(a0[r].y + xv * wxv.y, 0.f);
                o.z = fmaxf(a1[r].x + xv * wxv.z, 0.f);
                o.w = fmaxf(a1[r].y + xv * wxv.w, 0.f);
                *(float4*)(outp + (size_t)rg * H + ct * 4) = o;
            }
        }
    }
}

// ---------------- small GEMM (only for x2 = [u_a|u_b] @ W_x_2) ----------------
template<int K, int NO>
__global__ void __launch_bounds__(NO * 4) k_gemm2(const float* __restrict__ A,
                                                  const float* __restrict__ A2,
                                                  const float* __restrict__ W,
                                                  const float* __restrict__ W2,
                                                  float* __restrict__ out) {
    constexpr int NT = NO * 4;
    __shared__ float sA[16][33];
    __shared__ __align__(16) float sW[32 * NO];
    const int tid = threadIdx.x, rr = tid & 15, cq = tid >> 4;
    const int r0 = blockIdx.x << 4;
    float2 acc0 = f2(0.f), acc1 = f2(0.f);
    for (int pass = 0; pass < 2; pass++) {
        const float* Ap = pass ? A2 : A;
        const float* Wp = pass ? W2 : W;
        for (int k0 = 0; k0 < K; k0 += 32) {
#pragma unroll
            for (int idx = tid; idx < 512; idx += NT) {
                int r = idx >> 5, c = idx & 31;
                sA[r][c] = Ap[(size_t)(r0 + r) * K + k0 + c];
            }
#pragma unroll
            for (int idx = tid; idx < 32 * NO; idx += NT)
                sW[idx] = Wp[(size_t)(k0 + idx / NO) * NO + (idx & (NO - 1))];
            __syncthreads();
#pragma unroll
            for (int kk = 0; kk < 32; kk++) {
                float a = sA[rr][kk];
                float4 wv = ((const float4*)sW)[kk * (NO / 4) + cq];
                acc0 = fma2(f2(a), make_float2(wv.x, wv.y), acc0);
                acc1 = fma2(f2(a), make_float2(wv.z, wv.w), acc1);
            }
            __syncthreads();
        }
    }
    float4 r;
    r.x = acc0.x; r.y = acc0.y; r.z = acc1.x; r.w = acc1.y;
    size_t orow = (size_t)(r0 + rr) * NO + (cq << 2);
    ((float4*)out)[orow >> 2] = r;
}

// ---------------- final reduction ----------------
__global__ void __launch_bounds__(256) k_q(const float* __restrict__ g,
                                           const float* __restrict__ wq,
                                           float* __restrict__ out) {
    __shared__ float red[8];
    int b = blockIdx.x, tid = threadIdx.x, lane = tid & 31, warp = tid >> 5;
    const float* gb = g + (size_t)b * NN * 128;
    float acc = 0.f;
    for (int idx = tid; idx < NN * 128; idx += 256)
        acc += gb[idx] * wq[idx & 127];
#pragma unroll
    for (int o = 16; o; o >>= 1) acc += __shfl_xor_sync(0xffffffffu, acc, o);
    if (lane == 0) red[warp] = acc;
    __syncthreads();
    if (tid == 0) {
        float s = 0.f;
#pragma unroll
        for (int w = 0; w < 8; w++) s += red[w];
        out[b] = s;
    }
}

#define GETSYM(p, T, s) do { void* _q = nullptr; cudaGetSymbolAddress(&_q, s); (p) = (T*)_q; } while (0)

extern "C" void kernel_launch(void* const* d_in, const int* in_sizes, int n_in,
                              void* d_out, int out_size) {
    (void)in_sizes; (void)n_in; (void)out_size;
    const float* xs     = (const float*)d_in[0];
    const float* ap     = (const float*)d_in[1];
    const float* ac     = (const float*)d_in[2];
    const float* edge   = (const float*)d_in[3];
    const float* avail  = (const float*)d_in[4];
    const float* ua0    = (const float*)d_in[5];
    const float* g0     = (const float*)d_in[7];
    const float* W1p    = (const float*)d_in[8];
    const float* W2p    = (const float*)d_in[9];
    const float* Wx1a   = (const float*)d_in[10];
    const float* Wemb1a = (const float*)d_in[11];
    const float* Wl1a   = (const float*)d_in[12];
    const float* Wx1b   = (const float*)d_in[13];
    const float* Wl1b   = (const float*)d_in[15];
    const float* Wx2    = (const float*)d_in[16];
    const float* Wemb2  = (const float*)d_in[17];
    const float* Wl2    = (const float*)d_in[18];
    const float* WQ     = (const float*)d_in[19];

    float *pP, *pDm, *pxa, *puaA, *puaB, *pub, *px2, *pgA, *pgB;
    __half *pA, *pB;
    GETSYM(pP, float, g_P);   GETSYM(pDm, float, g_Dm);
    GETSYM(pA, __half, g_A); GETSYM(pB, __half, g_Bop);
    GETSYM(pxa, float, g_xa);
    GETSYM(puaA, float, g_uaA); GETSYM(puaB, float, g_uaB);
    GETSYM(pub, float, g_ub); GETSYM(px2, float, g_x2);
    GETSYM(pgA, float, g_gA); GETSYM(pgB, float, g_gB);

    // dynamic smem: stages + l + W (+W2)
    const int sm64_0 = 2 * (128 + 64) * 128 + 128 * 64 * 4 + 64 * 64 * 4;            // 98304
    const int sm64_1 = sm64_0 + 64 * 64 * 4;                                          // 114688
    const int sm128  = 2 * (128 + 128) * 128 + 128 * 128 * 4 + 128 * 128 * 4;         // 196608
    cudaFuncSetAttribute(k_mma<64, 0>,  cudaFuncAttributeMaxDynamicSharedMemorySize, sm64_0);
    cudaFuncSetAttribute(k_mma<64, 1>,  cudaFuncAttributeMaxDynamicSharedMemorySize, sm64_1);
    cudaFuncSetAttribute(k_mma<128, 2>, cudaFuncAttributeMaxDynamicSharedMemorySize, sm128);

    k_xa<<<64, 256>>>(xs, ap, ac, pxa);
    k_presence<<<BB * NC, 256>>>(edge, avail, W1p, W2p, pP, pDm);
    k_buildA<<<dim3(32, 32, BB), 256>>>(pP, pDm, pA);

    // T1: 5 iterations (H = 64), epilogue fused
    const float* uin = ua0;
    for (int it = 0; it < 5; it++) {
        k_buildB<64><<<dim3(32, 2, BB), 256>>>(uin, Wemb1a, pB);
        float* uout = (it & 1) ? puaB : puaA;
        if (it < 4)
            k_mma<64, 0><<<dim3(8, BB), 256, sm64_0>>>(
                pA, pB, Wl1a, nullptr, pxa, Wx1a, nullptr, nullptr, uout, nullptr);
        else
            k_mma<64, 1><<<dim3(8, BB), 256, sm64_1>>>(
                pA, pB, Wl1a, Wl1b, pxa, Wx1a, Wx1b, nullptr, uout, pub);
        uin = uout;
    }

    // x2 = [u_a | u_b] @ W_x_2
    k_gemm2<64, 128><<<1024, 512>>>(uin, pub, Wx2, Wx2 + 64 * 128, px2);

    // T2: 5 iterations (H = 128), epilogue fused
    const float* gin = g0;
    for (int it = 0; it < 5; it++) {
        k_buildB<128><<<dim3(32, 4, BB), 256>>>(gin, Wemb2, pB);
        float* gout = (it & 1) ? pgB : pgA;
        k_mma<128, 2><<<dim3(8, BB), 256, sm128>>>(
            pA, pB, Wl2, nullptr, nullptr, nullptr, nullptr, px2, gout, nullptr);
        gin = gout;
    }

    k_q<<<BB, 256>>>(gin, WQ, (float*)d_out);
}

// round 8
// speedup vs baseline: 4.2636x; 1.0091x over previous
#include <cuda_runtime.h>
#include <cuda_fp16.h>
#include <cstdint>

#define BB 16
#define NC 1023
#define NN 1024
#define BN (BB*NN)
#define KK 3072
#define KSTEPS (KK/64)

// degree-3 economized sigmoid poly on [-1,1]: sigma(x) ~= 0.5 + B1 x + B3 x^3 (max err ~1.2e-4)
#define PB1 0.24944117f
#define PB3 (-0.01850583f)

// ---------------- static device scratch ----------------
__device__ float g_P [BB*NC*NN];
__device__ float g_Dm[BB*NC*NN];
__device__ __half g_A[(size_t)BB*NN*KK];      // [b][i][kp*1024+c], planes p, p*d, p*d^3
__device__ __half g_B0[(size_t)BB*128*KK];    // B ping
__device__ __half g_B1[(size_t)BB*128*KK];    // B pong
__device__ float g_xa[BN];
__device__ float g_uaA[BN*64];
__device__ float g_uaB[BN*64];
__device__ float g_ub [BN*64];
__device__ float g_x2 [BN*128];
__device__ float g_gA [BN*128];
__device__ float g_gB [BN*128];

// ---------------- packed f32x2 helpers ----------------
__device__ __forceinline__ float2 f2(float x) { return make_float2(x, x); }
__device__ __forceinline__ float2 fma2(float2 a, float2 b, float2 c) {
    float2 r;
    asm("fma.rn.f32x2 %0, %1, %2, %3;"
        : "=l"(*(unsigned long long*)&r)
        : "l"(*(unsigned long long*)&a), "l"(*(unsigned long long*)&b),
          "l"(*(unsigned long long*)&c));
    return r;
}
__device__ __forceinline__ float2 mul2(float2 a, float2 b) {
    float2 r;
    asm("mul.rn.f32x2 %0, %1, %2;"
        : "=l"(*(unsigned long long*)&r)
        : "l"(*(unsigned long long*)&a), "l"(*(unsigned long long*)&b));
    return r;
}

__device__ __forceinline__ uint32_t smem_u32(const void* p) {
    uint32_t a;
    asm("{ .reg .u64 t; cvta.to.shared.u64 t, %1; cvt.u32.u64 %0, t; }" : "=r"(a) : "l"(p));
    return a;
}
__device__ __forceinline__ void ldgsts16(uint32_t s, const void* g) {
    asm volatile("cp.async.cg.shared.global [%0], [%1], 16;" :: "r"(s), "l"(g));
}
__device__ __forceinline__ void ldsm_x4(uint32_t& r0, uint32_t& r1, uint32_t& r2,
                                        uint32_t& r3, uint32_t addr) {
    asm volatile("ldmatrix.sync.aligned.m8n8.x4.shared.b16 {%0,%1,%2,%3}, [%4];"
        : "=r"(r0), "=r"(r1), "=r"(r2), "=r"(r3) : "r"(addr));
}
__device__ __forceinline__ void mma16816(float* c, uint32_t a0, uint32_t a1,
                                         uint32_t a2, uint32_t a3,
                                         uint32_t b0, uint32_t b1) {
    asm volatile("mma.sync.aligned.m16n8k16.row.col.f32.f16.f16.f32 "
        "{%0,%1,%2,%3}, {%4,%5,%6,%7}, {%8,%9}, {%0,%1,%2,%3};"
        : "+f"(c[0]), "+f"(c[1]), "+f"(c[2]), "+f"(c[3])
        : "r"(a0), "r"(a1), "r"(a2), "r"(a3), "r"(b0), "r"(b1));
}
__device__ __forceinline__ uint32_t pack2h(float a, float b) {
    __half2 h = __floats2half2_rn(a, b);
    return *(uint32_t*)&h;
}

// ---------------- presence MLP + masked softmax ----------------
__global__ void __launch_bounds__(256) k_presence(const float* __restrict__ edge,
                                                  const float* __restrict__ avail,
                                                  const float* __restrict__ W1,
                                                  const float* __restrict__ W2,
                                                  float* __restrict__ P,
                                                  float* __restrict__ Dm) {
    __shared__ float sW1[192];
    __shared__ float sW2[64];
    __shared__ float redA[8], redB[8];
    int bc = blockIdx.x;
    int b = bc / NC, c = bc - b * NC;
    int tid = threadIdx.x, lane = tid & 31, warp = tid >> 5;
    if (tid < 192) sW1[tid] = W1[tid];
    if (tid < 64)  sW2[tid] = W2[tid];
    __syncthreads();

    size_t ebase = (size_t)bc * NN * 3;
    size_t pbase = (size_t)bc * NN;
    float lg[4];
#pragma unroll
    for (int j = 0; j < 2; j++) {
        int n0 = tid + j * 512;
        int n1 = n0 + 256;
        float e00 = edge[ebase + (size_t)n0 * 3];
        float e01 = edge[ebase + (size_t)n0 * 3 + 1];
        float e02 = edge[ebase + (size_t)n0 * 3 + 2];
        float e10 = edge[ebase + (size_t)n1 * 3];
        float e11 = edge[ebase + (size_t)n1 * 3 + 1];
        float e12 = edge[ebase + (size_t)n1 * 3 + 2];
        float2 E0 = make_float2(e00, e10);
        float2 E1 = make_float2(e01, e11);
        float2 E2 = make_float2(e02, e12);
        float2 acc = f2(0.f);
#pragma unroll
        for (int h = 0; h < 64; h++) {
            float2 t = mul2(E0, f2(sW1[h]));
            t = fma2(E1, f2(sW1[64 + h]), t);
            t = fma2(E2, f2(sW1[128 + h]), t);
            t.x = fmaxf(t.x, 0.f); t.y = fmaxf(t.y, 0.f);
            acc = fma2(t, f2(sW2[h]), acc);
        }
        float h2a = fmaxf(acc.x, 0.f);
        float h2b = fmaxf(acc.y, 0.f);
        float m0 = (n0 == c ? 0.f : 1.f) * avail[(b << 10) + n0];
        float m1 = (n1 == c ? 0.f : 1.f) * avail[(b << 10) + n1];
        lg[2 * j]     = h2a * m0 - (1.f - m0) * 1e10f;
        lg[2 * j + 1] = h2b * m1 - (1.f - m1) * 1e10f;
        Dm[pbase + n0] = e00;
        Dm[pbase + n1] = e10;
    }
    float m = fmaxf(fmaxf(lg[0], lg[1]), fmaxf(lg[2], lg[3]));
#pragma unroll
    for (int o = 16; o; o >>= 1) m = fmaxf(m, __shfl_xor_sync(0xffffffffu, m, o));
    if (lane == 0) redA[warp] = m;
    __syncthreads();
    m = redA[0];
#pragma unroll
    for (int w = 1; w < 8; w++) m = fmaxf(m, redA[w]);
    float e0 = __expf(lg[0] - m), e1 = __expf(lg[1] - m);
    float e2 = __expf(lg[2] - m), e3 = __expf(lg[3] - m);
    float s = (e0 + e1) + (e2 + e3);
#pragma unroll
    for (int o = 16; o; o >>= 1) s += __shfl_xor_sync(0xffffffffu, s, o);
    if (lane == 0) redB[warp] = s;
    __syncthreads();
    s = redB[0];
#pragma unroll
    for (int w = 1; w < 8; w++) s += redB[w];
    float inv = 1.0f / s;
    P[pbase + tid]       = e0 * inv;
    P[pbase + tid + 256] = e1 * inv;
    P[pbase + tid + 512] = e2 * inv;
    P[pbase + tid + 768] = e3 * inv;
}

// ---------------- build A: transpose + powers {1, d, d^3}, fp32 -> fp16; also x_a ----------------
__global__ void __launch_bounds__(256) k_buildA(const float* __restrict__ P,
                                                const float* __restrict__ D,
                                                __half* __restrict__ A,
                                                const float* __restrict__ xs,
                                                const float* __restrict__ ap,
                                                const float* __restrict__ ac,
                                                float* __restrict__ xa) {
    __shared__ float sP[32][33], sD[32][33];
    int b = blockIdx.z, ct = blockIdx.y, nt = blockIdx.x, tid = threadIdx.x;
#pragma unroll
    for (int k = 0; k < 4; k++) {
        int idx = tid + (k << 8);
        int r = idx >> 5, j = idx & 31;
        int c = (ct << 5) + r, n = (nt << 5) + j;
        float pv = 0.f, dv = 0.f;
        if (c < NC) {
            size_t g = ((size_t)(b * NC + c) << 10) + n;
            pv = P[g]; dv = D[g];
        }
        sP[r][j] = pv; sD[r][j] = dv;
    }
    __syncthreads();
#pragma unroll
    for (int k = 0; k < 4; k++) {
        int idx = tid + (k << 8);
        int rn = idx >> 5, jc = idx & 31;
        int n = (nt << 5) + rn, c = (ct << 5) + jc;
        float p = sP[jc][rn], d = sD[jc][rn];
        __half* row = A + ((size_t)((b << 10) + n)) * KK + c;
        row[0]    = __float2half(p);
        row[1024] = __float2half(p * d);
        row[2048] = __float2half(p * d * d * d);
    }
    // fused x_a: blocks with ct==0 handle 32 n-values each
    if (ct == 0 && tid < 32) {
        int n = (nt << 5) + tid;
        float best = -3.4e38f;
#pragma unroll
        for (int r = 0; r < 8; r++) {
            int o = (((b << 3) + r) << 10) + n;
            best = fmaxf(best, xs[o] * (ap[o] + ac[o]));
        }
        xa[(b << 10) + n] = best;
    }
}

// ---------------- build B (loop-entry only): planes {0.5u, B1*w*u, B3*w^3*u} ----------------
template<int H>
__global__ void __launch_bounds__(256) k_buildB(const float* __restrict__ u,
                                                const float* __restrict__ W,
                                                __half* __restrict__ Bm) {
    __shared__ float sU[32][33];
    int b = blockIdx.z, ht = blockIdx.y, ct = blockIdx.x, tid = threadIdx.x;
#pragma unroll
    for (int k = 0; k < 4; k++) {
        int idx = tid + (k << 8);
        int r = idx >> 5, j = idx & 31;
        sU[r][j] = u[((size_t)((b << 10) + (ct << 5) + r)) * H + (ht << 5) + j];
    }
    __syncthreads();
#pragma unroll
    for (int k = 0; k < 4; k++) {
        int idx = tid + (k << 8);
        int rh = idx >> 5, jc = idx & 31;
        int h = (ht << 5) + rh, c = (ct << 5) + jc;
        float uu = sU[jc][rh];
        float w = W[h];
        __half* row = Bm + ((size_t)(b * 128 + h)) * KK + c;
        row[0]    = __float2half(0.5f * uu);
        row[1024] = __float2half(PB1 * w * uu);
        row[2048] = __float2half(PB3 * w * w * w * uu);
    }
}

// ---------------- fused mma GEMM + fp32 epilogue (+ optional next-iteration B build) ----
// mainloop: l[128,H] = A[128,KK] . B[H,KK]^T  (fp16 mma, fp32 accum)
// epilogue MODE 0: out1 = relu(l@W + xa*wx)
//          MODE 1: MODE0 plus out2 = relu(l@W2 + xa*wxb)
//          MODE 2: out1 = relu(l@W + x2)
// WB: additionally emit Bout[h][plane*1024 + i0+c] = coef_plane(h) * u[c,h]
template<int H, int MODE, bool WB>
__global__ void __launch_bounds__(256, 1) k_mma(const __half* __restrict__ A,
                                                const __half* __restrict__ Bm,
                                                const float* __restrict__ Wg,
                                                const float* __restrict__ Wg2,
                                                const float* __restrict__ xa,
                                                const float* __restrict__ wx,
                                                const float* __restrict__ wxb,
                                                const float* __restrict__ x2,
                                                float* __restrict__ out1,
                                                float* __restrict__ out2,
                                                const float* __restrict__ Wemb,
                                                __half* __restrict__ Bout) {
    constexpr int STAGE = (128 + H) * 128;       // bytes per cp.async stage
    constexpr int NG = (128 + H) / 32;           // 16B granules per thread per stage
    constexpr int NTILE = H / 2;
    constexpr int NT8 = NTILE / 8;
    constexpr int LOFF = 2 * STAGE;              // l tile fp32 [128][H]
    constexpr int WOFF = LOFF + 128 * H * 4;     // W fp32 [H][H]
    constexpr int W2OFF = WOFF + H * H * 4;
    constexpr int PH = H + 1;                    // transposed-u pitch (floats)
    extern __shared__ char dsm[];
    __shared__ float sWemb[128];
    const int tid = threadIdx.x;
    const int wid = tid >> 5, lane = tid & 31;
    const int wm = wid & 3, wn = wid >> 2;
    const int b = blockIdx.y, i0 = blockIdx.x << 7;

    const uint32_t sbase = smem_u32(dsm);
    const __half* Ab = A + ((size_t)(b * NN) + i0) * KK;
    const __half* Bb = Bm + (size_t)b * 128 * KK;

    // stage W (and W2) into smem; Wemb coefs for B emit
    {
        float4* dst = (float4*)(dsm + WOFF);
        const float4* src = (const float4*)Wg;
        for (int i = tid; i < H * H / 4; i += 256) dst[i] = src[i];
        if (MODE == 1) {
            float4* dst2 = (float4*)(dsm + W2OFF);
            const float4* src2 = (const float4*)Wg2;
            for (int i = tid; i < H * H / 4; i += 256) dst2[i] = src2[i];
        }
        if (WB && tid < H) sWemb[tid] = Wemb[tid];
    }

    const __half* lsrc[NG]; uint32_t ldst[NG];
#pragma unroll
    for (int i = 0; i < NG; i++) {
        int idx = tid + (i << 8);
        int row = idx >> 3, g = idx & 7;
        if (row < 128) {
            lsrc[i] = Ab + (size_t)row * KK + (g << 3);
            ldst[i] = sbase + (((row << 3) + (g ^ (row & 7))) << 4);
        } else {
            int h = row - 128;
            lsrc[i] = Bb + (size_t)h * KK + (g << 3);
            ldst[i] = sbase + 16384 + (((h << 3) + (g ^ (h & 7))) << 4);
        }
    }

    float acc[2][NT8][4];
#pragma unroll
    for (int ms = 0; ms < 2; ms++)
#pragma unroll
        for (int j = 0; j < NT8; j++)
#pragma unroll
            for (int q = 0; q < 4; q++) acc[ms][j][q] = 0.f;

#pragma unroll
    for (int i = 0; i < NG; i++) ldgsts16(ldst[i], lsrc[i]);
    asm volatile("cp.async.commit_group;" ::: "memory");

#pragma unroll 1
    for (int ks = 0; ks < KSTEPS; ks++) {
        if (ks < KSTEPS - 1) {
            int s2 = (ks + 1) & 1;
            int koff = (ks + 1) << 6;
#pragma unroll
            for (int i = 0; i < NG; i++)
                ldgsts16(ldst[i] + s2 * STAGE, lsrc[i] + koff);
            asm volatile("cp.async.commit_group;" ::: "memory");
            asm volatile("cp.async.wait_group 1;" ::: "memory");
        } else {
            asm volatile("cp.async.wait_group 0;" ::: "memory");
        }
        __syncthreads();

        const uint32_t sA = sbase + (ks & 1) * STAGE;
        const uint32_t sB = sA + 16384;
#pragma unroll
        for (int kk = 0; kk < 4; kk++) {
            uint32_t a[2][4];
#pragma unroll
            for (int ms = 0; ms < 2; ms++) {
                int row = wm * 32 + ms * 16 + (lane & 15);
                int g = kk * 2 + (lane >> 4);
                uint32_t addr = sA + (((row << 3) + (g ^ (row & 7))) << 4);
                ldsm_x4(a[ms][0], a[ms][1], a[ms][2], a[ms][3], addr);
            }
#pragma unroll
            for (int nt = 0; nt < NT8 / 2; nt++) {
                uint32_t br[4];
                int h = wn * NTILE + nt * 16 + (lane & 15);
                int g = kk * 2 + (lane >> 4);
                uint32_t addr = sB + (((h << 3) + (g ^ (h & 7))) << 4);
                ldsm_x4(br[0], br[1], br[2], br[3], addr);
#pragma unroll
                for (int ms = 0; ms < 2; ms++) {
                    mma16816(acc[ms][2 * nt],     a[ms][0], a[ms][1], a[ms][2], a[ms][3], br[0], br[2]);
                    mma16816(acc[ms][2 * nt + 1], a[ms][0], a[ms][1], a[ms][2], a[ms][3], br[1], br[3]);
                }
            }
        }
        __syncthreads();
    }

    // ---- stage l to smem (fp32) ----
    float* lsm = (float*)(dsm + LOFF);
#pragma unroll
    for (int ms = 0; ms < 2; ms++) {
        int r0 = wm * 32 + ms * 16 + (lane >> 2);
        int cb = wn * NTILE + (lane & 3) * 2;
#pragma unroll
        for (int j = 0; j < NT8; j++) {
            *(float2*)(lsm + (size_t)r0 * H + cb + j * 8)       = make_float2(acc[ms][j][0], acc[ms][j][1]);
            *(float2*)(lsm + (size_t)(r0 + 8) * H + cb + j * 8) = make_float2(acc[ms][j][2], acc[ms][j][3]);
        }
    }
    __syncthreads();

    // ---- fp32 epilogue GEMM: out = relu(l @ W + extra) ----
    float* l2 = (float*)(dsm + LOFF);   // transposed-u overlay (l/W regions dead when used)
    if (MODE == 2) {
        // H == 128
        const float4* sW4 = (const float4*)(dsm + WOFF);
        const int ct = tid & 31, rt = tid >> 5;
        float2 a0[16], a1[16];
#pragma unroll
        for (int r = 0; r < 16; r++) { a0[r] = f2(0.f); a1[r] = f2(0.f); }
#pragma unroll 4
        for (int k = 0; k < H; k++) {
            float4 wv = sW4[k * (H / 4) + ct];
            float2 w01 = make_float2(wv.x, wv.y), w23 = make_float2(wv.z, wv.w);
            const float* lr = lsm + (size_t)rt * 16 * H + k;
#pragma unroll
            for (int r = 0; r < 16; r++) {
                float lv = lr[r * H];
                a0[r] = fma2(f2(lv), w01, a0[r]);
                a1[r] = fma2(f2(lv), w23, a1[r]);
            }
        }
#pragma unroll
        for (int r = 0; r < 16; r++) {
            int rg = (b << 10) + i0 + rt * 16 + r;
            float4 xv = *(const float4*)(x2 + (size_t)rg * H + ct * 4);
            float4 o;
            o.x = fmaxf(a0[r].x + xv.x, 0.f);
            o.y = fmaxf(a0[r].y + xv.y, 0.f);
            o.z = fmaxf(a1[r].x + xv.z, 0.f);
            o.w = fmaxf(a1[r].y + xv.w, 0.f);
            a0[r] = make_float2(o.x, o.y);
            a1[r] = make_float2(o.z, o.w);
            *(float4*)(out1 + (size_t)rg * H + ct * 4) = o;
        }
        if (WB) {
            __syncthreads();   // all lsm reads complete before overlay
#pragma unroll
            for (int r = 0; r < 16; r++) {
                int row = rt * 16 + r;
                l2[row * PH + ct * 4 + 0] = a0[r].x;
                l2[row * PH + ct * 4 + 1] = a0[r].y;
                l2[row * PH + ct * 4 + 2] = a1[r].x;
                l2[row * PH + ct * 4 + 3] = a1[r].y;
            }
        }
    } else {
        // H == 64
        const int ct = tid & 15, rt = tid >> 4;
        const int NPASS = (MODE == 1) ? 2 : 1;
#pragma unroll
        for (int pass = 0; pass < NPASS; pass++) {
            const float4* sW4 = (const float4*)(dsm + (pass ? W2OFF : WOFF));
            const float* wxp = pass ? wxb : wx;
            float* outp = pass ? out2 : out1;
            float2 a0[8], a1[8];
#pragma unroll
            for (int r = 0; r < 8; r++) { a0[r] = f2(0.f); a1[r] = f2(0.f); }
#pragma unroll 4
            for (int k = 0; k < H; k++) {
                float4 wv = sW4[k * (H / 4) + ct];
                float2 w01 = make_float2(wv.x, wv.y), w23 = make_float2(wv.z, wv.w);
                const float* lr = lsm + (size_t)rt * 8 * H + k;
#pragma unroll
                for (int r = 0; r < 8; r++) {
                    float lv = lr[r * H];
                    a0[r] = fma2(f2(lv), w01, a0[r]);
                    a1[r] = fma2(f2(lv), w23, a1[r]);
                }
            }
            float4 wxv = *(const float4*)(wxp + ct * 4);
#pragma unroll
            for (int r = 0; r < 8; r++) {
                int rg = (b << 10) + i0 + rt * 8 + r;
                float xv = xa[rg];
                float4 o;
                o.x = fmaxf(a0[r].x + xv * wxv.x, 0.f);
                o.y = fmaxf(a0[r].y + xv * wxv.y, 0.f);
                o.z = fmaxf(a1[r].x + xv * wxv.z, 0.f);
                o.w = fmaxf(a1[r].y + xv * wxv.w, 0.f);
                a0[r] = make_float2(o.x, o.y);
                a1[r] = make_float2(o.z, o.w);
                *(float4*)(outp + (size_t)rg * H + ct * 4) = o;
            }
            if (WB && pass == 0) {
                __syncthreads();
#pragma unroll
                for (int r = 0; r < 8; r++) {
                    int row = rt * 8 + r;
                    l2[row * PH + ct * 4 + 0] = a0[r].x;
                    l2[row * PH + ct * 4 + 1] = a0[r].y;
                    l2[row * PH + ct * 4 + 2] = a1[r].x;
                    l2[row * PH + ct * 4 + 3] = a1[r].y;
                }
            }
        }
    }

    // ---- emit B for next iteration: Bout[h][plane*1024 + i0 + c] ----
    if (WB) {
        __syncthreads();
        constexpr int SEGS = H * 16 / 256;   // (H*128)/(256*8)
#pragma unroll
        for (int s = 0; s < SEGS; s++) {
            int seg = s * 256 + tid;
            int h = seg >> 4;
            int c8 = (seg & 15) << 3;
            float w = sWemb[h];
            float cw1 = PB1 * w;
            float cw3 = PB3 * w * w * w;
            float v[8];
#pragma unroll
            for (int j = 0; j < 8; j++) v[j] = l2[(c8 + j) * PH + h];
            uint4 q0, q1, q2;
            q0.x = pack2h(0.5f * v[0], 0.5f * v[1]);
            q0.y = pack2h(0.5f * v[2], 0.5f * v[3]);
            q0.z = pack2h(0.5f * v[4], 0.5f * v[5]);
            q0.w = pack2h(0.5f * v[6], 0.5f * v[7]);
            q1.x = pack2h(cw1 * v[0], cw1 * v[1]);
            q1.y = pack2h(cw1 * v[2], cw1 * v[3]);
            q1.z = pack2h(cw1 * v[4], cw1 * v[5]);
            q1.w = pack2h(cw1 * v[6], cw1 * v[7]);
            q2.x = pack2h(cw3 * v[0], cw3 * v[1]);
            q2.y = pack2h(cw3 * v[2], cw3 * v[3]);
            q2.z = pack2h(cw3 * v[4], cw3 * v[5]);
            q2.w = pack2h(cw3 * v[6], cw3 * v[7]);
            __half* brow = Bout + (size_t)(b * 128 + h) * KK + i0 + c8;
            *(uint4*)(brow)        = q0;
            *(uint4*)(brow + 1024) = q1;
            *(uint4*)(brow + 2048) = q2;
        }
    }
}

// ---------------- small GEMM (x2 = [u_a|u_b] @ W_x_2) ----------------
template<int K, int NO>
__global__ void __launch_bounds__(NO * 4) k_gemm2(const float* __restrict__ A,
                                                  const float* __restrict__ A2,
                                                  const float* __restrict__ W,
                                                  const float* __restrict__ W2,
                                                  float* __restrict__ out) {
    constexpr int NT = NO * 4;
    __shared__ float sA[16][33];
    __shared__ __align__(16) float sW[32 * NO];
    const int tid = threadIdx.x, rr = tid & 15, cq = tid >> 4;
    const int r0 = blockIdx.x << 4;
    float2 acc0 = f2(0.f), acc1 = f2(0.f);
    for (int pass = 0; pass < 2; pass++) {
        const float* Ap = pass ? A2 : A;
        const float* Wp = pass ? W2 : W;
        for (int k0 = 0; k0 < K; k0 += 32) {
#pragma unroll
            for (int idx = tid; idx < 512; idx += NT) {
                int r = idx >> 5, c = idx & 31;
                sA[r][c] = Ap[(size_t)(r0 + r) * K + k0 + c];
            }
#pragma unroll
            for (int idx = tid; idx < 32 * NO; idx += NT)
                sW[idx] = Wp[(size_t)(k0 + idx / NO) * NO + (idx & (NO - 1))];
            __syncthreads();
#pragma unroll
            for (int kk = 0; kk < 32; kk++) {
                float a = sA[rr][kk];
                float4 wv = ((const float4*)sW)[kk * (NO / 4) + cq];
                acc0 = fma2(f2(a), make_float2(wv.x, wv.y), acc0);
                acc1 = fma2(f2(a), make_float2(wv.z, wv.w), acc1);
            }
            __syncthreads();
        }
    }
    float4 r;
    r.x = acc0.x; r.y = acc0.y; r.z = acc1.x; r.w = acc1.y;
    size_t orow = (size_t)(r0 + rr) * NO + (cq << 2);
    ((float4*)out)[orow >> 2] = r;
}

// ---------------- final reduction ----------------
__global__ void __launch_bounds__(256) k_q(const float* __restrict__ g,
                                           const float* __restrict__ wq,
                                           float* __restrict__ out) {
    __shared__ float red[8];
    int b = blockIdx.x, tid = threadIdx.x, lane = tid & 31, warp = tid >> 5;
    const float* gb = g + (size_t)b * NN * 128;
    float acc = 0.f;
    for (int idx = tid; idx < NN * 128; idx += 256)
        acc += gb[idx] * wq[idx & 127];
#pragma unroll
    for (int o = 16; o; o >>= 1) acc += __shfl_xor_sync(0xffffffffu, acc, o);
    if (lane == 0) red[warp] = acc;
    __syncthreads();
    if (tid == 0) {
        float s = 0.f;
#pragma unroll
        for (int w = 0; w < 8; w++) s += red[w];
        out[b] = s;
    }
}

#define GETSYM(p, T, s) do { void* _q = nullptr; cudaGetSymbolAddress(&_q, s); (p) = (T*)_q; } while (0)

extern "C" void kernel_launch(void* const* d_in, const int* in_sizes, int n_in,
                              void* d_out, int out_size) {
    (void)in_sizes; (void)n_in; (void)out_size;
    const float* xs     = (const float*)d_in[0];
    const float* ap     = (const float*)d_in[1];
    const float* ac     = (const float*)d_in[2];
    const float* edge   = (const float*)d_in[3];
    const float* avail  = (const float*)d_in[4];
    const float* ua0    = (const float*)d_in[5];
    const float* g0     = (const float*)d_in[7];
    const float* W1p    = (const float*)d_in[8];
    const float* W2p    = (const float*)d_in[9];
    const float* Wx1a   = (const float*)d_in[10];
    const float* Wemb1a = (const float*)d_in[11];
    const float* Wl1a   = (const float*)d_in[12];
    const float* Wx1b   = (const float*)d_in[13];
    const float* Wl1b   = (const float*)d_in[15];
    const float* Wx2    = (const float*)d_in[16];
    const float* Wemb2  = (const float*)d_in[17];
    const float* Wl2    = (const float*)d_in[18];
    const float* WQ     = (const float*)d_in[19];

    float *pP, *pDm, *pxa, *puaA, *puaB, *pub, *px2, *pgA, *pgB;
    __half *pA, *pB0, *pB1;
    GETSYM(pP, float, g_P);   GETSYM(pDm, float, g_Dm);
    GETSYM(pA, __half, g_A);
    GETSYM(pB0, __half, g_B0); GETSYM(pB1, __half, g_B1);
    GETSYM(pxa, float, g_xa);
    GETSYM(puaA, float, g_uaA); GETSYM(puaB, float, g_uaB);
    GETSYM(pub, float, g_ub); GETSYM(px2, float, g_x2);
    GETSYM(pgA, float, g_gA); GETSYM(pgB, float, g_gB);

    // dynamic smem: stages + l + W (+W2)
    const int sm64_0 = 2 * (128 + 64) * 128 + 128 * 64 * 4 + 64 * 64 * 4;            // 98304
    const int sm64_1 = sm64_0 + 64 * 64 * 4;                                          // 114688
    const int sm128  = 2 * (128 + 128) * 128 + 128 * 128 * 4 + 128 * 128 * 4;         // 196608
    cudaFuncSetAttribute(k_mma<64, 0, true>,   cudaFuncAttributeMaxDynamicSharedMemorySize, sm64_0);
    cudaFuncSetAttribute(k_mma<64, 1, false>,  cudaFuncAttributeMaxDynamicSharedMemorySize, sm64_1);
    cudaFuncSetAttribute(k_mma<128, 2, true>,  cudaFuncAttributeMaxDynamicSharedMemorySize, sm128);
    cudaFuncSetAttribute(k_mma<128, 2, false>, cudaFuncAttributeMaxDynamicSharedMemorySize, sm128);

    k_presence<<<BB * NC, 256>>>(edge, avail, W1p, W2p, pP, pDm);
    k_buildA<<<dim3(32, 32, BB), 256>>>(pP, pDm, pA, xs, ap, ac, pxa);

    // T1: 5 iterations (H = 64); B double-buffered, emitted by previous epilogue
    k_buildB<64><<<dim3(32, 2, BB), 256>>>(ua0, Wemb1a, pB0);
    __half* bcur = pB0;
    __half* bnxt = pB1;
    const float* uin = ua0;
    for (int it = 0; it < 5; it++) {
        float* uout = (it & 1) ? puaB : puaA;
        if (it < 4)
            k_mma<64, 0, true><<<dim3(8, BB), 256, sm64_0>>>(
                pA, bcur, Wl1a, nullptr, pxa, Wx1a, nullptr, nullptr, uout, nullptr,
                Wemb1a, bnxt);
        else
            k_mma<64, 1, false><<<dim3(8, BB), 256, sm64_1>>>(
                pA, bcur, Wl1a, Wl1b, pxa, Wx1a, Wx1b, nullptr, uout, pub,
                nullptr, nullptr);
        __half* t = bcur; bcur = bnxt; bnxt = t;
        uin = uout;
    }

    // x2 = [u_a | u_b] @ W_x_2
    k_gemm2<64, 128><<<1024, 512>>>(uin, pub, Wx2, Wx2 + 64 * 128, px2);

    // T2: 5 iterations (H = 128)
    k_buildB<128><<<dim3(32, 4, BB), 256>>>(g0, Wemb2, pB0);
    bcur = pB0; bnxt = pB1;
    const float* gin = g0;
    for (int it = 0; it < 5; it++) {
        float* gout = (it & 1) ? pgB : pgA;
        if (it < 4)
            k_mma<128, 2, true><<<dim3(8, BB), 256, sm128>>>(
                pA, bcur, Wl2, nullptr, nullptr, nullptr, nullptr, px2, gout, nullptr,
                Wemb2, bnxt);
        else
            k_mma<128, 2, false><<<dim3(8, BB), 256, sm128>>>(
                pA, bcur, Wl2, nullptr, nullptr, nullptr, nullptr, px2, gout, nullptr,
                nullptr, nullptr);
        __half* t = bcur; bcur = bnxt; bnxt = t;
        gin = gout;
    }

    k_q<<<BB, 256>>>(gin, WQ, (float*)d_out);
}

// round 10
// speedup vs baseline: 4.4210x; 1.0369x over previous
#include <cuda_runtime.h>
#include <cuda_fp16.h>
#include <cstdint>

#define BB 16
#define NC 1023
#define NN 1024
#define BN (BB*NN)
#define KK 3072
#define KSTEPS (KK/64)

// degree-3 economized sigmoid poly on [-1,1]: sigma(x) ~= 0.5 + B1 x + B3 x^3 (max err ~1.2e-4)
#define PB1 0.24944117f
#define PB3 (-0.01850583f)

// ---------------- static device scratch ----------------
__device__ float g_P [BB*NC*NN];
__device__ float g_Dm[BB*NC*NN];
__device__ __half g_A[(size_t)BB*NN*KK];      // [b][i][kp*1024+c], planes p, p*d, p*d^3
__device__ __half g_B0[(size_t)BB*128*KK];    // B ping
__device__ __half g_B1[(size_t)BB*128*KK];    // B pong
__device__ float g_xa[BN];
__device__ float g_uaA[BN*64];
__device__ float g_uaB[BN*64];
__device__ float g_ub [BN*64];
__device__ float g_x2 [BN*128];
__device__ float g_gA [BN*128];
__device__ float g_gB [BN*128];

// ---------------- packed f32x2 helpers ----------------
__device__ __forceinline__ float2 f2(float x) { return make_float2(x, x); }
__device__ __forceinline__ float2 fma2(float2 a, float2 b, float2 c) {
    float2 r;
    asm("fma.rn.f32x2 %0, %1, %2, %3;"
        : "=l"(*(unsigned long long*)&r)
        : "l"(*(unsigned long long*)&a), "l"(*(unsigned long long*)&b),
          "l"(*(unsigned long long*)&c));
    return r;
}
__device__ __forceinline__ float2 mul2(float2 a, float2 b) {
    float2 r;
    asm("mul.rn.f32x2 %0, %1, %2;"
        : "=l"(*(unsigned long long*)&r)
        : "l"(*(unsigned long long*)&a), "l"(*(unsigned long long*)&b));
    return r;
}

__device__ __forceinline__ uint32_t smem_u32(const void* p) {
    uint32_t a;
    asm("{ .reg .u64 t; cvta.to.shared.u64 t, %1; cvt.u32.u64 %0, t; }" : "=r"(a) : "l"(p));
    return a;
}
__device__ __forceinline__ void ldgsts16(uint32_t s, const void* g) {
    asm volatile("cp.async.cg.shared.global [%0], [%1], 16;" :: "r"(s), "l"(g));
}
__device__ __forceinline__ void ldsm_x4(uint32_t& r0, uint32_t& r1, uint32_t& r2,
                                        uint32_t& r3, uint32_t addr) {
    asm volatile("ldmatrix.sync.aligned.m8n8.x4.shared.b16 {%0,%1,%2,%3}, [%4];"
        : "=r"(r0), "=r"(r1), "=r"(r2), "=r"(r3) : "r"(addr));
}
__device__ __forceinline__ void mma16816(float* c, uint32_t a0, uint32_t a1,
                                         uint32_t a2, uint32_t a3,
                                         uint32_t b0, uint32_t b1) {
    asm volatile("mma.sync.aligned.m16n8k16.row.col.f32.f16.f16.f32 "
        "{%0,%1,%2,%3}, {%4,%5,%6,%7}, {%8,%9}, {%0,%1,%2,%3};"
        : "+f"(c[0]), "+f"(c[1]), "+f"(c[2]), "+f"(c[3])
        : "r"(a0), "r"(a1), "r"(a2), "r"(a3), "r"(b0), "r"(b1));
}
__device__ __forceinline__ uint32_t pack2h(float a, float b) {
    __half2 h = __floats2half2_rn(a, b);
    return *(uint32_t*)&h;
}

// ---------------- presence MLP + masked softmax ----------------
__global__ void __launch_bounds__(256) k_presence(const float* __restrict__ edge,
                                                  const float* __restrict__ avail,
                                                  const float* __restrict__ W1,
                                                  const float* __restrict__ W2,
                                                  float* __restrict__ P,
                                                  float* __restrict__ Dm) {
    __shared__ float sW1[192];
    __shared__ float sW2[64];
    __shared__ float redA[8], redB[8];
    int bc = blockIdx.x;
    int b = bc / NC, c = bc - b * NC;
    int tid = threadIdx.x, lane = tid & 31, warp = tid >> 5;
    if (tid < 192) sW1[tid] = W1[tid];
    if (tid < 64)  sW2[tid] = W2[tid];
    __syncthreads();

    size_t ebase = (size_t)bc * NN * 3;
    size_t pbase = (size_t)bc * NN;
    float lg[4];
#pragma unroll
    for (int j = 0; j < 2; j++) {
        int n0 = tid + j * 512;
        int n1 = n0 + 256;
        float e00 = edge[ebase + (size_t)n0 * 3];
        float e01 = edge[ebase + (size_t)n0 * 3 + 1];
        float e02 = edge[ebase + (size_t)n0 * 3 + 2];
        float e10 = edge[ebase + (size_t)n1 * 3];
        float e11 = edge[ebase + (size_t)n1 * 3 + 1];
        float e12 = edge[ebase + (size_t)n1 * 3 + 2];
        float2 E0 = make_float2(e00, e10);
        float2 E1 = make_float2(e01, e11);
        float2 E2 = make_float2(e02, e12);
        float2 acc = f2(0.f);
#pragma unroll
        for (int h = 0; h < 64; h++) {
            float2 t = mul2(E0, f2(sW1[h]));
            t = fma2(E1, f2(sW1[64 + h]), t);
            t = fma2(E2, f2(sW1[128 + h]), t);
            t.x = fmaxf(t.x, 0.f); t.y = fmaxf(t.y, 0.f);
            acc = fma2(t, f2(sW2[h]), acc);
        }
        float h2a = fmaxf(acc.x, 0.f);
        float h2b = fmaxf(acc.y, 0.f);
        float m0 = (n0 == c ? 0.f : 1.f) * avail[(b << 10) + n0];
        float m1 = (n1 == c ? 0.f : 1.f) * avail[(b << 10) + n1];
        lg[2 * j]     = h2a * m0 - (1.f - m0) * 1e10f;
        lg[2 * j + 1] = h2b * m1 - (1.f - m1) * 1e10f;
        Dm[pbase + n0] = e00;
        Dm[pbase + n1] = e10;
    }
    float m = fmaxf(fmaxf(lg[0], lg[1]), fmaxf(lg[2], lg[3]));
#pragma unroll
    for (int o = 16; o; o >>= 1) m = fmaxf(m, __shfl_xor_sync(0xffffffffu, m, o));
    if (lane == 0) redA[warp] = m;
    __syncthreads();
    m = redA[0];
#pragma unroll
    for (int w = 1; w < 8; w++) m = fmaxf(m, redA[w]);
    float e0 = __expf(lg[0] - m), e1 = __expf(lg[1] - m);
    float e2 = __expf(lg[2] - m), e3 = __expf(lg[3] - m);
    float s = (e0 + e1) + (e2 + e3);
#pragma unroll
    for (int o = 16; o; o >>= 1) s += __shfl_xor_sync(0xffffffffu, s, o);
    if (lane == 0) redB[warp] = s;
    __syncthreads();
    s = redB[0];
#pragma unroll
    for (int w = 1; w < 8; w++) s += redB[w];
    float inv = 1.0f / s;
    P[pbase + tid]       = e0 * inv;
    P[pbase + tid + 256] = e1 * inv;
    P[pbase + tid + 512] = e2 * inv;
    P[pbase + tid + 768] = e3 * inv;
}

// ---------------- build A: transpose + powers {1, d, d^3}, fp32 -> fp16; also x_a ----------------
__global__ void __launch_bounds__(256) k_buildA(const float* __restrict__ P,
                                                const float* __restrict__ D,
                                                __half* __restrict__ A,
                                                const float* __restrict__ xs,
                                                const float* __restrict__ ap,
                                                const float* __restrict__ ac,
                                                float* __restrict__ xa) {
    __shared__ float sP[32][33], sD[32][33];
    int b = blockIdx.z, ct = blockIdx.y, nt = blockIdx.x, tid = threadIdx.x;
#pragma unroll
    for (int k = 0; k < 4; k++) {
        int idx = tid + (k << 8);
        int r = idx >> 5, j = idx & 31;
        int c = (ct << 5) + r, n = (nt << 5) + j;
        float pv = 0.f, dv = 0.f;
        if (c < NC) {
            size_t g = ((size_t)(b * NC + c) << 10) + n;
            pv = P[g]; dv = D[g];
        }
        sP[r][j] = pv; sD[r][j] = dv;
    }
    __syncthreads();
#pragma unroll
    for (int k = 0; k < 4; k++) {
        int idx = tid + (k << 8);
        int rn = idx >> 5, jc = idx & 31;
        int n = (nt << 5) + rn, c = (ct << 5) + jc;
        float p = sP[jc][rn], d = sD[jc][rn];
        __half* row = A + ((size_t)((b << 10) + n)) * KK + c;
        row[0]    = __float2half(p);
        row[1024] = __float2half(p * d);
        row[2048] = __float2half(p * d * d * d);
    }
    if (ct == 0 && tid < 32) {
        int n = (nt << 5) + tid;
        float best = -3.4e38f;
#pragma unroll
        for (int r = 0; r < 8; r++) {
            int o = (((b << 3) + r) << 10) + n;
            best = fmaxf(best, xs[o] * (ap[o] + ac[o]));
        }
        xa[(b << 10) + n] = best;
    }
}

// ---------------- build B (loop-entry only) ----------------
template<int H>
__global__ void __launch_bounds__(256) k_buildB(const float* __restrict__ u,
                                                const float* __restrict__ W,
                                                __half* __restrict__ Bm) {
    __shared__ float sU[32][33];
    int b = blockIdx.z, ht = blockIdx.y, ct = blockIdx.x, tid = threadIdx.x;
#pragma unroll
    for (int k = 0; k < 4; k++) {
        int idx = tid + (k << 8);
        int r = idx >> 5, j = idx & 31;
        sU[r][j] = u[((size_t)((b << 10) + (ct << 5) + r)) * H + (ht << 5) + j];
    }
    __syncthreads();
#pragma unroll
    for (int k = 0; k < 4; k++) {
        int idx = tid + (k << 8);
        int rh = idx >> 5, jc = idx & 31;
        int h = (ht << 5) + rh, c = (ct << 5) + jc;
        float uu = sU[jc][rh];
        float w = W[h];
        __half* row = Bm + ((size_t)(b * 128 + h)) * KK + c;
        row[0]    = __float2half(0.5f * uu);
        row[1024] = __float2half(PB1 * w * uu);
        row[2048] = __float2half(PB3 * w * w * w * uu);
    }
}

// ---------------- fused mma GEMM (M-tile 64) + fp32 epilogue (+ B emit) ----------------
// mainloop: l[64,H] = A[64,KK] . B[H,KK]^T  (fp16 mma, fp32 accum)
// MODE 0: out1 = relu(l@W + xa*wx); MODE 1: + out2 = relu(l@W2 + xa*wxb); MODE 2: out1 = relu(l@W + x2)
template<int H, int MODE, bool WB>
__global__ void __launch_bounds__(256, 2) k_mma(const __half* __restrict__ A,
                                                const __half* __restrict__ Bm,
                                                const float* __restrict__ Wg,
                                                const float* __restrict__ Wg2,
                                                const float* __restrict__ xa,
                                                const float* __restrict__ wx,
                                                const float* __restrict__ wxb,
                                                const float* __restrict__ x2,
                                                float* __restrict__ out1,
                                                float* __restrict__ out2,
                                                const float* __restrict__ Wemb,
                                                __half* __restrict__ Bout) {
    constexpr int MT = 64;
    constexpr int STAGE = (MT + H) * 128;        // bytes per cp.async stage
    constexpr int NSTAGE = (H == 64) ? 4 : 3;
    constexpr int NG = (MT + H) / 32;            // 16B granules per thread per stage
    constexpr int NTILE = H / 4;                 // n-cols per warp
    constexpr int NT8 = NTILE / 8;               // 2 (H=64) or 4 (H=128)
    constexpr int LOFF = NSTAGE * STAGE;
    constexpr int PH = H + 1;
    extern __shared__ char dsm[];
    __shared__ float sWemb[128];
    const int tid = threadIdx.x;
    const int wid = tid >> 5, lane = tid & 31;
    const int wm = wid & 1, wn = wid >> 1;       // 2 (m) x 4 (n) warps
    const int b = blockIdx.y, i0 = blockIdx.x << 6;

    const uint32_t sbase = smem_u32(dsm);
    const __half* Ab = A + ((size_t)(b * NN) + i0) * KK;
    const __half* Bb = Bm + (size_t)b * 128 * KK;
    if (WB && tid < H) sWemb[tid] = Wemb[tid];

    const __half* lsrc[NG]; uint32_t ldst[NG];
#pragma unroll
    for (int i = 0; i < NG; i++) {
        int idx = tid + (i << 8);
        int row = idx >> 3, g = idx & 7;
        if (row < MT) {
            lsrc[i] = Ab + (size_t)row * KK + (g << 3);
            ldst[i] = sbase + (((row << 3) + (g ^ (row & 7))) << 4);
        } else {
            int h = row - MT;
            lsrc[i] = Bb + (size_t)h * KK + (g << 3);
            ldst[i] = sbase + MT * 128 + (((h << 3) + (g ^ (h & 7))) << 4);
        }
    }

    float acc[2][NT8][4];
#pragma unroll
    for (int ms = 0; ms < 2; ms++)
#pragma unroll
        for (int j = 0; j < NT8; j++)
#pragma unroll
            for (int q = 0; q < 4; q++) acc[ms][j][q] = 0.f;

    // prologue: issue NSTAGE-1 stages
#pragma unroll
    for (int s = 0; s < NSTAGE - 1; s++) {
#pragma unroll
        for (int i = 0; i < NG; i++)
            ldgsts16(ldst[i] + s * STAGE, lsrc[i] + (s << 6));
        asm volatile("cp.async.commit_group;" ::: "memory");
    }

#pragma unroll 1
    for (int ks = 0; ks < KSTEPS; ks++) {
        int kpre = ks + NSTAGE - 1;
        if (kpre < KSTEPS) {
            int s2 = kpre % NSTAGE;
#pragma unroll
            for (int i = 0; i < NG; i++)
                ldgsts16(ldst[i] + s2 * STAGE, lsrc[i] + (kpre << 6));
        }
        asm volatile("cp.async.commit_group;" ::: "memory");
        asm volatile("cp.async.wait_group %0;" :: "n"(NSTAGE - 2) : "memory");
        __syncthreads();

        const uint32_t sA = sbase + (ks % NSTAGE) * STAGE;
        const uint32_t sB = sA + MT * 128;
#pragma unroll
        for (int kk = 0; kk < 4; kk++) {
            uint32_t a[2][4];
#pragma unroll
            for (int ms = 0; ms < 2; ms++) {
                int row = wm * 32 + ms * 16 + (lane & 15);
                int g = kk * 2 + (lane >> 4);
                uint32_t addr = sA + (((row << 3) + (g ^ (row & 7))) << 4);
                ldsm_x4(a[ms][0], a[ms][1], a[ms][2], a[ms][3], addr);
            }
#pragma unroll
            for (int nt = 0; nt < NT8 / 2; nt++) {
                uint32_t br[4];
                int h = wn * NTILE + nt * 16 + (lane & 15);
                int g = kk * 2 + (lane >> 4);
                uint32_t addr = sB + (((h << 3) + (g ^ (h & 7))) << 4);
                ldsm_x4(br[0], br[1], br[2], br[3], addr);
#pragma unroll
                for (int ms = 0; ms < 2; ms++) {
                    mma16816(acc[ms][2 * nt],     a[ms][0], a[ms][1], a[ms][2], a[ms][3], br[0], br[2]);
                    mma16816(acc[ms][2 * nt + 1], a[ms][0], a[ms][1], a[ms][2], a[ms][3], br[1], br[3]);
                }
            }
        }
        __syncthreads();
    }

    // ---- stage l to smem (fp32, [64][H]) ----
    float* lsm = (float*)(dsm + LOFF);
#pragma unroll
    for (int ms = 0; ms < 2; ms++) {
        int r0 = wm * 32 + ms * 16 + (lane >> 2);
        int cb = wn * NTILE + (lane & 3) * 2;
#pragma unroll
        for (int j = 0; j < NT8; j++) {
            *(float2*)(lsm + (size_t)r0 * H + cb + j * 8)       = make_float2(acc[ms][j][0], acc[ms][j][1]);
            *(float2*)(lsm + (size_t)(r0 + 8) * H + cb + j * 8) = make_float2(acc[ms][j][2], acc[ms][j][3]);
        }
    }
    __syncthreads();

    // ---- fp32 epilogue GEMM: out = relu(l @ W + extra); W read via L1/L2 ----
    float* l2 = (float*)(dsm + LOFF);   // transposed-u overlay
    if (MODE == 2) {
        const int ct = tid & 31, rt = tid >> 5;   // 8 row-groups x 8 rows
        float2 a0[8], a1[8];
#pragma unroll
        for (int r = 0; r < 8; r++) { a0[r] = f2(0.f); a1[r] = f2(0.f); }
#pragma unroll 4
        for (int k = 0; k < H; k++) {
            float4 wv = __ldg((const float4*)Wg + k * (H / 4) + ct);
            float2 w01 = make_float2(wv.x, wv.y), w23 = make_float2(wv.z, wv.w);
            const float* lr = lsm + (size_t)rt * 8 * H + k;
#pragma unroll
            for (int r = 0; r < 8; r++) {
                float lv = lr[r * H];
                a0[r] = fma2(f2(lv), w01, a0[r]);
                a1[r] = fma2(f2(lv), w23, a1[r]);
            }
        }
#pragma unroll
        for (int r = 0; r < 8; r++) {
            int row = rt * 8 + r;
            int rg = (b << 10) + i0 + row;
            float4 xv = *(const float4*)(x2 + (size_t)rg * H + ct * 4);
            float4 o;
            o.x = fmaxf(a0[r].x + xv.x, 0.f);
            o.y = fmaxf(a0[r].y + xv.y, 0.f);
            o.z = fmaxf(a1[r].x + xv.z, 0.f);
            o.w = fmaxf(a1[r].y + xv.w, 0.f);
            a0[r] = make_float2(o.x, o.y);
            a1[r] = make_float2(o.z, o.w);
            *(float4*)(out1 + (size_t)rg * H + ct * 4) = o;
        }
        if (WB) {
            __syncthreads();
#pragma unroll
            for (int r = 0; r < 8; r++) {
                int row = rt * 8 + r;
                l2[row * PH + ct * 4 + 0] = a0[r].x;
                l2[row * PH + ct * 4 + 1] = a0[r].y;
                l2[row * PH + ct * 4 + 2] = a1[r].x;
                l2[row * PH + ct * 4 + 3] = a1[r].y;
            }
        }
    } else {
        const int ct = tid & 15, rt = tid >> 4;   // 16 row-groups x 4 rows
        const int NPASS = (MODE == 1) ? 2 : 1;
#pragma unroll
        for (int pass = 0; pass < NPASS; pass++) {
            const float* Wp = pass ? Wg2 : Wg;
            const float* wxp = pass ? wxb : wx;
            float* outp = pass ? out2 : out1;
            float2 a0[4], a1[4];
#pragma unroll
            for (int r = 0; r < 4; r++) { a0[r] = f2(0.f); a1[r] = f2(0.f); }
#pragma unroll 4
            for (int k = 0; k < H; k++) {
                float4 wv = __ldg((const float4*)Wp + k * (H / 4) + ct);
                float2 w01 = make_float2(wv.x, wv.y), w23 = make_float2(wv.z, wv.w);
                const float* lr = lsm + (size_t)rt * 4 * H + k;
#pragma unroll
                for (int r = 0; r < 4; r++) {
                    float lv = lr[r * H];
                    a0[r] = fma2(f2(lv), w01, a0[r]);
                    a1[r] = fma2(f2(lv), w23, a1[r]);
                }
            }
            float4 wxv = *(const float4*)(wxp + ct * 4);
#pragma unroll
            for (int r = 0; r < 4; r++) {
                int row = rt * 4 + r;
                int rg = (b << 10) + i0 + row;
                float xv = xa[rg];
                float4 o;
                o.x = fmaxf(a0[r].x + xv * wxv.x, 0.f);
                o.y = fmaxf(a0[r].y + xv * wxv.y, 0.f);
                o.z = fmaxf(a1[r].x + xv * wxv.z, 0.f);
                o.w = fmaxf(a1[r].y + xv * wxv.w, 0.f);
                a0[r] = make_float2(o.x, o.y);
                a1[r] = make_float2(o.z, o.w);
                *(float4*)(outp + (size_t)rg * H + ct * 4) = o;
            }
            if (WB && pass == 0) {
                __syncthreads();
#pragma unroll
                for (int r = 0; r < 4; r++) {
                    int row = rt * 4 + r;
                    l2[row * PH + ct * 4 + 0] = a0[r].x;
                    l2[row * PH + ct * 4 + 1] = a0[r].y;
                    l2[row * PH + ct * 4 + 2] = a1[r].x;
                    l2[row * PH + ct * 4 + 3] = a1[r].y;
                }
            }
        }
    }

    // ---- emit B for next iteration: Bout[h][plane*1024 + i0 + c], c in [0,64) ----
    if (WB) {
        __syncthreads();
        constexpr int SEGS = H / 32;   // (H*64)/(256*8)
#pragma unroll
        for (int s = 0; s < SEGS; s++) {
            int seg = s * 256 + tid;
            int h = seg >> 3;
            int c8 = (seg & 7) << 3;
            float w = sWemb[h];
            float cw1 = PB1 * w;
            float cw3 = PB3 * w * w * w;
            float v[8];
#pragma unroll
            for (int j = 0; j < 8; j++) v[j] = l2[(c8 + j) * PH + h];
            uint4 q0, q1, q2;
            q0.x = pack2h(0.5f * v[0], 0.5f * v[1]);
            q0.y = pack2h(0.5f * v[2], 0.5f * v[3]);
            q0.z = pack2h(0.5f * v[4], 0.5f * v[5]);
            q0.w = pack2h(0.5f * v[6], 0.5f * v[7]);
            q1.x = pack2h(cw1 * v[0], cw1 * v[1]);
            q1.y = pack2h(cw1 * v[2], cw1 * v[3]);
            q1.z = pack2h(cw1 * v[4], cw1 * v[5]);
            q1.w = pack2h(cw1 * v[6], cw1 * v[7]);
            q2.x = pack2h(cw3 * v[0], cw3 * v[1]);
            q2.y = pack2h(cw3 * v[2], cw3 * v[3]);
            q2.z = pack2h(cw3 * v[4], cw3 * v[5]);
            q2.w = pack2h(cw3 * v[6], cw3 * v[7]);
            __half* brow = Bout + (size_t)(b * 128 + h) * KK + i0 + c8;
            *(uint4*)(brow)        = q0;
            *(uint4*)(brow + 1024) = q1;
            *(uint4*)(brow + 2048) = q2;
        }
    }
}

// ---------------- small GEMM (x2 = [u_a|u_b] @ W_x_2) ----------------
template<int K, int NO>
__global__ void __launch_bounds__(NO * 4) k_gemm2(const float* __restrict__ A,
                                                  const float* __restrict__ A2,
                                                  const float* __restrict__ W,
                                                  const float* __restrict__ W2,
                                                  float* __restrict__ out) {
    constexpr int NT = NO * 4;
    __shared__ float sA[16][33];
    __shared__ __align__(16) float sW[32 * NO];
    const int tid = threadIdx.x, rr = tid & 15, cq = tid >> 4;
    const int r0 = blockIdx.x << 4;
    float2 acc0 = f2(0.f), acc1 = f2(0.f);
    for (int pass = 0; pass < 2; pass++) {
        const float* Ap = pass ? A2 : A;
        const float* Wp = pass ? W2 : W;
        for (int k0 = 0; k0 < K; k0 += 32) {
#pragma unroll
            for (int idx = tid; idx < 512; idx += NT) {
                int r = idx >> 5, c = idx & 31;
                sA[r][c] = Ap[(size_t)(r0 + r) * K + k0 + c];
            }
#pragma unroll
            for (int idx = tid; idx < 32 * NO; idx += NT)
                sW[idx] = Wp[(size_t)(k0 + idx / NO) * NO + (idx & (NO - 1))];
            __syncthreads();
#pragma unroll
            for (int kk = 0; kk < 32; kk++) {
                float a = sA[rr][kk];
                float4 wv = ((const float4*)sW)[kk * (NO / 4) + cq];
                acc0 = fma2(f2(a), make_float2(wv.x, wv.y), acc0);
                acc1 = fma2(f2(a), make_float2(wv.z, wv.w), acc1);
            }
            __syncthreads();
        }
    }
    float4 r;
    r.x = acc0.x; r.y = acc0.y; r.z = acc1.x; r.w = acc1.y;
    size_t orow = (size_t)(r0 + rr) * NO + (cq << 2);
    ((float4*)out)[orow >> 2] = r;
}

// ---------------- final reduction ----------------
__global__ void __launch_bounds__(256) k_q(const float* __restrict__ g,
                                           const float* __restrict__ wq,
                                           float* __restrict__ out) {
    __shared__ float red[8];
    int b = blockIdx.x, tid = threadIdx.x, lane = tid & 31, warp = tid >> 5;
    const float* gb = g + (size_t)b * NN * 128;
    float acc = 0.f;
    for (int idx = tid; idx < NN * 128; idx += 256)
        acc += gb[idx] * wq[idx & 127];
#pragma unroll
    for (int o = 16; o; o >>= 1) acc += __shfl_xor_sync(0xffffffffu, acc, o);
    if (lane == 0) red[warp] = acc;
    __syncthreads();
    if (tid == 0) {
        float s = 0.f;
#pragma unroll
        for (int w = 0; w < 8; w++) s += red[w];
        out[b] = s;
    }
}

#define GETSYM(p, T, s) do { void* _q = nullptr; cudaGetSymbolAddress(&_q, s); (p) = (T*)_q; } while (0)

extern "C" void kernel_launch(void* const* d_in, const int* in_sizes, int n_in,
                              void* d_out, int out_size) {
    (void)in_sizes; (void)n_in; (void)out_size;
    const float* xs     = (const float*)d_in[0];
    const float* ap     = (const float*)d_in[1];
    const float* ac     = (const float*)d_in[2];
    const float* edge   = (const float*)d_in[3];
    const float* avail  = (const float*)d_in[4];
    const float* ua0    = (const float*)d_in[5];
    const float* g0     = (const float*)d_in[7];
    const float* W1p    = (const float*)d_in[8];
    const float* W2p    = (const float*)d_in[9];
    const float* Wx1a   = (const float*)d_in[10];
    const float* Wemb1a = (const float*)d_in[11];
    const float* Wl1a   = (const float*)d_in[12];
    const float* Wx1b   = (const float*)d_in[13];
    const float* Wl1b   = (const float*)d_in[15];
    const float* Wx2    = (const float*)d_in[16];
    const float* Wemb2  = (const float*)d_in[17];
    const float* Wl2    = (const float*)d_in[18];
    const float* WQ     = (const float*)d_in[19];

    float *pP, *pDm, *pxa, *puaA, *puaB, *pub, *px2, *pgA, *pgB;
    __half *pA, *pB0, *pB1;
    GETSYM(pP, float, g_P);   GETSYM(pDm, float, g_Dm);
    GETSYM(pA, __half, g_A);
    GETSYM(pB0, __half, g_B0); GETSYM(pB1, __half, g_B1);
    GETSYM(pxa, float, g_xa);
    GETSYM(puaA, float, g_uaA); GETSYM(puaB, float, g_uaB);
    GETSYM(pub, float, g_ub); GETSYM(px2, float, g_x2);
    GETSYM(pgA, float, g_gA); GETSYM(pgB, float, g_gB);

    // dynamic smem: NSTAGE stages + l-region (64 x (H+1) fp32)
    const int sm64  = 4 * (64 + 64) * 128 + 64 * 65 * 4;    // 82176
    const int sm128 = 3 * (64 + 128) * 128 + 64 * 129 * 4;  // 106752
    cudaFuncSetAttribute(k_mma<64, 0, true>,   cudaFuncAttributeMaxDynamicSharedMemorySize, sm64);
    cudaFuncSetAttribute(k_mma<64, 1, false>,  cudaFuncAttributeMaxDynamicSharedMemorySize, sm64);
    cudaFuncSetAttribute(k_mma<128, 2, true>,  cudaFuncAttributeMaxDynamicSharedMemorySize, sm128);
    cudaFuncSetAttribute(k_mma<128, 2, false>, cudaFuncAttributeMaxDynamicSharedMemorySize, sm128);

    k_presence<<<BB * NC, 256>>>(edge, avail, W1p, W2p, pP, pDm);
    k_buildA<<<dim3(32, 32, BB), 256>>>(pP, pDm, pA, xs, ap, ac, pxa);

    // T1: 5 iterations (H = 64); B double-buffered, emitted by previous epilogue
    k_buildB<64><<<dim3(32, 2, BB), 256>>>(ua0, Wemb1a, pB0);
    __half* bcur = pB0;
    __half* bnxt = pB1;
    const float* uin = ua0;
    for (int it = 0; it < 5; it++) {
        float* uout = (it & 1) ? puaB : puaA;
        if (it < 4)
            k_mma<64, 0, true><<<dim3(16, BB), 256, sm64>>>(
                pA, bcur, Wl1a, nullptr, pxa, Wx1a, nullptr, nullptr, uout, nullptr,
                Wemb1a, bnxt);
        else
            k_mma<64, 1, false><<<dim3(16, BB), 256, sm64>>>(
                pA, bcur, Wl1a, Wl1b, pxa, Wx1a, Wx1b, nullptr, uout, pub,
                nullptr, nullptr);
        __half* t = bcur; bcur = bnxt; bnxt = t;
        uin = uout;
    }

    // x2 = [u_a | u_b] @ W_x_2
    k_gemm2<64, 128><<<1024, 512>>>(uin, pub, Wx2, Wx2 + 64 * 128, px2);

    // T2: 5 iterations (H = 128)
    k_buildB<128><<<dim3(32, 4, BB), 256>>>(g0, Wemb2, pB0);
    bcur = pB0; bnxt = pB1;
    const float* gin = g0;
    for (int it = 0; it < 5; it++) {
        float* gout = (it & 1) ? pgB : pgA;
        if (it < 4)
            k_mma<128, 2, true><<<dim3(16, BB), 256, sm128>>>(
                pA, bcur, Wl2, nullptr, nullptr, nullptr, nullptr, px2, gout, nullptr,
                Wemb2, bnxt);
        else
            k_mma<128, 2, false><<<dim3(16, BB), 256, sm128>>>(
                pA, bcur, Wl2, nullptr, nullptr, nullptr, nullptr, px2, gout, nullptr,
                nullptr, nullptr);
        __half* t = bcur; bcur = bnxt; bnxt = t;
        gin = gout;
    }

    k_q<<<BB, 256>>>(gin, WQ, (float*)d_out);
}

// round 13
// speedup vs baseline: 4.5909x; 1.0384x over previous
#include <cuda_runtime.h>
#include <cuda_fp16.h>
#include <cstdint>

#define BB 16
#define NC 1023
#define NN 1024
#define BN (BB*NN)
#define KK 3072
#define KSTEPS (KK/64)

// degree-3 economized sigmoid poly on [-1,1]: sigma(x) ~= 0.5 + B1 x + B3 x^3 (max err ~1.2e-4)
#define PB1 0.24944117f
#define PB3 (-0.01850583f)

// ---------------- static device scratch ----------------
__device__ float g_P [BB*NC*NN];
__device__ float g_Dm[BB*NC*NN];
__device__ __half g_A[(size_t)BB*NN*KK];      // [b][i][kp*1024+c], planes p, p*d, p*d^3
__device__ __half g_B0[(size_t)BB*128*KK];    // B ping
__device__ __half g_B1[(size_t)BB*128*KK];    // B pong
__device__ float g_xa[BN];
__device__ float g_uaA[BN*64];
__device__ float g_uaB[BN*64];
__device__ float g_ub [BN*64];
__device__ float g_x2 [BN*128];
__device__ float g_gA [BN*128];
__device__ float g_gB [BN*128];

// ---------------- packed f32x2 helpers ----------------
__device__ __forceinline__ float2 f2(float x) { return make_float2(x, x); }
__device__ __forceinline__ float2 fma2(float2 a, float2 b, float2 c) {
    float2 r;
    asm("fma.rn.f32x2 %0, %1, %2, %3;"
        : "=l"(*(unsigned long long*)&r)
        : "l"(*(unsigned long long*)&a), "l"(*(unsigned long long*)&b),
          "l"(*(unsigned long long*)&c));
    return r;
}
__device__ __forceinline__ float2 mul2(float2 a, float2 b) {
    float2 r;
    asm("mul.rn.f32x2 %0, %1, %2;"
        : "=l"(*(unsigned long long*)&r)
        : "l"(*(unsigned long long*)&a), "l"(*(unsigned long long*)&b));
    return r;
}

__device__ __forceinline__ uint32_t smem_u32(const void* p) {
    uint32_t a;
    asm("{ .reg .u64 t; cvta.to.shared.u64 t, %1; cvt.u32.u64 %0, t; }" : "=r"(a) : "l"(p));
    return a;
}
__device__ __forceinline__ void ldgsts16(uint32_t s, const void* g) {
    asm volatile("cp.async.cg.shared.global [%0], [%1], 16;" :: "r"(s), "l"(g));
}
__device__ __forceinline__ void ldsm_x4(uint32_t& r0, uint32_t& r1, uint32_t& r2,
                                        uint32_t& r3, uint32_t addr) {
    asm volatile("ldmatrix.sync.aligned.m8n8.x4.shared.b16 {%0,%1,%2,%3}, [%4];"
        : "=r"(r0), "=r"(r1), "=r"(r2), "=r"(r3) : "r"(addr));
}
__device__ __forceinline__ void mma16816(float* c, uint32_t a0, uint32_t a1,
                                         uint32_t a2, uint32_t a3,
                                         uint32_t b0, uint32_t b1) {
    asm volatile("mma.sync.aligned.m16n8k16.row.col.f32.f16.f16.f32 "
        "{%0,%1,%2,%3}, {%4,%5,%6,%7}, {%8,%9}, {%0,%1,%2,%3};"
        : "+f"(c[0]), "+f"(c[1]), "+f"(c[2]), "+f"(c[3])
        : "r"(a0), "r"(a1), "r"(a2), "r"(a3), "r"(b0), "r"(b1));
}
__device__ __forceinline__ uint32_t pack2h(float a, float b) {
    __half2 h = __floats2half2_rn(a, b);
    return *(uint32_t*)&h;
}

// ---------------- presence MLP + masked softmax ----------------
__global__ void __launch_bounds__(256) k_presence(const float* __restrict__ edge,
                                                  const float* __restrict__ avail,
                                                  const float* __restrict__ W1,
                                                  const float* __restrict__ W2,
                                                  float* __restrict__ P,
                                                  float* __restrict__ Dm) {
    __shared__ float sW1[192];
    __shared__ float sW2[64];
    __shared__ float redA[8], redB[8];
    int bc = blockIdx.x;
    int b = bc / NC, c = bc - b * NC;
    int tid = threadIdx.x, lane = tid & 31, warp = tid >> 5;
    if (tid < 192) sW1[tid] = W1[tid];
    if (tid < 64)  sW2[tid] = W2[tid];
    __syncthreads();

    size_t ebase = (size_t)bc * NN * 3;
    size_t pbase = (size_t)bc * NN;
    float lg[4];
#pragma unroll
    for (int j = 0; j < 2; j++) {
        int n0 = tid + j * 512;
        int n1 = n0 + 256;
        float e00 = edge[ebase + (size_t)n0 * 3];
        float e01 = edge[ebase + (size_t)n0 * 3 + 1];
        float e02 = edge[ebase + (size_t)n0 * 3 + 2];
        float e10 = edge[ebase + (size_t)n1 * 3];
        float e11 = edge[ebase + (size_t)n1 * 3 + 1];
        float e12 = edge[ebase + (size_t)n1 * 3 + 2];
        float2 E0 = make_float2(e00, e10);
        float2 E1 = make_float2(e01, e11);
        float2 E2 = make_float2(e02, e12);
        float2 acc = f2(0.f);
#pragma unroll
        for (int h = 0; h < 64; h++) {
            float2 t = mul2(E0, f2(sW1[h]));
            t = fma2(E1, f2(sW1[64 + h]), t);
            t = fma2(E2, f2(sW1[128 + h]), t);
            t.x = fmaxf(t.x, 0.f); t.y = fmaxf(t.y, 0.f);
            acc = fma2(t, f2(sW2[h]), acc);
        }
        float h2a = fmaxf(acc.x, 0.f);
        float h2b = fmaxf(acc.y, 0.f);
        float m0 = (n0 == c ? 0.f : 1.f) * avail[(b << 10) + n0];
        float m1 = (n1 == c ? 0.f : 1.f) * avail[(b << 10) + n1];
        lg[2 * j]     = h2a * m0 - (1.f - m0) * 1e10f;
        lg[2 * j + 1] = h2b * m1 - (1.f - m1) * 1e10f;
        Dm[pbase + n0] = e00;
        Dm[pbase + n1] = e10;
    }
    float m = fmaxf(fmaxf(lg[0], lg[1]), fmaxf(lg[2], lg[3]));
#pragma unroll
    for (int o = 16; o; o >>= 1) m = fmaxf(m, __shfl_xor_sync(0xffffffffu, m, o));
    if (lane == 0) redA[warp] = m;
    __syncthreads();
    m = redA[0];
#pragma unroll
    for (int w = 1; w < 8; w++) m = fmaxf(m, redA[w]);
    float e0 = __expf(lg[0] - m), e1 = __expf(lg[1] - m);
    float e2 = __expf(lg[2] - m), e3 = __expf(lg[3] - m);
    float s = (e0 + e1) + (e2 + e3);
#pragma unroll
    for (int o = 16; o; o >>= 1) s += __shfl_xor_sync(0xffffffffu, s, o);
    if (lane == 0) redB[warp] = s;
    __syncthreads();
    s = redB[0];
#pragma unroll
    for (int w = 1; w < 8; w++) s += redB[w];
    float inv = 1.0f / s;
    P[pbase + tid]       = e0 * inv;
    P[pbase + tid + 256] = e1 * inv;
    P[pbase + tid + 512] = e2 * inv;
    P[pbase + tid + 768] = e3 * inv;
}

// ---------------- build A: transpose + powers {1, d, d^3}, fp32 -> fp16; also x_a ----------------
__global__ void __launch_bounds__(256) k_buildA(const float* __restrict__ P,
                                                const float* __restrict__ D,
                                                __half* __restrict__ A,
                                                const float* __restrict__ xs,
                                                const float* __restrict__ ap,
                                                const float* __restrict__ ac,
                                                float* __restrict__ xa) {
    __shared__ float sP[32][33], sD[32][33];
    int b = blockIdx.z, ct = blockIdx.y, nt = blockIdx.x, tid = threadIdx.x;
#pragma unroll
    for (int k = 0; k < 4; k++) {
        int idx = tid + (k << 8);
        int r = idx >> 5, j = idx & 31;
        int c = (ct << 5) + r, n = (nt << 5) + j;
        float pv = 0.f, dv = 0.f;
        if (c < NC) {
            size_t g = ((size_t)(b * NC + c) << 10) + n;
            pv = P[g]; dv = D[g];
        }
        sP[r][j] = pv; sD[r][j] = dv;
    }
    __syncthreads();
#pragma unroll
    for (int k = 0; k < 4; k++) {
        int idx = tid + (k << 8);
        int rn = idx >> 5, jc = idx & 31;
        int n = (nt << 5) + rn, c = (ct << 5) + jc;
        float p = sP[jc][rn], d = sD[jc][rn];
        __half* row = A + ((size_t)((b << 10) + n)) * KK + c;
        row[0]    = __float2half(p);
        row[1024] = __float2half(p * d);
        row[2048] = __float2half(p * d * d * d);
    }
    if (ct == 0 && tid < 32) {
        int n = (nt << 5) + tid;
        float best = -3.4e38f;
#pragma unroll
        for (int r = 0; r < 8; r++) {
            int o = (((b << 3) + r) << 10) + n;
            best = fmaxf(best, xs[o] * (ap[o] + ac[o]));
        }
        xa[(b << 10) + n] = best;
    }
}

// ---------------- build B (loop-entry only) ----------------
template<int H>
__global__ void __launch_bounds__(256) k_buildB(const float* __restrict__ u,
                                                const float* __restrict__ W,
                                                __half* __restrict__ Bm) {
    __shared__ float sU[32][33];
    int b = blockIdx.z, ht = blockIdx.y, ct = blockIdx.x, tid = threadIdx.x;
#pragma unroll
    for (int k = 0; k < 4; k++) {
        int idx = tid + (k << 8);
        int r = idx >> 5, j = idx & 31;
        sU[r][j] = u[((size_t)((b << 10) + (ct << 5) + r)) * H + (ht << 5) + j];
    }
    __syncthreads();
#pragma unroll
    for (int k = 0; k < 4; k++) {
        int idx = tid + (k << 8);
        int rh = idx >> 5, jc = idx & 31;
        int h = (ht << 5) + rh, c = (ct << 5) + jc;
        float uu = sU[jc][rh];
        float w = W[h];
        __half* row = Bm + ((size_t)(b * 128 + h)) * KK + c;
        row[0]    = __float2half(0.5f * uu);
        row[1024] = __float2half(PB1 * w * uu);
        row[2048] = __float2half(PB3 * w * w * w * uu);
    }
}

// ---------------- fused mma GEMM (M-tile 64) + fp32 epilogue (+ B emit) ----------------
// mainloop: l[64,H] = A[64,KK] . B[H,KK]^T  (fp16 mma, fp32 accum); ONE sync per K-step.
// l/epilogue regions OVERLAY the (dead) cp.async stage buffers.
// MODE 0: out1 = relu(l@W + xa*wx); MODE 1: + out2 = relu(l@W2 + xa*wxb); MODE 2: out1 = relu(l@W + x2)
template<int H, int MODE, bool WB>
__global__ void __launch_bounds__(256, 2) k_mma(const __half* __restrict__ A,
                                                const __half* __restrict__ Bm,
                                                const float* __restrict__ Wg,
                                                const float* __restrict__ Wg2,
                                                const float* __restrict__ xa,
                                                const float* __restrict__ wx,
                                                const float* __restrict__ wxb,
                                                const float* __restrict__ x2,
                                                float* __restrict__ out1,
                                                float* __restrict__ out2,
                                                const float* __restrict__ Wemb,
                                                __half* __restrict__ Bout) {
    constexpr int MT = 64;
    constexpr int STAGE = (MT + H) * 128;        // bytes per cp.async stage
    constexpr int NSTAGE = (H == 64) ? 5 : 4;
    constexpr int NG = (MT + H) / 32;            // 16B granules per thread per stage
    constexpr int NTILE = H / 4;                 // n-cols per warp
    constexpr int NT8 = NTILE / 8;               // 2 (H=64) or 4 (H=128)
    constexpr int PH = H + 1;
    extern __shared__ char dsm[];
    __shared__ float sWemb[128];
    const int tid = threadIdx.x;
    const int wid = tid >> 5, lane = tid & 31;
    const int wm = wid & 1, wn = wid >> 1;       // 2 (m) x 4 (n) warps
    const int b = blockIdx.y, i0 = blockIdx.x << 6;

    const uint32_t sbase = smem_u32(dsm);
    const __half* Ab = A + ((size_t)(b * NN) + i0) * KK;
    const __half* Bb = Bm + (size_t)b * 128 * KK;
    if (WB && tid < H) sWemb[tid] = Wemb[tid];

    const __half* lsrc[NG]; uint32_t ldst[NG];
#pragma unroll
    for (int i = 0; i < NG; i++) {
        int idx = tid + (i << 8);
        int row = idx >> 3, g = idx & 7;
        if (row < MT) {
            lsrc[i] = Ab + (size_t)row * KK + (g << 3);
            ldst[i] = sbase + (((row << 3) + (g ^ (row & 7))) << 4);
        } else {
            int h = row - MT;
            lsrc[i] = Bb + (size_t)h * KK + (g << 3);
            ldst[i] = sbase + MT * 128 + (((h << 3) + (g ^ (h & 7))) << 4);
        }
    }

    float acc[2][NT8][4];
#pragma unroll
    for (int ms = 0; ms < 2; ms++)
#pragma unroll
        for (int j = 0; j < NT8; j++)
#pragma unroll
            for (int q = 0; q < 4; q++) acc[ms][j][q] = 0.f;

    // prologue: issue NSTAGE-1 stages
#pragma unroll
    for (int s = 0; s < NSTAGE - 1; s++) {
#pragma unroll
        for (int i = 0; i < NG; i++)
            ldgsts16(ldst[i] + s * STAGE, lsrc[i] + (s << 6));
        asm volatile("cp.async.commit_group;" ::: "memory");
    }

    int sc = 0;                     // compute stage
    int sp = NSTAGE - 1;            // prefetch stage
#pragma unroll 1
    for (int ks = 0; ks < KSTEPS; ks++) {
        // group ks complete -> stage sc data resident
        asm volatile("cp.async.wait_group %0;" :: "n"(NSTAGE - 2) : "memory");
        __syncthreads();

        // prefetch step ks+NSTAGE-1 into stage sp (its readers finished before the sync)
        int kpre = ks + NSTAGE - 1;
        if (kpre < KSTEPS) {
#pragma unroll
            for (int i = 0; i < NG; i++)
                ldgsts16(ldst[i] + sp * STAGE, lsrc[i] + (kpre << 6));
        }
        asm volatile("cp.async.commit_group;" ::: "memory");   // always: keeps group count uniform
        if (++sp == NSTAGE) sp = 0;

        const uint32_t sA = sbase + sc * STAGE;
        const uint32_t sB = sA + MT * 128;
        if (++sc == NSTAGE) sc = 0;
#pragma unroll
        for (int kk = 0; kk < 4; kk++) {
            uint32_t a[2][4];
#pragma unroll
            for (int ms = 0; ms < 2; ms++) {
                int row = wm * 32 + ms * 16 + (lane & 15);
                int g = kk * 2 + (lane >> 4);
                uint32_t addr = sA + (((row << 3) + (g ^ (row & 7))) << 4);
                ldsm_x4(a[ms][0], a[ms][1], a[ms][2], a[ms][3], addr);
            }
#pragma unroll
            for (int nt = 0; nt < NT8 / 2; nt++) {
                uint32_t br[4];
                int h = wn * NTILE + nt * 16 + (lane & 15);
                int g = kk * 2 + (lane >> 4);
                uint32_t addr = sB + (((h << 3) + (g ^ (h & 7))) << 4);
                ldsm_x4(br[0], br[1], br[2], br[3], addr);
#pragma unroll
                for (int ms = 0; ms < 2; ms++) {
                    mma16816(acc[ms][2 * nt],     a[ms][0], a[ms][1], a[ms][2], a[ms][3], br[0], br[2]);
                    mma16816(acc[ms][2 * nt + 1], a[ms][0], a[ms][1], a[ms][2], a[ms][3], br[1], br[3]);
                }
            }
        }
    }
    __syncthreads();   // all stage reads done before l overlays stage memory

    // ---- stage l to smem (fp32, [64][H]) — overlays stage buffers ----
    float* lsm = (float*)dsm;
#pragma unroll
    for (int ms = 0; ms < 2; ms++) {
        int r0 = wm * 32 + ms * 16 + (lane >> 2);
        int cb = wn * NTILE + (lane & 3) * 2;
#pragma unroll
        for (int j = 0; j < NT8; j++) {
            *(float2*)(lsm + (size_t)r0 * H + cb + j * 8)       = make_float2(acc[ms][j][0], acc[ms][j][1]);
            *(float2*)(lsm + (size_t)(r0 + 8) * H + cb + j * 8) = make_float2(acc[ms][j][2], acc[ms][j][3]);
        }
    }
    __syncthreads();

    // ---- fp32 epilogue GEMM: out = relu(l @ W + extra); W read via L1/L2 ----
    float* l2 = (float*)dsm;   // transposed-u overlay (pitch PH), written after sync
    if (MODE == 2) {
        const int ct = tid & 31, rt = tid >> 5;   // 8 row-groups x 8 rows
        float2 a0[8], a1[8];
#pragma unroll
        for (int r = 0; r < 8; r++) { a0[r] = f2(0.f); a1[r] = f2(0.f); }
#pragma unroll 4
        for (int k = 0; k < H; k++) {
            float4 wv = __ldg((const float4*)Wg + k * (H / 4) + ct);
            float2 w01 = make_float2(wv.x, wv.y), w23 = make_float2(wv.z, wv.w);
            const float* lr = lsm + (size_t)rt * 8 * H + k;
#pragma unroll
            for (int r = 0; r < 8; r++) {
                float lv = lr[r * H];
                a0[r] = fma2(f2(lv), w01, a0[r]);
                a1[r] = fma2(f2(lv), w23, a1[r]);
            }
        }
#pragma unroll
        for (int r = 0; r < 8; r++) {
            int row = rt * 8 + r;
            int rg = (b << 10) + i0 + row;
            float4 xv = *(const float4*)(x2 + (size_t)rg * H + ct * 4);
            float4 o;
            o.x = fmaxf(a0[r].x + xv.x, 0.f);
            o.y = fmaxf(a0[r].y + xv.y, 0.f);
            o.z = fmaxf(a1[r].x + xv.z, 0.f);
            o.w = fmaxf(a1[r].y + xv.w, 0.f);
            a0[r] = make_float2(o.x, o.y);
            a1[r] = make_float2(o.z, o.w);
            *(float4*)(out1 + (size_t)rg * H + ct * 4) = o;
        }
        if (WB) {
            __syncthreads();
#pragma unroll
            for (int r = 0; r < 8; r++) {
                int row = rt * 8 + r;
                l2[row * PH + ct * 4 + 0] = a0[r].x;
                l2[row * PH + ct * 4 + 1] = a0[r].y;
                l2[row * PH + ct * 4 + 2] = a1[r].x;
                l2[row * PH + ct * 4 + 3] = a1[r].y;
            }
        }
    } else {
        const int ct = tid & 15, rt = tid >> 4;   // 16 row-groups x 4 rows
        const int NPASS = (MODE == 1) ? 2 : 1;
#pragma unroll
        for (int pass = 0; pass < NPASS; pass++) {
            const float* Wp = pass ? Wg2 : Wg;
            const float* wxp = pass ? wxb : wx;
            float* outp = pass ? out2 : out1;
            float2 a0[4], a1[4];
#pragma unroll
            for (int r = 0; r < 4; r++) { a0[r] = f2(0.f); a1[r] = f2(0.f); }
#pragma unroll 4
            for (int k = 0; k < H; k++) {
                float4 wv = __ldg((const float4*)Wp + k * (H / 4) + ct);
                float2 w01 = make_float2(wv.x, wv.y), w23 = make_float2(wv.z, wv.w);
                const float* lr = lsm + (size_t)rt * 4 * H + k;
#pragma unroll
                for (int r = 0; r < 4; r++) {
                    float lv = lr[r * H];
                    a0[r] = fma2(f2(lv), w01, a0[r]);
                    a1[r] = fma2(f2(lv), w23, a1[r]);
                }
            }
            float4 wxv = *(const float4*)(wxp + ct * 4);
#pragma unroll
            for (int r = 0; r < 4; r++) {
                int row = rt * 4 + r;
                int rg = (b << 10) + i0 + row;
                float xv = xa[rg];
                float4 o;
                o.x = fmaxf(a0[r].x + xv * wxv.x, 0.f);
                o.y = fmaxf(a0[r].y + xv * wxv.y, 0.f);
                o.z = fmaxf(a1[r].x + xv * wxv.z, 0.f);
                o.w = fmaxf(a1[r].y + xv * wxv.w, 0.f);
                a0[r] = make_float2(o.x, o.y);
                a1[r] = make_float2(o.z, o.w);
                *(float4*)(outp + (size_t)rg * H + ct * 4) = o;
            }
            if (WB && pass == 0) {
                __syncthreads();
#pragma unroll
                for (int r = 0; r < 4; r++) {
                    int row = rt * 4 + r;
                    l2[row * PH + ct * 4 + 0] = a0[r].x;
                    l2[row * PH + ct * 4 + 1] = a0[r].y;
                    l2[row * PH + ct * 4 + 2] = a1[r].x;
                    l2[row * PH + ct * 4 + 3] = a1[r].y;
                }
            }
        }
    }

    // ---- emit B for next iteration: Bout[h][plane*1024 + i0 + c], c in [0,64) ----
    if (WB) {
        __syncthreads();
        constexpr int SEGS = H / 32;   // (H*64)/(256*8)
#pragma unroll
        for (int s = 0; s < SEGS; s++) {
            int seg = s * 256 + tid;
            int h = seg >> 3;
            int c8 = (seg & 7) << 3;
            float w = sWemb[h];
            float cw1 = PB1 * w;
            float cw3 = PB3 * w * w * w;
            float v[8];
#pragma unroll
            for (int j = 0; j < 8; j++) v[j] = l2[(c8 + j) * PH + h];
            uint4 q0, q1, q2;
            q0.x = pack2h(0.5f * v[0], 0.5f * v[1]);
            q0.y = pack2h(0.5f * v[2], 0.5f * v[3]);
            q0.z = pack2h(0.5f * v[4], 0.5f * v[5]);
            q0.w = pack2h(0.5f * v[6], 0.5f * v[7]);
            q1.x = pack2h(cw1 * v[0], cw1 * v[1]);
            q1.y = pack2h(cw1 * v[2], cw1 * v[3]);
            q1.z = pack2h(cw1 * v[4], cw1 * v[5]);
            q1.w = pack2h(cw1 * v[6], cw1 * v[7]);
            q2.x = pack2h(cw3 * v[0], cw3 * v[1]);
            q2.y = pack2h(cw3 * v[2], cw3 * v[3]);
            q2.z = pack2h(cw3 * v[4], cw3 * v[5]);
            q2.w = pack2h(cw3 * v[6], cw3 * v[7]);
            __half* brow = Bout + (size_t)(b * 128 + h) * KK + i0 + c8;
            *(uint4*)(brow)        = q0;
            *(uint4*)(brow + 1024) = q1;
            *(uint4*)(brow + 2048) = q2;
        }
    }
}

// ---------------- small GEMM (x2 = [u_a|u_b] @ W_x_2) ----------------
template<int K, int NO>
__global__ void __launch_bounds__(NO * 4) k_gemm2(const float* __restrict__ A,
                                                  const float* __restrict__ A2,
                                                  const float* __restrict__ W,
                                                  const float* __restrict__ W2,
                                                  float* __restrict__ out) {
    constexpr int NT = NO * 4;
    __shared__ float sA[16][33];
    __shared__ __align__(16) float sW[32 * NO];
    const int tid = threadIdx.x, rr = tid & 15, cq = tid >> 4;
    const int r0 = blockIdx.x << 4;
    float2 acc0 = f2(0.f), acc1 = f2(0.f);
    for (int pass = 0; pass < 2; pass++) {
        const float* Ap = pass ? A2 : A;
        const float* Wp = pass ? W2 : W;
        for (int k0 = 0; k0 < K; k0 += 32) {
#pragma unroll
            for (int idx = tid; idx < 512; idx += NT) {
                int r = idx >> 5, c = idx & 31;
                sA[r][c] = Ap[(size_t)(r0 + r) * K + k0 + c];
            }
#pragma unroll
            for (int idx = tid; idx < 32 * NO; idx += NT)
                sW[idx] = Wp[(size_t)(k0 + idx / NO) * NO + (idx & (NO - 1))];
            __syncthreads();
#pragma unroll
            for (int kk = 0; kk < 32; kk++) {
                float a = sA[rr][kk];
                float4 wv = ((const float4*)sW)[kk * (NO / 4) + cq];
                acc0 = fma2(f2(a), make_float2(wv.x, wv.y), acc0);
                acc1 = fma2(f2(a), make_float2(wv.z, wv.w), acc1);
            }
            __syncthreads();
        }
    }
    float4 r;
    r.x = acc0.x; r.y = acc0.y; r.z = acc1.x; r.w = acc1.y;
    size_t orow = (size_t)(r0 + rr) * NO + (cq << 2);
    ((float4*)out)[orow >> 2] = r;
}

// ---------------- final reduction ----------------
__global__ void __launch_bounds__(256) k_q(const float* __restrict__ g,
                                           const float* __restrict__ wq,
                                           float* __restrict__ out) {
    __shared__ float red[8];
    int b = blockIdx.x, tid = threadIdx.x, lane = tid & 31, warp = tid >> 5;
    const float* gb = g + (size_t)b * NN * 128;
    float acc = 0.f;
    for (int idx = tid; idx < NN * 128; idx += 256)
        acc += gb[idx] * wq[idx & 127];
#pragma unroll
    for (int o = 16; o; o >>= 1) acc += __shfl_xor_sync(0xffffffffu, acc, o);
    if (lane == 0) red[warp] = acc;
    __syncthreads();
    if (tid == 0) {
        float s = 0.f;
#pragma unroll
        for (int w = 0; w < 8; w++) s += red[w];
        out[b] = s;
    }
}

#define GETSYM(p, T, s) do { void* _q = nullptr; cudaGetSymbolAddress(&_q, s); (p) = (T*)_q; } while (0)

extern "C" void kernel_launch(void* const* d_in, const int* in_sizes, int n_in,
                              void* d_out, int out_size) {
    (void)in_sizes; (void)n_in; (void)out_size;
    const float* xs     = (const float*)d_in[0];
    const float* ap     = (const float*)d_in[1];
    const float* ac     = (const float*)d_in[2];
    const float* edge   = (const float*)d_in[3];
    const float* avail  = (const float*)d_in[4];
    const float* ua0    = (const float*)d_in[5];
    const float* g0     = (const float*)d_in[7];
    const float* W1p    = (const float*)d_in[8];
    const float* W2p    = (const float*)d_in[9];
    const float* Wx1a   = (const float*)d_in[10];
    const float* Wemb1a = (const float*)d_in[11];
    const float* Wl1a   = (const float*)d_in[12];
    const float* Wx1b   = (const float*)d_in[13];
    const float* Wl1b   = (const float*)d_in[15];
    const float* Wx2    = (const float*)d_in[16];
    const float* Wemb2  = (const float*)d_in[17];
    const float* Wl2    = (const float*)d_in[18];
    const float* WQ     = (const float*)d_in[19];

    float *pP, *pDm, *pxa, *puaA, *puaB, *pub, *px2, *pgA, *pgB;
    __half *pA, *pB0, *pB1;
    GETSYM(pP, float, g_P);   GETSYM(pDm, float, g_Dm);
    GETSYM(pA, __half, g_A);
    GETSYM(pB0, __half, g_B0); GETSYM(pB1, __half, g_B1);
    GETSYM(pxa, float, g_xa);
    GETSYM(puaA, float, g_uaA); GETSYM(puaB, float, g_uaB);
    GETSYM(pub, float, g_ub); GETSYM(px2, float, g_x2);
    GETSYM(pgA, float, g_gA); GETSYM(pgB, float, g_gB);

    // dynamic smem: NSTAGE stages; l/epilogue overlays the stages
    const int sm64  = 5 * (64 + 64) * 128;    // 81920
    const int sm128 = 4 * (64 + 128) * 128;   // 98304
    cudaFuncSetAttribute(k_mma<64, 0, true>,   cudaFuncAttributeMaxDynamicSharedMemorySize, sm64);
    cudaFuncSetAttribute(k_mma<64, 1, false>,  cudaFuncAttributeMaxDynamicSharedMemorySize, sm64);
    cudaFuncSetAttribute(k_mma<128, 2, true>,  cudaFuncAttributeMaxDynamicSharedMemorySize, sm128);
    cudaFuncSetAttribute(k_mma<128, 2, false>, cudaFuncAttributeMaxDynamicSharedMemorySize, sm128);

    k_presence<<<BB * NC, 256>>>(edge, avail, W1p, W2p, pP, pDm);
    k_buildA<<<dim3(32, 32, BB), 256>>>(pP, pDm, pA, xs, ap, ac, pxa);

    // T1: 5 iterations (H = 64); B double-buffered, emitted by previous epilogue
    k_buildB<64><<<dim3(32, 2, BB), 256>>>(ua0, Wemb1a, pB0);
    __half* bcur = pB0;
    __half* bnxt = pB1;
    const float* uin = ua0;
    for (int it = 0; it < 5; it++) {
        float* uout = (it & 1) ? puaB : puaA;
        if (it < 4)
            k_mma<64, 0, true><<<dim3(16, BB), 256, sm64>>>(
                pA, bcur, Wl1a, nullptr, pxa, Wx1a, nullptr, nullptr, uout, nullptr,
                Wemb1a, bnxt);
        else
            k_mma<64, 1, false><<<dim3(16, BB), 256, sm64>>>(
                pA, bcur, Wl1a, Wl1b, pxa, Wx1a, Wx1b, nullptr, uout, pub,
                nullptr, nullptr);
        __half* t = bcur; bcur = bnxt; bnxt = t;
        uin = uout;
    }

    // x2 = [u_a | u_b] @ W_x_2
    k_gemm2<64, 128><<<1024, 512>>>(uin, pub, Wx2, Wx2 + 64 * 128, px2);

    // T2: 5 iterations (H = 128)
    k_buildB<128><<<dim3(32, 4, BB), 256>>>(g0, Wemb2, pB0);
    bcur = pB0; bnxt = pB1;
    const float* gin = g0;
    for (int it = 0; it < 5; it++) {
        float* gout = (it & 1) ? pgB : pgA;
        if (it < 4)
            k_mma<128, 2, true><<<dim3(16, BB), 256, sm128>>>(
                pA, bcur, Wl2, nullptr, nullptr, nullptr, nullptr, px2, gout, nullptr,
                Wemb2, bnxt);
        else
            k_mma<128, 2, false><<<dim3(16, BB), 256, sm128>>>(
                pA, bcur, Wl2, nullptr, nullptr, nullptr, nullptr, px2, gout, nullptr,
                nullptr, nullptr);
        __half* t = bcur; bcur = bnxt; bnxt = t;
        gin = gout;
    }

    k_q<<<BB, 256>>>(gin, WQ, (float*)d_out);
}

// round 16
// speedup vs baseline: 4.6336x; 1.0093x over previous
#include <cuda_runtime.h>
#include <cuda_fp16.h>
#include <cstdint>

#define BB 16
#define NC 1023
#define NN 1024
#define BN (BB*NN)
#define KK 3072
#define KSTEPS (KK/64)

// degree-3 economized sigmoid poly on [-1,1]: sigma(x) ~= 0.5 + B1 x + B3 x^3 (max err ~1.2e-4)
#define PB1 0.24944117f
#define PB3 (-0.01850583f)

// ---------------- static device scratch ----------------
__device__ float g_P [BB*NC*NN];
__device__ float g_Dm[BB*NC*NN];
__device__ __half g_A[(size_t)BB*NN*KK];      // [b][i][kp*1024+c], planes p, p*d, p*d^3
__device__ __half g_B0[(size_t)BB*128*KK];    // B ping
__device__ __half g_B1[(size_t)BB*128*KK];    // B pong
__device__ float g_xa[BN];
__device__ float g_uaA[BN*64];
__device__ float g_uaB[BN*64];
__device__ float g_ub [BN*64];
__device__ float g_x2 [BN*128];
__device__ float g_gA [BN*128];
__device__ float g_gB [BN*128];

// ---------------- packed f32x2 helpers ----------------
__device__ __forceinline__ float2 f2(float x) { return make_float2(x, x); }
__device__ __forceinline__ float2 fma2(float2 a, float2 b, float2 c) {
    float2 r;
    asm("fma.rn.f32x2 %0, %1, %2, %3;"
        : "=l"(*(unsigned long long*)&r)
        : "l"(*(unsigned long long*)&a), "l"(*(unsigned long long*)&b),
          "l"(*(unsigned long long*)&c));
    return r;
}
__device__ __forceinline__ float2 mul2(float2 a, float2 b) {
    float2 r;
    asm("mul.rn.f32x2 %0, %1, %2;"
        : "=l"(*(unsigned long long*)&r)
        : "l"(*(unsigned long long*)&a), "l"(*(unsigned long long*)&b));
    return r;
}

__device__ __forceinline__ uint32_t smem_u32(const void* p) {
    uint32_t a;
    asm("{ .reg .u64 t; cvta.to.shared.u64 t, %1; cvt.u32.u64 %0, t; }" : "=r"(a) : "l"(p));
    return a;
}
__device__ __forceinline__ void ldgsts16(uint32_t s, const void* g) {
    asm volatile("cp.async.cg.shared.global [%0], [%1], 16;" :: "r"(s), "l"(g));
}
__device__ __forceinline__ void ldsm_x4(uint32_t& r0, uint32_t& r1, uint32_t& r2,
                                        uint32_t& r3, uint32_t addr) {
    asm volatile("ldmatrix.sync.aligned.m8n8.x4.shared.b16 {%0,%1,%2,%3}, [%4];"
        : "=r"(r0), "=r"(r1), "=r"(r2), "=r"(r3) : "r"(addr));
}
__device__ __forceinline__ void mma16816(float* c, uint32_t a0, uint32_t a1,
                                         uint32_t a2, uint32_t a3,
                                         uint32_t b0, uint32_t b1) {
    asm volatile("mma.sync.aligned.m16n8k16.row.col.f32.f16.f16.f32 "
        "{%0,%1,%2,%3}, {%4,%5,%6,%7}, {%8,%9}, {%0,%1,%2,%3};"
        : "+f"(c[0]), "+f"(c[1]), "+f"(c[2]), "+f"(c[3])
        : "r"(a0), "r"(a1), "r"(a2), "r"(a3), "r"(b0), "r"(b1));
}
__device__ __forceinline__ uint32_t pack2h(float a, float b) {
    __half2 h = __floats2half2_rn(a, b);
    return *(uint32_t*)&h;
}

// ---------------- presence MLP + masked softmax ----------------
__global__ void __launch_bounds__(256) k_presence(const float* __restrict__ edge,
                                                  const float* __restrict__ avail,
                                                  const float* __restrict__ W1,
                                                  const float* __restrict__ W2,
                                                  float* __restrict__ P,
                                                  float* __restrict__ Dm) {
    __shared__ float sW1[192];
    __shared__ float sW2[64];
    __shared__ float redA[8], redB[8];
    int bc = blockIdx.x;
    int b = bc / NC, c = bc - b * NC;
    int tid = threadIdx.x, lane = tid & 31, warp = tid >> 5;
    if (tid < 192) sW1[tid] = W1[tid];
    if (tid < 64)  sW2[tid] = W2[tid];
    __syncthreads();

    size_t ebase = (size_t)bc * NN * 3;
    size_t pbase = (size_t)bc * NN;
    float lg[4];
#pragma unroll
    for (int j = 0; j < 2; j++) {
        int n0 = tid + j * 512;
        int n1 = n0 + 256;
        float e00 = edge[ebase + (size_t)n0 * 3];
        float e01 = edge[ebase + (size_t)n0 * 3 + 1];
        float e02 = edge[ebase + (size_t)n0 * 3 + 2];
        float e10 = edge[ebase + (size_t)n1 * 3];
        float e11 = edge[ebase + (size_t)n1 * 3 + 1];
        float e12 = edge[ebase + (size_t)n1 * 3 + 2];
        float2 E0 = make_float2(e00, e10);
        float2 E1 = make_float2(e01, e11);
        float2 E2 = make_float2(e02, e12);
        float2 acc = f2(0.f);
#pragma unroll
        for (int h = 0; h < 64; h++) {
            float2 t = mul2(E0, f2(sW1[h]));
            t = fma2(E1, f2(sW1[64 + h]), t);
            t = fma2(E2, f2(sW1[128 + h]), t);
            t.x = fmaxf(t.x, 0.f); t.y = fmaxf(t.y, 0.f);
            acc = fma2(t, f2(sW2[h]), acc);
        }
        float h2a = fmaxf(acc.x, 0.f);
        float h2b = fmaxf(acc.y, 0.f);
        float m0 = (n0 == c ? 0.f : 1.f) * avail[(b << 10) + n0];
        float m1 = (n1 == c ? 0.f : 1.f) * avail[(b << 10) + n1];
        lg[2 * j]     = h2a * m0 - (1.f - m0) * 1e10f;
        lg[2 * j + 1] = h2b * m1 - (1.f - m1) * 1e10f;
        Dm[pbase + n0] = e00;
        Dm[pbase + n1] = e10;
    }
    float m = fmaxf(fmaxf(lg[0], lg[1]), fmaxf(lg[2], lg[3]));
#pragma unroll
    for (int o = 16; o; o >>= 1) m = fmaxf(m, __shfl_xor_sync(0xffffffffu, m, o));
    if (lane == 0) redA[warp] = m;
    __syncthreads();
    m = redA[0];
#pragma unroll
    for (int w = 1; w < 8; w++) m = fmaxf(m, redA[w]);
    float e0 = __expf(lg[0] - m), e1 = __expf(lg[1] - m);
    float e2 = __expf(lg[2] - m), e3 = __expf(lg[3] - m);
    float s = (e0 + e1) + (e2 + e3);
#pragma unroll
    for (int o = 16; o; o >>= 1) s += __shfl_xor_sync(0xffffffffu, s, o);
    if (lane == 0) redB[warp] = s;
    __syncthreads();
    s = redB[0];
#pragma unroll
    for (int w = 1; w < 8; w++) s += redB[w];
    float inv = 1.0f / s;
    P[pbase + tid]       = e0 * inv;
    P[pbase + tid + 256] = e1 * inv;
    P[pbase + tid + 512] = e2 * inv;
    P[pbase + tid + 768] = e3 * inv;
}

// ---------------- build A: transpose + powers {1, d, d^3}, fp32 -> fp16; also x_a ----------------
__global__ void __launch_bounds__(256) k_buildA(const float* __restrict__ P,
                                                const float* __restrict__ D,
                                                __half* __restrict__ A,
                                                const float* __restrict__ xs,
                                                const float* __restrict__ ap,
                                                const float* __restrict__ ac,
                                                float* __restrict__ xa) {
    __shared__ float sP[32][33], sD[32][33];
    int b = blockIdx.z, ct = blockIdx.y, nt = blockIdx.x, tid = threadIdx.x;
#pragma unroll
    for (int k = 0; k < 4; k++) {
        int idx = tid + (k << 8);
        int r = idx >> 5, j = idx & 31;
        int c = (ct << 5) + r, n = (nt << 5) + j;
        float pv = 0.f, dv = 0.f;
        if (c < NC) {
            size_t g = ((size_t)(b * NC + c) << 10) + n;
            pv = P[g]; dv = D[g];
        }
        sP[r][j] = pv; sD[r][j] = dv;
    }
    __syncthreads();
#pragma unroll
    for (int k = 0; k < 4; k++) {
        int idx = tid + (k << 8);
        int rn = idx >> 5, jc = idx & 31;
        int n = (nt << 5) + rn, c = (ct << 5) + jc;
        float p = sP[jc][rn], d = sD[jc][rn];
        __half* row = A + ((size_t)((b << 10) + n)) * KK + c;
        row[0]    = __float2half(p);
        row[1024] = __float2half(p * d);
        row[2048] = __float2half(p * d * d * d);
    }
    if (ct == 0 && tid < 32) {
        int n = (nt << 5) + tid;
        float best = -3.4e38f;
#pragma unroll
        for (int r = 0; r < 8; r++) {
            int o = (((b << 3) + r) << 10) + n;
            best = fmaxf(best, xs[o] * (ap[o] + ac[o]));
        }
        xa[(b << 10) + n] = best;
    }
}

// ---------------- build B (loop-entry only) ----------------
template<int H>
__global__ void __launch_bounds__(256) k_buildB(const float* __restrict__ u,
                                                const float* __restrict__ W,
                                                __half* __restrict__ Bm) {
    __shared__ float sU[32][33];
    int b = blockIdx.z, ht = blockIdx.y, ct = blockIdx.x, tid = threadIdx.x;
#pragma unroll
    for (int k = 0; k < 4; k++) {
        int idx = tid + (k << 8);
        int r = idx >> 5, j = idx & 31;
        sU[r][j] = u[((size_t)((b << 10) + (ct << 5) + r)) * H + (ht << 5) + j];
    }
    __syncthreads();
#pragma unroll
    for (int k = 0; k < 4; k++) {
        int idx = tid + (k << 8);
        int rh = idx >> 5, jc = idx & 31;
        int h = (ht << 5) + rh, c = (ct << 5) + jc;
        float uu = sU[jc][rh];
        float w = W[h];
        __half* row = Bm + ((size_t)(b * 128 + h)) * KK + c;
        row[0]    = __float2half(0.5f * uu);
        row[1024] = __float2half(PB1 * w * uu);
        row[2048] = __float2half(PB3 * w * w * w * uu);
    }
}

// ---------------- fused mma GEMM (M-tile 64) + fp32 epilogue (+ B emit) ----------------
// mainloop: l[64,H] = A[64,KK] . B[H,KK]^T  (fp16 mma, fp32 accum); ONE sync per K-step.
// REV: traverse K chunks high->low (serpentine across launches for L2 reuse of A).
// MODE 0: out1 = relu(l@W + xa*wx); MODE 1: + out2 = relu(l@W2 + xa*wxb); MODE 2: out1 = relu(l@W + x2)
template<int H, int MODE, bool WB, bool REV>
__global__ void __launch_bounds__(256, 2) k_mma(const __half* __restrict__ A,
                                                const __half* __restrict__ Bm,
                                                const float* __restrict__ Wg,
                                                const float* __restrict__ Wg2,
                                                const float* __restrict__ xa,
                                                const float* __restrict__ wx,
                                                const float* __restrict__ wxb,
                                                const float* __restrict__ x2,
                                                float* __restrict__ out1,
                                                float* __restrict__ out2,
                                                const float* __restrict__ Wemb,
                                                __half* __restrict__ Bout) {
    constexpr int MT = 64;
    constexpr int STAGE = (MT + H) * 128;        // bytes per cp.async stage
    constexpr int NSTAGE = (H == 64) ? 5 : 4;
    constexpr int NG = (MT + H) / 32;            // 16B granules per thread per stage
    constexpr int NTILE = H / 4;                 // n-cols per warp
    constexpr int NT8 = NTILE / 8;               // 2 (H=64) or 4 (H=128)
    constexpr int PH = H + 1;
    extern __shared__ char dsm[];
    __shared__ float sWemb[128];
    const int tid = threadIdx.x;
    const int wid = tid >> 5, lane = tid & 31;
    const int wm = wid & 1, wn = wid >> 1;       // 2 (m) x 4 (n) warps
    const int b = blockIdx.y, i0 = blockIdx.x << 6;

    const uint32_t sbase = smem_u32(dsm);
    const __half* Ab = A + ((size_t)(b * NN) + i0) * KK;
    const __half* Bb = Bm + (size_t)b * 128 * KK;
    if (WB && tid < H) sWemb[tid] = Wemb[tid];

    const __half* lsrc[NG]; uint32_t ldst[NG];
#pragma unroll
    for (int i = 0; i < NG; i++) {
        int idx = tid + (i << 8);
        int row = idx >> 3, g = idx & 7;
        if (row < MT) {
            lsrc[i] = Ab + (size_t)row * KK + (g << 3);
            ldst[i] = sbase + (((row << 3) + (g ^ (row & 7))) << 4);
        } else {
            int h = row - MT;
            lsrc[i] = Bb + (size_t)h * KK + (g << 3);
            ldst[i] = sbase + MT * 128 + (((h << 3) + (g ^ (h & 7))) << 4);
        }
    }

    float acc[2][NT8][4];
#pragma unroll
    for (int ms = 0; ms < 2; ms++)
#pragma unroll
        for (int j = 0; j < NT8; j++)
#pragma unroll
            for (int q = 0; q < 4; q++) acc[ms][j][q] = 0.f;

    // K-chunk map: forward or reversed (serpentine)
#define KMAP(ks) (REV ? (KSTEPS - 1 - (ks)) : (ks))

    // prologue: issue NSTAGE-1 stages
#pragma unroll
    for (int s = 0; s < NSTAGE - 1; s++) {
#pragma unroll
        for (int i = 0; i < NG; i++)
            ldgsts16(ldst[i] + s * STAGE, lsrc[i] + (KMAP(s) << 6));
        asm volatile("cp.async.commit_group;" ::: "memory");
    }

    int sc = 0;                     // compute stage
    int sp = NSTAGE - 1;            // prefetch stage
#pragma unroll 1
    for (int ks = 0; ks < KSTEPS; ks++) {
        // group ks complete -> stage sc data resident
        asm volatile("cp.async.wait_group %0;" :: "n"(NSTAGE - 2) : "memory");
        __syncthreads();

        // prefetch step ks+NSTAGE-1 into stage sp (its readers finished before the sync)
        int kpre = ks + NSTAGE - 1;
        if (kpre < KSTEPS) {
#pragma unroll
            for (int i = 0; i < NG; i++)
                ldgsts16(ldst[i] + sp * STAGE, lsrc[i] + (KMAP(kpre) << 6));
        }
        asm volatile("cp.async.commit_group;" ::: "memory");   // always: keeps group count uniform
        if (++sp == NSTAGE) sp = 0;

        const uint32_t sA = sbase + sc * STAGE;
        const uint32_t sB = sA + MT * 128;
        if (++sc == NSTAGE) sc = 0;
#pragma unroll
        for (int kk = 0; kk < 4; kk++) {
            uint32_t a[2][4];
#pragma unroll
            for (int ms = 0; ms < 2; ms++) {
                int row = wm * 32 + ms * 16 + (lane & 15);
                int g = kk * 2 + (lane >> 4);
                uint32_t addr = sA + (((row << 3) + (g ^ (row & 7))) << 4);
                ldsm_x4(a[ms][0], a[ms][1], a[ms][2], a[ms][3], addr);
            }
#pragma unroll
            for (int nt = 0; nt < NT8 / 2; nt++) {
                uint32_t br[4];
                int h = wn * NTILE + nt * 16 + (lane & 15);
                int g = kk * 2 + (lane >> 4);
                uint32_t addr = sB + (((h << 3) + (g ^ (h & 7))) << 4);
                ldsm_x4(br[0], br[1], br[2], br[3], addr);
#pragma unroll
                for (int ms = 0; ms < 2; ms++) {
                    mma16816(acc[ms][2 * nt],     a[ms][0], a[ms][1], a[ms][2], a[ms][3], br[0], br[2]);
                    mma16816(acc[ms][2 * nt + 1], a[ms][0], a[ms][1], a[ms][2], a[ms][3], br[1], br[3]);
                }
            }
        }
    }
#undef KMAP
    __syncthreads();   // all stage reads done before l overlays stage memory

    // ---- stage l to smem (fp32, [64][H]) — overlays stage buffers ----
    float* lsm = (float*)dsm;
#pragma unroll
    for (int ms = 0; ms < 2; ms++) {
        int r0 = wm * 32 + ms * 16 + (lane >> 2);
        int cb = wn * NTILE + (lane & 3) * 2;
#pragma unroll
        for (int j = 0; j < NT8; j++) {
            *(float2*)(lsm + (size_t)r0 * H + cb + j * 8)       = make_float2(acc[ms][j][0], acc[ms][j][1]);
            *(float2*)(lsm + (size_t)(r0 + 8) * H + cb + j * 8) = make_float2(acc[ms][j][2], acc[ms][j][3]);
        }
    }
    __syncthreads();

    // ---- fp32 epilogue GEMM: out = relu(l @ W + extra); W read via L1/L2 ----
    float* l2 = (float*)dsm;   // transposed-u overlay (pitch PH), written after sync
    if (MODE == 2) {
        const int ct = tid & 31, rt = tid >> 5;   // 8 row-groups x 8 rows
        float2 a0[8], a1[8];
#pragma unroll
        for (int r = 0; r < 8; r++) { a0[r] = f2(0.f); a1[r] = f2(0.f); }
#pragma unroll 4
        for (int k = 0; k < H; k++) {
            float4 wv = __ldg((const float4*)Wg + k * (H / 4) + ct);
            float2 w01 = make_float2(wv.x, wv.y), w23 = make_float2(wv.z, wv.w);
            const float* lr = lsm + (size_t)rt * 8 * H + k;
#pragma unroll
            for (int r = 0; r < 8; r++) {
                float lv = lr[r * H];
                a0[r] = fma2(f2(lv), w01, a0[r]);
                a1[r] = fma2(f2(lv), w23, a1[r]);
            }
        }
#pragma unroll
        for (int r = 0; r < 8; r++) {
            int row = rt * 8 + r;
            int rg = (b << 10) + i0 + row;
            float4 xv = *(const float4*)(x2 + (size_t)rg * H + ct * 4);
            float4 o;
            o.x = fmaxf(a0[r].x + xv.x, 0.f);
            o.y = fmaxf(a0[r].y + xv.y, 0.f);
            o.z = fmaxf(a1[r].x + xv.z, 0.f);
            o.w = fmaxf(a1[r].y + xv.w, 0.f);
            a0[r] = make_float2(o.x, o.y);
            a1[r] = make_float2(o.z, o.w);
            *(float4*)(out1 + (size_t)rg * H + ct * 4) = o;
        }
        if (WB) {
            __syncthreads();
#pragma unroll
            for (int r = 0; r < 8; r++) {
                int row = rt * 8 + r;
                l2[row * PH + ct * 4 + 0] = a0[r].x;
                l2[row * PH + ct * 4 + 1] = a0[r].y;
                l2[row * PH + ct * 4 + 2] = a1[r].x;
                l2[row * PH + ct * 4 + 3] = a1[r].y;
            }
        }
    } else {
        const int ct = tid & 15, rt = tid >> 4;   // 16 row-groups x 4 rows
        const int NPASS = (MODE == 1) ? 2 : 1;
#pragma unroll
        for (int pass = 0; pass < NPASS; pass++) {
            const float* Wp = pass ? Wg2 : Wg;
            const float* wxp = pass ? wxb : wx;
            float* outp = pass ? out2 : out1;
            float2 a0[4], a1[4];
#pragma unroll
            for (int r = 0; r < 4; r++) { a0[r] = f2(0.f); a1[r] = f2(0.f); }
#pragma unroll 4
            for (int k = 0; k < H; k++) {
                float4 wv = __ldg((const float4*)Wp + k * (H / 4) + ct);
                float2 w01 = make_float2(wv.x, wv.y), w23 = make_float2(wv.z, wv.w);
                const float* lr = lsm + (size_t)rt * 4 * H + k;
#pragma unroll
                for (int r = 0; r < 4; r++) {
                    float lv = lr[r * H];
                    a0[r] = fma2(f2(lv), w01, a0[r]);
                    a1[r] = fma2(f2(lv), w23, a1[r]);
                }
            }
            float4 wxv = *(const float4*)(wxp + ct * 4);
#pragma unroll
            for (int r = 0; r < 4; r++) {
                int row = rt * 4 + r;
                int rg = (b << 10) + i0 + row;
                float xv = xa[rg];
                float4 o;
                o.x = fmaxf(a0[r].x + xv * wxv.x, 0.f);
                o.y = fmaxf(a0[r].y + xv * wxv.y, 0.f);
                o.z = fmaxf(a1[r].x + xv * wxv.z, 0.f);
                o.w = fmaxf(a1[r].y + xv * wxv.w, 0.f);
                a0[r] = make_float2(o.x, o.y);
                a1[r] = make_float2(o.z, o.w);
                *(float4*)(outp + (size_t)rg * H + ct * 4) = o;
            }
            if (WB && pass == 0) {
                __syncthreads();
#pragma unroll
                for (int r = 0; r < 4; r++) {
                    int row = rt * 4 + r;
                    l2[row * PH + ct * 4 + 0] = a0[r].x;
                    l2[row * PH + ct * 4 + 1] = a0[r].y;
                    l2[row * PH + ct * 4 + 2] = a1[r].x;
                    l2[row * PH + ct * 4 + 3] = a1[r].y;
                }
            }
        }
    }

    // ---- emit B for next iteration: Bout[h][plane*1024 + i0 + c], c in [0,64) ----
    if (WB) {
        __syncthreads();
        constexpr int SEGS = H / 32;   // (H*64)/(256*8)
#pragma unroll
        for (int s = 0; s < SEGS; s++) {
            int seg = s * 256 + tid;
            int h = seg >> 3;
            int c8 = (seg & 7) << 3;
            float w = sWemb[h];
            float cw1 = PB1 * w;
            float cw3 = PB3 * w * w * w;
            float v[8];
#pragma unroll
            for (int j = 0; j < 8; j++) v[j] = l2[(c8 + j) * PH + h];
            uint4 q0, q1, q2;
            q0.x = pack2h(0.5f * v[0], 0.5f * v[1]);
            q0.y = pack2h(0.5f * v[2], 0.5f * v[3]);
            q0.z = pack2h(0.5f * v[4], 0.5f * v[5]);
            q0.w = pack2h(0.5f * v[6], 0.5f * v[7]);
            q1.x = pack2h(cw1 * v[0], cw1 * v[1]);
            q1.y = pack2h(cw1 * v[2], cw1 * v[3]);
            q1.z = pack2h(cw1 * v[4], cw1 * v[5]);
            q1.w = pack2h(cw1 * v[6], cw1 * v[7]);
            q2.x = pack2h(cw3 * v[0], cw3 * v[1]);
            q2.y = pack2h(cw3 * v[2], cw3 * v[3]);
            q2.z = pack2h(cw3 * v[4], cw3 * v[5]);
            q2.w = pack2h(cw3 * v[6], cw3 * v[7]);
            __half* brow = Bout + (size_t)(b * 128 + h) * KK + i0 + c8;
            *(uint4*)(brow)        = q0;
            *(uint4*)(brow + 1024) = q1;
            *(uint4*)(brow + 2048) = q2;
        }
    }
}

// ---------------- small GEMM (x2 = [u_a|u_b] @ W_x_2) ----------------
template<int K, int NO>
__global__ void __launch_bounds__(NO * 4) k_gemm2(const float* __restrict__ A,
                                                  const float* __restrict__ A2,
                                                  const float* __restrict__ W,
                                                  const float* __restrict__ W2,
                                                  float* __restrict__ out) {
    constexpr int NT = NO * 4;
    __shared__ float sA[16][33];
    __shared__ __align__(16) float sW[32 * NO];
    const int tid = threadIdx.x, rr = tid & 15, cq = tid >> 4;
    const int r0 = blockIdx.x << 4;
    float2 acc0 = f2(0.f), acc1 = f2(0.f);
    for (int pass = 0; pass < 2; pass++) {
        const float* Ap = pass ? A2 : A;
        const float* Wp = pass ? W2 : W;
        for (int k0 = 0; k0 < K; k0 += 32) {
#pragma unroll
            for (int idx = tid; idx < 512; idx += NT) {
                int r = idx >> 5, c = idx & 31;
                sA[r][c] = Ap[(size_t)(r0 + r) * K + k0 + c];
            }
#pragma unroll
            for (int idx = tid; idx < 32 * NO; idx += NT)
                sW[idx] = Wp[(size_t)(k0 + idx / NO) * NO + (idx & (NO - 1))];
            __syncthreads();
#pragma unroll
            for (int kk = 0; kk < 32; kk++) {
                float a = sA[rr][kk];
                float4 wv = ((const float4*)sW)[kk * (NO / 4) + cq];
                acc0 = fma2(f2(a), make_float2(wv.x, wv.y), acc0);
                acc1 = fma2(f2(a), make_float2(wv.z, wv.w), acc1);
            }
            __syncthreads();
        }
    }
    float4 r;
    r.x = acc0.x; r.y = acc0.y; r.z = acc1.x; r.w = acc1.y;
    size_t orow = (size_t)(r0 + rr) * NO + (cq << 2);
    ((float4*)out)[orow >> 2] = r;
}

// ---------------- final reduction ----------------
__global__ void __launch_bounds__(256) k_q(const float* __restrict__ g,
                                           const float* __restrict__ wq,
                                           float* __restrict__ out) {
    __shared__ float red[8];
    int b = blockIdx.x, tid = threadIdx.x, lane = tid & 31, warp = tid >> 5;
    const float* gb = g + (size_t)b * NN * 128;
    float acc = 0.f;
    for (int idx = tid; idx < NN * 128; idx += 256)
        acc += gb[idx] * wq[idx & 127];
#pragma unroll
    for (int o = 16; o; o >>= 1) acc += __shfl_xor_sync(0xffffffffu, acc, o);
    if (lane == 0) red[warp] = acc;
    __syncthreads();
    if (tid == 0) {
        float s = 0.f;
#pragma unroll
        for (int w = 0; w < 8; w++) s += red[w];
        out[b] = s;
    }
}

#define GETSYM(p, T, s) do { void* _q = nullptr; cudaGetSymbolAddress(&_q, s); (p) = (T*)_q; } while (0)

extern "C" void kernel_launch(void* const* d_in, const int* in_sizes, int n_in,
                              void* d_out, int out_size) {
    (void)in_sizes; (void)n_in; (void)out_size;
    const float* xs     = (const float*)d_in[0];
    const float* ap     = (const float*)d_in[1];
    const float* ac     = (const float*)d_in[2];
    const float* edge   = (const float*)d_in[3];
    const float* avail  = (const float*)d_in[4];
    const float* ua0    = (const float*)d_in[5];
    const float* g0     = (const float*)d_in[7];
    const float* W1p    = (const float*)d_in[8];
    const float* W2p    = (const float*)d_in[9];
    const float* Wx1a   = (const float*)d_in[10];
    const float* Wemb1a = (const float*)d_in[11];
    const float* Wl1a   = (const float*)d_in[12];
    const float* Wx1b   = (const float*)d_in[13];
    const float* Wl1b   = (const float*)d_in[15];
    const float* Wx2    = (const float*)d_in[16];
    const float* Wemb2  = (const float*)d_in[17];
    const float* Wl2    = (const float*)d_in[18];
    const float* WQ     = (const float*)d_in[19];

    float *pP, *pDm, *pxa, *puaA, *puaB, *pub, *px2, *pgA, *pgB;
    __half *pA, *pB0, *pB1;
    GETSYM(pP, float, g_P);   GETSYM(pDm, float, g_Dm);
    GETSYM(pA, __half, g_A);
    GETSYM(pB0, __half, g_B0); GETSYM(pB1, __half, g_B1);
    GETSYM(pxa, float, g_xa);
    GETSYM(puaA, float, g_uaA); GETSYM(puaB, float, g_uaB);
    GETSYM(pub, float, g_ub); GETSYM(px2, float, g_x2);
    GETSYM(pgA, float, g_gA); GETSYM(pgB, float, g_gB);

    // dynamic smem: NSTAGE stages; l/epilogue overlays the stages
    const int sm64  = 5 * (64 + 64) * 128;    // 81920
    const int sm128 = 4 * (64 + 128) * 128;   // 98304
    cudaFuncSetAttribute(k_mma<64, 0, true, false>,   cudaFuncAttributeMaxDynamicSharedMemorySize, sm64);
    cudaFuncSetAttribute(k_mma<64, 0, true, true>,    cudaFuncAttributeMaxDynamicSharedMemorySize, sm64);
    cudaFuncSetAttribute(k_mma<64, 1, false, false>,  cudaFuncAttributeMaxDynamicSharedMemorySize, sm64);
    cudaFuncSetAttribute(k_mma<128, 2, true, false>,  cudaFuncAttributeMaxDynamicSharedMemorySize, sm128);
    cudaFuncSetAttribute(k_mma<128, 2, true, true>,   cudaFuncAttributeMaxDynamicSharedMemorySize, sm128);
    cudaFuncSetAttribute(k_mma<128, 2, false, false>, cudaFuncAttributeMaxDynamicSharedMemorySize, sm128);
    cudaFuncSetAttribute(k_mma<128, 2, false, true>,  cudaFuncAttributeMaxDynamicSharedMemorySize, sm128);

    k_presence<<<BB * NC, 256>>>(edge, avail, W1p, W2p, pP, pDm);
    k_buildA<<<dim3(32, 32, BB), 256>>>(pP, pDm, pA, xs, ap, ac, pxa);

    // T1: 5 iterations (H = 64); serpentine K traversal F,R,F,R,F for L2 reuse of A
    k_buildB<64><<<dim3(32, 2, BB), 256>>>(ua0, Wemb1a, pB0);
    __half* bcur = pB0;
    __half* bnxt = pB1;
    const float* uin = ua0;
    for (int it = 0; it < 5; it++) {
        float* uout = (it & 1) ? puaB : puaA;
        if (it < 4) {
            if (it & 1)
                k_mma<64, 0, true, true><<<dim3(16, BB), 256, sm64>>>(
                    pA, bcur, Wl1a, nullptr, pxa, Wx1a, nullptr, nullptr, uout, nullptr,
                    Wemb1a, bnxt);
            else
                k_mma<64, 0, true, false><<<dim3(16, BB), 256, sm64>>>(
                    pA, bcur, Wl1a, nullptr, pxa, Wx1a, nullptr, nullptr, uout, nullptr,
                    Wemb1a, bnxt);
        } else {
            k_mma<64, 1, false, false><<<dim3(16, BB), 256, sm64>>>(
                pA, bcur, Wl1a, Wl1b, pxa, Wx1a, Wx1b, nullptr, uout, pub,
                nullptr, nullptr);
        }
        __half* t = bcur; bcur = bnxt; bnxt = t;
        uin = uout;
    }

    // x2 = [u_a | u_b] @ W_x_2
    k_gemm2<64, 128><<<1024, 512>>>(uin, pub, Wx2, Wx2 + 64 * 128, px2);

    // T2: 5 iterations (H = 128); continue serpentine R,F,R,F,R (T1 ended forward)
    k_buildB<128><<<dim3(32, 4, BB), 256>>>(g0, Wemb2, pB0);
    bcur = pB0; bnxt = pB1;
    const float* gin = g0;
    for (int it = 0; it < 5; it++) {
        float* gout = (it & 1) ? pgB : pgA;
        bool rev = ((it & 1) == 0);
        if (it < 4) {
            if (rev)
                k_mma<128, 2, true, true><<<dim3(16, BB), 256, sm128>>>(
                    pA, bcur, Wl2, nullptr, nullptr, nullptr, nullptr, px2, gout, nullptr,
                    Wemb2, bnxt);
            else
                k_mma<128, 2, true, false><<<dim3(16, BB), 256, sm128>>>(
                    pA, bcur, Wl2, nullptr, nullptr, nullptr, nullptr, px2, gout, nullptr,
                    Wemb2, bnxt);
        } else {
            if (rev)
                k_mma<128, 2, false, true><<<dim3(16, BB), 256, sm128>>>(
                    pA, bcur, Wl2, nullptr, nullptr, nullptr, nullptr, px2, gout, nullptr,
                    nullptr, nullptr);
            else
                k_mma<128, 2, false, false><<<dim3(16, BB), 256, sm128>>>(
                    pA, bcur, Wl2, nullptr, nullptr, nullptr, nullptr, px2, gout, nullptr,
                    nullptr, nullptr);
        }
        __half* t = bcur; bcur = bnxt; bnxt = t;
        gin = gout;
    }

    k_q<<<BB, 256>>>(gin, WQ, (float*)d_out);
}